// round 2
// baseline (speedup 1.0000x reference)
#include <cuda_runtime.h>
#include <math.h>

#define B_   2
#define S_   2048
#define D_   512
#define L_   4
#define H_   8
#define DH   64
#define M_   (B_*S_)      // 4096 rows
#define DI   512          // H*DH
#define QKVN 1536
#define DHID 1365

// ---------------- scratch (no allocation allowed) ----------------
__device__ float g_t   [M_ * D_];          // residual stream
__device__ float g_x   [M_ * D_];          // normed activations
__device__ float g_qkv [M_ * QKVN];        // q|k|v packed per row
__device__ float g_fv  [M_ * DI];          // first layer's v
__device__ float g_o   [M_ * DI];          // attention output
__device__ float g_h   [M_ * 2 * DHID];    // ff_in output
__device__ float g_y1  [M_ * DHID];        // gated gelu output

// ---------------- elementwise copy ----------------
__global__ void copy_k(const float4* __restrict__ in, float4* __restrict__ out, int n4) {
    int i = blockIdx.x * blockDim.x + threadIdx.x;
    if (i < n4) out[i] = in[i];
}

// ---------------- rmsnorm: one block per row of 512 ----------------
__global__ void rmsnorm_k(const float* __restrict__ in, const float* __restrict__ w,
                          float* __restrict__ out) {
    int row = blockIdx.x;
    const float4* ip = (const float4*)(in + (size_t)row * D_);
    float4 v = ip[threadIdx.x];                       // 128 threads * 4 = 512
    float ss = v.x*v.x + v.y*v.y + v.z*v.z + v.w*v.w;
    #pragma unroll
    for (int o = 16; o; o >>= 1) ss += __shfl_xor_sync(0xffffffffu, ss, o);
    __shared__ float sred[4];
    if ((threadIdx.x & 31) == 0) sred[threadIdx.x >> 5] = ss;
    __syncthreads();
    float tot = sred[0] + sred[1] + sred[2] + sred[3];
    float sc = rsqrtf(tot * (1.0f / 512.0f) + 1.1920929e-7f);
    const float4* wp = (const float4*)w;
    float4 wv = wp[threadIdx.x];
    float4 o4;
    o4.x = v.x * sc * wv.x; o4.y = v.y * sc * wv.y;
    o4.z = v.z * sc * wv.z; o4.w = v.w * sc * wv.w;
    ((float4*)(out + (size_t)row * D_))[threadIdx.x] = o4;
}

// ---------------- generic SGEMM: C[M,N] = A[M,K]@B[K,N] (+bias)(+add) ----------------
// BM=BN=128, BK=16, 256 threads, 8x8 per thread. M must be a multiple of 128 (it is: 4096).
__global__ void sgemm128(int M, int N, int K,
                         const float* __restrict__ A, const float* __restrict__ B,
                         float* __restrict__ C, const float* __restrict__ bias,
                         const float* __restrict__ addsrc) {
    __shared__ float As[16][128];
    __shared__ float Bs[16][128];
    int tid = threadIdx.x;
    int tx = tid & 15, ty = tid >> 4;
    int m0 = blockIdx.y * 128, n0 = blockIdx.x * 128;

    float acc[8][8];
    #pragma unroll
    for (int i = 0; i < 8; i++)
        #pragma unroll
        for (int j = 0; j < 8; j++) acc[i][j] = 0.0f;

    int am = tid >> 1;           // 0..127 row in tile
    int ak = (tid & 1) * 8;      // 0 or 8
    int bn = tid & 127;          // col in tile
    int bk = (tid >> 7) * 8;     // 0 or 8

    for (int k0 = 0; k0 < K; k0 += 16) {
        #pragma unroll
        for (int i = 0; i < 8; i++) {
            int kk = k0 + ak + i;
            As[ak + i][am] = (kk < K) ? A[(size_t)(m0 + am) * K + kk] : 0.0f;
        }
        bool ncol = (n0 + bn) < N;
        #pragma unroll
        for (int i = 0; i < 8; i++) {
            int kk = k0 + bk + i;
            Bs[bk + i][bn] = (kk < K && ncol) ? B[(size_t)kk * N + n0 + bn] : 0.0f;
        }
        __syncthreads();
        #pragma unroll
        for (int kk = 0; kk < 16; kk++) {
            float a[8], b[8];
            #pragma unroll
            for (int i = 0; i < 8; i++) a[i] = As[kk][ty * 8 + i];
            #pragma unroll
            for (int j = 0; j < 8; j++) b[j] = Bs[kk][tx * 8 + j];
            #pragma unroll
            for (int i = 0; i < 8; i++)
                #pragma unroll
                for (int j = 0; j < 8; j++) acc[i][j] += a[i] * b[j];
        }
        __syncthreads();
    }
    #pragma unroll
    for (int i = 0; i < 8; i++) {
        int row = m0 + ty * 8 + i;
        #pragma unroll
        for (int j = 0; j < 8; j++) {
            int col = n0 + tx * 8 + j;
            if (col < N) {
                float v = acc[i][j];
                if (bias)   v += bias[col];
                if (addsrc) v += addsrc[(size_t)row * N + col];
                C[(size_t)row * N + col] = v;
            }
        }
    }
}

// ---------------- save first-layer v ----------------
__global__ void savefv_k(const float* __restrict__ qkv, float* __restrict__ fv) {
    int idx = blockIdx.x * blockDim.x + threadIdx.x;   // < M_*512
    int row = idx >> 9, c = idx & 511;
    fv[idx] = qkv[(size_t)row * QKVN + 1024 + c];
}

// ---------------- v-mix (l>0): one warp per (row, head) ----------------
__global__ void vmix_k(const float* __restrict__ x, const float* __restrict__ mw,
                       const float* __restrict__ mb, float* __restrict__ qkv,
                       const float* __restrict__ fv) {
    int row = blockIdx.x;
    int lane = threadIdx.x & 31;
    int h = threadIdx.x >> 5;     // 0..7 (blockDim = 256)
    float dot = 0.0f;
    #pragma unroll
    for (int d = lane; d < 512; d += 32) dot += x[(size_t)row * 512 + d] * mw[d * 8 + h];
    #pragma unroll
    for (int o = 16; o; o >>= 1) dot += __shfl_xor_sync(0xffffffffu, dot, o);
    float mix = 1.0f / (1.0f + expf(-(dot + mb[h])));
    #pragma unroll
    for (int d = lane; d < 64; d += 32) {
        size_t vi = (size_t)row * QKVN + 1024 + h * 64 + d;
        float v = qkv[vi];
        float f = fv[(size_t)row * 512 + h * 64 + d];
        qkv[vi] = v + mix * (f - v);
    }
}

// ---------------- RoPE on q and k ----------------
__global__ void rope_k(float* __restrict__ qkv) {
    int idx = blockIdx.x * blockDim.x + threadIdx.x;   // < M_*H_*32
    int pair = idx & 31;
    int h    = (idx >> 5) & 7;
    int row  = idx >> 8;
    int pos  = row & (S_ - 1);
    float inv = expf(-logf(10000.0f) * (float)pair * (1.0f / 32.0f));
    float f = (float)pos * inv;
    float s, c;
    sincosf(f, &s, &c);
    size_t base = (size_t)row * QKVN + h * 64 + 2 * pair;
    float q1 = qkv[base], q2 = qkv[base + 1];
    qkv[base]     = q1 * c - q2 * s;
    qkv[base + 1] = q1 * s + q2 * c;
    float k1 = qkv[base + 512], k2 = qkv[base + 513];
    qkv[base + 512] = k1 * c - k2 * s;
    qkv[base + 513] = k1 * s + k2 * c;
}

// ---------------- block-causal flash attention ----------------
// grid (64 qblocks, B*H), 128 threads. Query block qi attends key blocks 0..qi fully.
__global__ void attn_k(const float* __restrict__ qkv, float* __restrict__ o) {
    int qi = blockIdx.x;
    int h  = blockIdx.y & 7;
    int b  = blockIdx.y >> 3;
    __shared__ float Qs[32][65];
    __shared__ float Ks[32][65];
    __shared__ float Vs[32][65];
    int tid = threadIdx.x;
    int row0 = b * S_ + qi * 32;

    #pragma unroll
    for (int i = 0; i < 16; i++) {
        int e = i * 128 + tid;
        int r = e >> 6, d = e & 63;
        Qs[r][d] = qkv[(size_t)(row0 + r) * QKVN + h * 64 + d] * 0.125f;  // scale = Dh^-0.5
    }

    int r = tid >> 2, cg = tid & 3;
    int lane = tid & 31;
    float m_prev = -INFINITY, lsum = 0.0f;
    float O[16];
    #pragma unroll
    for (int i = 0; i < 16; i++) O[i] = 0.0f;

    for (int j = 0; j <= qi; j++) {
        __syncthreads();
        int krow0 = b * S_ + j * 32;
        #pragma unroll
        for (int i = 0; i < 16; i++) {
            int e = i * 128 + tid;
            int rr = e >> 6, d = e & 63;
            size_t base = (size_t)(krow0 + rr) * QKVN + h * 64 + d;
            Ks[rr][d] = qkv[base + 512];
            Vs[rr][d] = qkv[base + 1024];
        }
        __syncthreads();

        float sc[8];
        #pragma unroll
        for (int c = 0; c < 8; c++) {
            float s = 0.0f;
            #pragma unroll
            for (int k = 0; k < 64; k++) s += Qs[r][k] * Ks[cg * 8 + c][k];
            sc[c] = s;
        }
        float mx = sc[0];
        #pragma unroll
        for (int c = 1; c < 8; c++) mx = fmaxf(mx, sc[c]);
        mx = fmaxf(mx, __shfl_xor_sync(0xffffffffu, mx, 1));
        mx = fmaxf(mx, __shfl_xor_sync(0xffffffffu, mx, 2));
        float m_new = fmaxf(m_prev, mx);
        float alpha = __expf(m_prev - m_new);

        float p[8];
        float psum = 0.0f;
        #pragma unroll
        for (int c = 0; c < 8; c++) { p[c] = __expf(sc[c] - m_new); psum += p[c]; }
        lsum = lsum * alpha + psum;
        #pragma unroll
        for (int d = 0; d < 16; d++) O[d] *= alpha;

        #pragma unroll
        for (int c = 0; c < 32; c++) {
            float pc = __shfl_sync(0xffffffffu, p[c & 7], (lane & ~3) | (c >> 3));
            #pragma unroll
            for (int d = 0; d < 16; d++) O[d] += pc * Vs[c][cg * 16 + d];
        }
        m_prev = m_new;
    }
    lsum += __shfl_xor_sync(0xffffffffu, lsum, 1);
    lsum += __shfl_xor_sync(0xffffffffu, lsum, 2);
    float inv = 1.0f / lsum;
    size_t ob = (size_t)(row0 + r) * 512 + h * 64 + cg * 16;
    #pragma unroll
    for (int d = 0; d < 16; d++) o[ob + d] = O[d] * inv;
}

// ---------------- gated exact GELU ----------------
__global__ void gelu_k(const float* __restrict__ hb, float* __restrict__ y1) {
    int idx = blockIdx.x * blockDim.x + threadIdx.x;
    if (idx >= M_ * DHID) return;
    int row = idx / DHID;
    int j   = idx - row * DHID;
    float a = hb[(size_t)row * (2 * DHID) + j];
    float g = hb[(size_t)row * (2 * DHID) + DHID + j];
    float ge = 0.5f * g * (1.0f + erff(g * 0.70710678118654752f));
    y1[idx] = a * ge;
}

// ---------------- launch ----------------
extern "C" void kernel_launch(void* const* d_in, const int* in_sizes, int n_in,
                              void* d_out, int out_size) {
    const float* tokens       = (const float*)d_in[0];
    const float* attn_norm_w  = (const float*)d_in[1];
    const float* qkv_w        = (const float*)d_in[2];
    const float* out_w        = (const float*)d_in[3];
    const float* mix_w        = (const float*)d_in[4];
    const float* mix_b        = (const float*)d_in[5];
    const float* ff_norm_w    = (const float*)d_in[6];
    const float* ff_in_w      = (const float*)d_in[7];
    const float* ff_in_b      = (const float*)d_in[8];
    const float* ff_out_w     = (const float*)d_in[9];
    const float* ff_out_b     = (const float*)d_in[10];
    const float* final_norm_w = (const float*)d_in[11];

    float *t_, *x_, *qkv_, *fv_, *o_, *h_, *y1_;
    cudaGetSymbolAddress((void**)&t_,   g_t);
    cudaGetSymbolAddress((void**)&x_,   g_x);
    cudaGetSymbolAddress((void**)&qkv_, g_qkv);
    cudaGetSymbolAddress((void**)&fv_,  g_fv);
    cudaGetSymbolAddress((void**)&o_,   g_o);
    cudaGetSymbolAddress((void**)&h_,   g_h);
    cudaGetSymbolAddress((void**)&y1_,  g_y1);

    copy_k<<<(M_ * D_ / 4 + 255) / 256, 256>>>((const float4*)tokens, (float4*)t_, M_ * D_ / 4);

    for (int l = 0; l < L_; l++) {
        rmsnorm_k<<<M_, 128>>>(t_, attn_norm_w + l * D_, x_);

        sgemm128<<<dim3(QKVN / 128, M_ / 128), 256>>>(
            M_, QKVN, D_, x_, qkv_w + (size_t)l * D_ * QKVN, qkv_, nullptr, nullptr);

        if (l == 0)
            savefv_k<<<(M_ * DI) / 256, 256>>>(qkv_, fv_);
        else
            vmix_k<<<M_, 256>>>(x_, mix_w + (size_t)l * D_ * H_, mix_b + l * H_, qkv_, fv_);

        rope_k<<<M_, 256>>>(qkv_);

        attn_k<<<dim3(S_ / 32, B_ * H_), 128>>>(qkv_, o_);

        sgemm128<<<dim3(D_ / 128, M_ / 128), 256>>>(
            M_, D_, DI, o_, out_w + (size_t)l * DI * D_, t_, nullptr, t_);

        rmsnorm_k<<<M_, 128>>>(t_, ff_norm_w + l * D_, x_);

        sgemm128<<<dim3((2 * DHID + 127) / 128, M_ / 128), 256>>>(
            M_, 2 * DHID, D_, x_, ff_in_w + (size_t)l * D_ * 2 * DHID, h_,
            ff_in_b + (size_t)l * 2 * DHID, nullptr);

        gelu_k<<<(M_ * DHID + 255) / 256, 256>>>(h_, y1_);

        sgemm128<<<dim3(D_ / 128, M_ / 128), 256>>>(
            M_, D_, DHID, y1_, ff_out_w + (size_t)l * DHID * D_, t_,
            ff_out_b + (size_t)l * D_, t_);
    }

    rmsnorm_k<<<M_, 128>>>(t_, final_norm_w, (float*)d_out);
}

// round 4
// speedup vs baseline: 1.3180x; 1.3180x over previous
#include <cuda_runtime.h>
#include <cuda_bf16.h>
#include <math.h>
#include <stdint.h>

#define B_   2
#define S_   2048
#define D_   512
#define L_   4
#define H_   8
#define DH   64
#define M_   (B_*S_)      // 4096 rows
#define DI   512          // H*DH
#define QKVN 1536
#define DHID 1365
#define LDH_  2732        // padded row stride for ff_in output (16B-aligned rows)
#define LDY_  1368        // padded row stride for gelu output (16B-aligned rows)

// ---------------- scratch (no allocation allowed) ----------------
__device__ float g_t   [M_ * D_];          // residual stream
__device__ float g_x   [M_ * D_];          // normed activations
__device__ float g_qkv [M_ * QKVN];        // q|k|v packed per row
__device__ float g_fv  [M_ * DI];          // first layer's v
__device__ float g_o   [M_ * DI];          // attention output
__device__ float g_h   [(size_t)M_ * LDH_];// ff_in output (padded stride)
__device__ float g_y1  [(size_t)M_ * LDY_];// gated gelu output (padded stride)

// ---------------- helpers ----------------
// pack two f32 into bf16x2 (x -> low half, y -> high half)
__device__ __forceinline__ uint32_t pack_bf(float x, float y) {
    uint32_t r;
    asm("cvt.rn.bf16x2.f32 %0, %1, %2;" : "=r"(r) : "f"(y), "f"(x));
    return r;
}
// split (x,y) into hi bf16x2 + residual-lo bf16x2
__device__ __forceinline__ void split2(float x, float y, uint32_t& hi, uint32_t& lo) {
    hi = pack_bf(x, y);
    float rx = x - __uint_as_float(hi << 16);
    float ry = y - __uint_as_float(hi & 0xFFFF0000u);
    lo = pack_bf(rx, ry);
}

__device__ __forceinline__ void mma16816(float* c, const uint32_t* a, const uint32_t* b) {
    asm volatile(
        "mma.sync.aligned.m16n8k16.row.col.f32.bf16.bf16.f32 "
        "{%0,%1,%2,%3}, {%4,%5,%6,%7}, {%8,%9}, {%0,%1,%2,%3};"
        : "+f"(c[0]), "+f"(c[1]), "+f"(c[2]), "+f"(c[3])
        : "r"(a[0]), "r"(a[1]), "r"(a[2]), "r"(a[3]), "r"(b[0]), "r"(b[1]));
}

// ================= split-bf16 HMMA GEMM =================
// C[M,N] = A[M,K] @ B[K,N] (+bias)(+addsrc).  BM=BN=128, BK=32, 256 thr / 8 warps.
// Warp grid 2(M)x4(N); each warp: 64x32 = 4x4 m16n8k16 tiles. 3-product split-bf16.
__global__ void __launch_bounds__(256) gemm_mma(
    int N, int K, int lda, int ldb, int ldc,
    const float* __restrict__ A, const float* __restrict__ B,
    float* __restrict__ C, const float* __restrict__ bias,
    const float* __restrict__ addsrc)
{
    __shared__ uint32_t Ah[128][17], Al[128][17];   // [row][kpair], pad 17
    __shared__ uint32_t Bh[128][17], Bl[128][17];   // [col][kpair]

    int tid = threadIdx.x;
    int wid = tid >> 5, lane = tid & 31;
    int m0 = blockIdx.y * 128, n0 = blockIdx.x * 128;
    int wm = (wid >> 2) * 64, wn = (wid & 3) * 32;
    int g = lane >> 2, t = lane & 3;

    float acc[4][4][4];
    #pragma unroll
    for (int i = 0; i < 4; i++)
        #pragma unroll
        for (int j = 0; j < 4; j++)
            #pragma unroll
            for (int q = 0; q < 4; q++) acc[i][j][q] = 0.0f;

    int arow = tid >> 1, ah = (tid & 1) * 16;     // A: each thread 16 k of one row
    int bn = tid & 127, bhk = (tid >> 7) * 16;    // B: each thread 16 k of one col

    for (int k0 = 0; k0 < K; k0 += 32) {
        // ---- A tile -> smem (hi/lo) ----
        {
            const float* ap = A + (size_t)(m0 + arow) * lda + k0 + ah;
            #pragma unroll
            for (int i = 0; i < 4; i++) {
                int kk = k0 + ah + i * 4;
                float4 v;
                if (kk + 3 < K) {
                    v = *(const float4*)(ap + i * 4);
                } else {
                    v.x = (kk + 0 < K) ? ap[i * 4 + 0] : 0.0f;
                    v.y = (kk + 1 < K) ? ap[i * 4 + 1] : 0.0f;
                    v.z = (kk + 2 < K) ? ap[i * 4 + 2] : 0.0f;
                    v.w = (kk + 3 < K) ? ap[i * 4 + 3] : 0.0f;
                }
                uint32_t h0, l0, h1, l1;
                split2(v.x, v.y, h0, l0);
                split2(v.z, v.w, h1, l1);
                int kp = (ah >> 1) + i * 2;
                Ah[arow][kp] = h0; Ah[arow][kp + 1] = h1;
                Al[arow][kp] = l0; Al[arow][kp + 1] = l1;
            }
        }
        // ---- B tile -> smem transposed (hi/lo) ----
        {
            bool nv = (n0 + bn) < N;
            const float* bp = B + (size_t)(k0 + bhk) * ldb + n0 + bn;
            #pragma unroll
            for (int i = 0; i < 8; i++) {
                int kk = k0 + bhk + i * 2;
                float b0 = (nv && kk + 0 < K) ? bp[(size_t)(i * 2 + 0) * ldb] : 0.0f;
                float b1 = (nv && kk + 1 < K) ? bp[(size_t)(i * 2 + 1) * ldb] : 0.0f;
                uint32_t hi, lo;
                split2(b0, b1, hi, lo);
                int kp = (bhk >> 1) + i;
                Bh[bn][kp] = hi;
                Bl[bn][kp] = lo;
            }
        }
        __syncthreads();

        #pragma unroll
        for (int s = 0; s < 2; s++) {
            uint32_t afh[4][4], afl[4][4];
            #pragma unroll
            for (int mt = 0; mt < 4; mt++) {
                int r0 = wm + mt * 16 + g, r1 = r0 + 8;
                int kp = s * 8 + t;
                afh[mt][0] = Ah[r0][kp];     afh[mt][1] = Ah[r1][kp];
                afh[mt][2] = Ah[r0][kp + 4]; afh[mt][3] = Ah[r1][kp + 4];
                afl[mt][0] = Al[r0][kp];     afl[mt][1] = Al[r1][kp];
                afl[mt][2] = Al[r0][kp + 4]; afl[mt][3] = Al[r1][kp + 4];
            }
            uint32_t bfh[4][2], bfl[4][2];
            #pragma unroll
            for (int nt = 0; nt < 4; nt++) {
                int nr = wn + nt * 8 + g;
                int kp = s * 8 + t;
                bfh[nt][0] = Bh[nr][kp]; bfh[nt][1] = Bh[nr][kp + 4];
                bfl[nt][0] = Bl[nr][kp]; bfl[nt][1] = Bl[nr][kp + 4];
            }
            #pragma unroll
            for (int mt = 0; mt < 4; mt++)
                #pragma unroll
                for (int nt = 0; nt < 4; nt++) {
                    mma16816(acc[mt][nt], afh[mt], bfh[nt]);
                    mma16816(acc[mt][nt], afh[mt], bfl[nt]);
                    mma16816(acc[mt][nt], afl[mt], bfh[nt]);
                }
        }
        __syncthreads();
    }

    // ---- epilogue ----
    #pragma unroll
    for (int mt = 0; mt < 4; mt++) {
        int r0 = m0 + wm + mt * 16 + g;
        #pragma unroll
        for (int nt = 0; nt < 4; nt++) {
            int col = n0 + wn + nt * 8 + 2 * t;
            #pragma unroll
            for (int half = 0; half < 2; half++) {
                int row = r0 + half * 8;
                float v0 = acc[mt][nt][half * 2 + 0];
                float v1 = acc[mt][nt][half * 2 + 1];
                if (col < N) {
                    if (bias)   v0 += bias[col];
                    if (addsrc) v0 += addsrc[(size_t)row * ldc + col];
                    C[(size_t)row * ldc + col] = v0;
                }
                if (col + 1 < N) {
                    if (bias)   v1 += bias[col + 1];
                    if (addsrc) v1 += addsrc[(size_t)row * ldc + col + 1];
                    C[(size_t)row * ldc + col + 1] = v1;
                }
            }
        }
    }
}

// ---------------- elementwise copy ----------------
__global__ void copy_k(const float4* __restrict__ in, float4* __restrict__ out, int n4) {
    int i = blockIdx.x * blockDim.x + threadIdx.x;
    if (i < n4) out[i] = in[i];
}

// ---------------- rmsnorm: one block per row of 512 ----------------
__global__ void rmsnorm_k(const float* __restrict__ in, const float* __restrict__ w,
                          float* __restrict__ out) {
    int row = blockIdx.x;
    const float4* ip = (const float4*)(in + (size_t)row * D_);
    float4 v = ip[threadIdx.x];
    float ss = v.x*v.x + v.y*v.y + v.z*v.z + v.w*v.w;
    #pragma unroll
    for (int o = 16; o; o >>= 1) ss += __shfl_xor_sync(0xffffffffu, ss, o);
    __shared__ float sred[4];
    if ((threadIdx.x & 31) == 0) sred[threadIdx.x >> 5] = ss;
    __syncthreads();
    float tot = sred[0] + sred[1] + sred[2] + sred[3];
    float sc = rsqrtf(tot * (1.0f / 512.0f) + 1.1920929e-7f);
    const float4* wp = (const float4*)w;
    float4 wv = wp[threadIdx.x];
    float4 o4;
    o4.x = v.x * sc * wv.x; o4.y = v.y * sc * wv.y;
    o4.z = v.z * sc * wv.z; o4.w = v.w * sc * wv.w;
    ((float4*)(out + (size_t)row * D_))[threadIdx.x] = o4;
}

// ---------------- save first-layer v ----------------
__global__ void savefv_k(const float* __restrict__ qkv, float* __restrict__ fv) {
    int idx = blockIdx.x * blockDim.x + threadIdx.x;
    int row = idx >> 9, c = idx & 511;
    fv[idx] = qkv[(size_t)row * QKVN + 1024 + c];
}

// ---------------- v-mix (l>0): one warp per (row, head) ----------------
__global__ void vmix_k(const float* __restrict__ x, const float* __restrict__ mw,
                       const float* __restrict__ mb, float* __restrict__ qkv,
                       const float* __restrict__ fv) {
    int row = blockIdx.x;
    int lane = threadIdx.x & 31;
    int h = threadIdx.x >> 5;
    float dot = 0.0f;
    #pragma unroll
    for (int d = lane; d < 512; d += 32) dot += x[(size_t)row * 512 + d] * mw[d * 8 + h];
    #pragma unroll
    for (int o = 16; o; o >>= 1) dot += __shfl_xor_sync(0xffffffffu, dot, o);
    float mix = 1.0f / (1.0f + expf(-(dot + mb[h])));
    #pragma unroll
    for (int d = lane; d < 64; d += 32) {
        size_t vi = (size_t)row * QKVN + 1024 + h * 64 + d;
        float v = qkv[vi];
        float f = fv[(size_t)row * 512 + h * 64 + d];
        qkv[vi] = v + mix * (f - v);
    }
}

// ---------------- RoPE on q and k ----------------
__global__ void rope_k(float* __restrict__ qkv) {
    int idx = blockIdx.x * blockDim.x + threadIdx.x;
    int pair = idx & 31;
    int h    = (idx >> 5) & 7;
    int row  = idx >> 8;
    int pos  = row & (S_ - 1);
    float inv = expf(-logf(10000.0f) * (float)pair * (1.0f / 32.0f));
    float f = (float)pos * inv;
    float s, c;
    sincosf(f, &s, &c);
    size_t base = (size_t)row * QKVN + h * 64 + 2 * pair;
    float q1 = qkv[base], q2 = qkv[base + 1];
    qkv[base]     = q1 * c - q2 * s;
    qkv[base + 1] = q1 * s + q2 * c;
    float k1 = qkv[base + 512], k2 = qkv[base + 513];
    qkv[base + 512] = k1 * c - k2 * s;
    qkv[base + 513] = k1 * s + k2 * c;
}

// ---------------- block-causal flash attention ----------------
__global__ void attn_k(const float* __restrict__ qkv, float* __restrict__ o) {
    int qi = blockIdx.x;
    int h  = blockIdx.y & 7;
    int b  = blockIdx.y >> 3;
    __shared__ float Qs[32][65];
    __shared__ float Ks[32][65];
    __shared__ float Vs[32][65];
    int tid = threadIdx.x;
    int row0 = b * S_ + qi * 32;

    #pragma unroll
    for (int i = 0; i < 16; i++) {
        int e = i * 128 + tid;
        int r = e >> 6, d = e & 63;
        Qs[r][d] = qkv[(size_t)(row0 + r) * QKVN + h * 64 + d] * 0.125f;
    }

    int r = tid >> 2, cg = tid & 3;
    int lane = tid & 31;
    float m_prev = -INFINITY, lsum = 0.0f;
    float O[16];
    #pragma unroll
    for (int i = 0; i < 16; i++) O[i] = 0.0f;

    for (int j = 0; j <= qi; j++) {
        __syncthreads();
        int krow0 = b * S_ + j * 32;
        #pragma unroll
        for (int i = 0; i < 16; i++) {
            int e = i * 128 + tid;
            int rr = e >> 6, d = e & 63;
            size_t base = (size_t)(krow0 + rr) * QKVN + h * 64 + d;
            Ks[rr][d] = qkv[base + 512];
            Vs[rr][d] = qkv[base + 1024];
        }
        __syncthreads();

        float sc[8];
        #pragma unroll
        for (int c = 0; c < 8; c++) {
            float s = 0.0f;
            #pragma unroll
            for (int k = 0; k < 64; k++) s += Qs[r][k] * Ks[cg * 8 + c][k];
            sc[c] = s;
        }
        float mx = sc[0];
        #pragma unroll
        for (int c = 1; c < 8; c++) mx = fmaxf(mx, sc[c]);
        mx = fmaxf(mx, __shfl_xor_sync(0xffffffffu, mx, 1));
        mx = fmaxf(mx, __shfl_xor_sync(0xffffffffu, mx, 2));
        float m_new = fmaxf(m_prev, mx);
        float alpha = __expf(m_prev - m_new);

        float p[8];
        float psum = 0.0f;
        #pragma unroll
        for (int c = 0; c < 8; c++) { p[c] = __expf(sc[c] - m_new); psum += p[c]; }
        lsum = lsum * alpha + psum;
        #pragma unroll
        for (int d = 0; d < 16; d++) O[d] *= alpha;

        #pragma unroll
        for (int c = 0; c < 32; c++) {
            float pc = __shfl_sync(0xffffffffu, p[c & 7], (lane & ~3) | (c >> 3));
            #pragma unroll
            for (int d = 0; d < 16; d++) O[d] += pc * Vs[c][cg * 16 + d];
        }
        m_prev = m_new;
    }
    lsum += __shfl_xor_sync(0xffffffffu, lsum, 1);
    lsum += __shfl_xor_sync(0xffffffffu, lsum, 2);
    float inv = 1.0f / lsum;
    size_t ob = (size_t)(row0 + r) * 512 + h * 64 + cg * 16;
    #pragma unroll
    for (int d = 0; d < 16; d++) o[ob + d] = O[d] * inv;
}

// ---------------- gated exact GELU (padded strides) ----------------
__global__ void gelu_k(const float* __restrict__ hb, float* __restrict__ y1) {
    int idx = blockIdx.x * blockDim.x + threadIdx.x;
    if (idx >= M_ * DHID) return;
    int row = idx / DHID;
    int j   = idx - row * DHID;
    float a = hb[(size_t)row * LDH_ + j];
    float g = hb[(size_t)row * LDH_ + DHID + j];
    float ge = 0.5f * g * (1.0f + erff(g * 0.70710678118654752f));
    y1[(size_t)row * LDY_ + j] = a * ge;
}

// ---------------- launch ----------------
extern "C" void kernel_launch(void* const* d_in, const int* in_sizes, int n_in,
                              void* d_out, int out_size) {
    const float* tokens       = (const float*)d_in[0];
    const float* attn_norm_w  = (const float*)d_in[1];
    const float* qkv_w        = (const float*)d_in[2];
    const float* out_w        = (const float*)d_in[3];
    const float* mix_w        = (const float*)d_in[4];
    const float* mix_b        = (const float*)d_in[5];
    const float* ff_norm_w    = (const float*)d_in[6];
    const float* ff_in_w      = (const float*)d_in[7];
    const float* ff_in_b      = (const float*)d_in[8];
    const float* ff_out_w     = (const float*)d_in[9];
    const float* ff_out_b     = (const float*)d_in[10];
    const float* final_norm_w = (const float*)d_in[11];

    float *t_, *x_, *qkv_, *fv_, *o_, *h_, *y1_;
    cudaGetSymbolAddress((void**)&t_,   g_t);
    cudaGetSymbolAddress((void**)&x_,   g_x);
    cudaGetSymbolAddress((void**)&qkv_, g_qkv);
    cudaGetSymbolAddress((void**)&fv_,  g_fv);
    cudaGetSymbolAddress((void**)&o_,   g_o);
    cudaGetSymbolAddress((void**)&h_,   g_h);
    cudaGetSymbolAddress((void**)&y1_,  g_y1);

    copy_k<<<(M_ * D_ / 4 + 255) / 256, 256>>>((const float4*)tokens, (float4*)t_, M_ * D_ / 4);

    for (int l = 0; l < L_; l++) {
        rmsnorm_k<<<M_, 128>>>(t_, attn_norm_w + l * D_, x_);

        gemm_mma<<<dim3(QKVN / 128, M_ / 128), 256>>>(
            QKVN, D_, D_, QKVN, QKVN,
            x_, qkv_w + (size_t)l * D_ * QKVN, qkv_, nullptr, nullptr);

        if (l == 0)
            savefv_k<<<(M_ * DI) / 256, 256>>>(qkv_, fv_);
        else
            vmix_k<<<M_, 256>>>(x_, mix_w + (size_t)l * D_ * H_, mix_b + l * H_, qkv_, fv_);

        rope_k<<<M_, 256>>>(qkv_);

        attn_k<<<dim3(S_ / 32, B_ * H_), 128>>>(qkv_, o_);

        gemm_mma<<<dim3(D_ / 128, M_ / 128), 256>>>(
            D_, DI, DI, D_, D_,
            o_, out_w + (size_t)l * DI * D_, t_, nullptr, t_);

        rmsnorm_k<<<M_, 128>>>(t_, ff_norm_w + l * D_, x_);

        gemm_mma<<<dim3((2 * DHID + 127) / 128, M_ / 128), 256>>>(
            2 * DHID, D_, D_, 2 * DHID, LDH_,
            x_, ff_in_w + (size_t)l * D_ * 2 * DHID, h_,
            ff_in_b + (size_t)l * 2 * DHID, nullptr);

        gelu_k<<<(M_ * DHID + 255) / 256, 256>>>(h_, y1_);

        gemm_mma<<<dim3(D_ / 128, M_ / 128), 256>>>(
            D_, DHID, LDY_, D_, D_,
            y1_, ff_out_w + (size_t)l * DHID * D_, t_,
            ff_out_b + (size_t)l * D_, t_);
    }

    rmsnorm_k<<<M_, 128>>>(t_, final_norm_w, (float*)d_out);
}

// round 5
// speedup vs baseline: 2.2368x; 1.6971x over previous
#include <cuda_runtime.h>
#include <cuda_bf16.h>
#include <math.h>
#include <stdint.h>

#define B_   2
#define S_   2048
#define D_   512
#define L_   4
#define H_   8
#define DH   64
#define M_   (B_*S_)      // 4096 rows
#define DI   512          // H*DH
#define QKVN 1536
#define DHID 1365
#define LDH_  2732        // padded row stride for ff_in output (16B-aligned rows)
#define LDY_  1368        // padded row stride for gelu output (16B-aligned rows)

// ---------------- scratch (no allocation allowed) ----------------
__device__ float g_t   [M_ * D_];          // residual stream
__device__ float g_x   [M_ * D_];          // normed activations
__device__ float g_qkv [M_ * QKVN];        // q|k|v packed per row
__device__ float g_fv  [M_ * DI];          // first layer's v
__device__ float g_o   [M_ * DI];          // attention output
__device__ float g_h   [(size_t)M_ * LDH_];// ff_in output (padded stride)
__device__ float g_y1  [(size_t)M_ * LDY_];// gated gelu output (padded stride)

// ---------------- helpers ----------------
// pack two f32 into bf16x2 (x -> low half, y -> high half)
__device__ __forceinline__ uint32_t pack_bf(float x, float y) {
    uint32_t r;
    asm("cvt.rn.bf16x2.f32 %0, %1, %2;" : "=r"(r) : "f"(y), "f"(x));
    return r;
}
// split (x,y) into hi bf16x2 + residual-lo bf16x2
__device__ __forceinline__ void split2(float x, float y, uint32_t& hi, uint32_t& lo) {
    hi = pack_bf(x, y);
    float rx = x - __uint_as_float(hi << 16);
    float ry = y - __uint_as_float(hi & 0xFFFF0000u);
    lo = pack_bf(rx, ry);
}

__device__ __forceinline__ void mma16816(float* c, const uint32_t* a, const uint32_t* b) {
    asm volatile(
        "mma.sync.aligned.m16n8k16.row.col.f32.bf16.bf16.f32 "
        "{%0,%1,%2,%3}, {%4,%5,%6,%7}, {%8,%9}, {%0,%1,%2,%3};"
        : "+f"(c[0]), "+f"(c[1]), "+f"(c[2]), "+f"(c[3])
        : "r"(a[0]), "r"(a[1]), "r"(a[2]), "r"(a[3]), "r"(b[0]), "r"(b[1]));
}

// ================= split-bf16 HMMA GEMM =================
// C[M,N] = A[M,K] @ B[K,N] (+bias)(+addsrc).  BM=BN=128, BK=32, 256 thr / 8 warps.
__global__ void __launch_bounds__(256) gemm_mma(
    int N, int K, int lda, int ldb, int ldc,
    const float* __restrict__ A, const float* __restrict__ B,
    float* __restrict__ C, const float* __restrict__ bias,
    const float* __restrict__ addsrc)
{
    __shared__ uint32_t Ah[128][17], Al[128][17];   // [row][kpair], pad 17
    __shared__ uint32_t Bh[128][17], Bl[128][17];   // [col][kpair]

    int tid = threadIdx.x;
    int wid = tid >> 5, lane = tid & 31;
    int m0 = blockIdx.y * 128, n0 = blockIdx.x * 128;
    int wm = (wid >> 2) * 64, wn = (wid & 3) * 32;
    int g = lane >> 2, t = lane & 3;

    float acc[4][4][4];
    #pragma unroll
    for (int i = 0; i < 4; i++)
        #pragma unroll
        for (int j = 0; j < 4; j++)
            #pragma unroll
            for (int q = 0; q < 4; q++) acc[i][j][q] = 0.0f;

    int arow = tid >> 1, ah = (tid & 1) * 16;
    int bn = tid & 127, bhk = (tid >> 7) * 16;

    for (int k0 = 0; k0 < K; k0 += 32) {
        {
            const float* ap = A + (size_t)(m0 + arow) * lda + k0 + ah;
            #pragma unroll
            for (int i = 0; i < 4; i++) {
                int kk = k0 + ah + i * 4;
                float4 v;
                if (kk + 3 < K) {
                    v = *(const float4*)(ap + i * 4);
                } else {
                    v.x = (kk + 0 < K) ? ap[i * 4 + 0] : 0.0f;
                    v.y = (kk + 1 < K) ? ap[i * 4 + 1] : 0.0f;
                    v.z = (kk + 2 < K) ? ap[i * 4 + 2] : 0.0f;
                    v.w = (kk + 3 < K) ? ap[i * 4 + 3] : 0.0f;
                }
                uint32_t h0, l0, h1, l1;
                split2(v.x, v.y, h0, l0);
                split2(v.z, v.w, h1, l1);
                int kp = (ah >> 1) + i * 2;
                Ah[arow][kp] = h0; Ah[arow][kp + 1] = h1;
                Al[arow][kp] = l0; Al[arow][kp + 1] = l1;
            }
        }
        {
            bool nv = (n0 + bn) < N;
            const float* bp = B + (size_t)(k0 + bhk) * ldb + n0 + bn;
            #pragma unroll
            for (int i = 0; i < 8; i++) {
                int kk = k0 + bhk + i * 2;
                float b0 = (nv && kk + 0 < K) ? bp[(size_t)(i * 2 + 0) * ldb] : 0.0f;
                float b1 = (nv && kk + 1 < K) ? bp[(size_t)(i * 2 + 1) * ldb] : 0.0f;
                uint32_t hi, lo;
                split2(b0, b1, hi, lo);
                int kp = (bhk >> 1) + i;
                Bh[bn][kp] = hi;
                Bl[bn][kp] = lo;
            }
        }
        __syncthreads();

        #pragma unroll
        for (int s = 0; s < 2; s++) {
            uint32_t afh[4][4], afl[4][4];
            #pragma unroll
            for (int mt = 0; mt < 4; mt++) {
                int r0 = wm + mt * 16 + g, r1 = r0 + 8;
                int kp = s * 8 + t;
                afh[mt][0] = Ah[r0][kp];     afh[mt][1] = Ah[r1][kp];
                afh[mt][2] = Ah[r0][kp + 4]; afh[mt][3] = Ah[r1][kp + 4];
                afl[mt][0] = Al[r0][kp];     afl[mt][1] = Al[r1][kp];
                afl[mt][2] = Al[r0][kp + 4]; afl[mt][3] = Al[r1][kp + 4];
            }
            uint32_t bfh[4][2], bfl[4][2];
            #pragma unroll
            for (int nt = 0; nt < 4; nt++) {
                int nr = wn + nt * 8 + g;
                int kp = s * 8 + t;
                bfh[nt][0] = Bh[nr][kp]; bfh[nt][1] = Bh[nr][kp + 4];
                bfl[nt][0] = Bl[nr][kp]; bfl[nt][1] = Bl[nr][kp + 4];
            }
            #pragma unroll
            for (int mt = 0; mt < 4; mt++)
                #pragma unroll
                for (int nt = 0; nt < 4; nt++) {
                    mma16816(acc[mt][nt], afh[mt], bfh[nt]);
                    mma16816(acc[mt][nt], afh[mt], bfl[nt]);
                    mma16816(acc[mt][nt], afl[mt], bfh[nt]);
                }
        }
        __syncthreads();
    }

    #pragma unroll
    for (int mt = 0; mt < 4; mt++) {
        int r0 = m0 + wm + mt * 16 + g;
        #pragma unroll
        for (int nt = 0; nt < 4; nt++) {
            int col = n0 + wn + nt * 8 + 2 * t;
            #pragma unroll
            for (int half = 0; half < 2; half++) {
                int row = r0 + half * 8;
                float v0 = acc[mt][nt][half * 2 + 0];
                float v1 = acc[mt][nt][half * 2 + 1];
                if (col < N) {
                    if (bias)   v0 += bias[col];
                    if (addsrc) v0 += addsrc[(size_t)row * ldc + col];
                    C[(size_t)row * ldc + col] = v0;
                }
                if (col + 1 < N) {
                    if (bias)   v1 += bias[col + 1];
                    if (addsrc) v1 += addsrc[(size_t)row * ldc + col + 1];
                    C[(size_t)row * ldc + col + 1] = v1;
                }
            }
        }
    }
}

// ================= split-bf16 HMMA flash attention =================
// Br=Bc=64, 4 warps x 16 query rows. Block-causal at 32 granularity.
// grid (S_/64, B_*H_), 128 threads.
__global__ void __launch_bounds__(128) attn_mma(
    const float* __restrict__ qkv, float* __restrict__ o)
{
    __shared__ uint32_t Kh[64][36], Kl[64][36];   // [key][dh-pair], stride 36: conflict-free frags
    __shared__ uint32_t Vh[64][36], Vl[64][36];   // [dh][key-pair]

    int Qb = blockIdx.x;
    int h  = blockIdx.y & 7, b = blockIdx.y >> 3;
    int tid = threadIdx.x, w = tid >> 5, lane = tid & 31;
    int g = lane >> 2, t = lane & 3;
    int row0 = b * S_ + Qb * 64;

    // ---- Q fragments (scaled by 1/8), hi/lo split ----
    uint32_t qh[4][4], ql[4][4];
    {
        int r0 = w * 16 + g, r1 = r0 + 8;
        #pragma unroll
        for (int kt = 0; kt < 4; kt++) {
            #pragma unroll
            for (int q = 0; q < 4; q++) {
                int rr = (q & 1) ? r1 : r0;
                int kk = kt * 16 + 2 * t + ((q & 2) ? 8 : 0);
                const float2 v = *(const float2*)(qkv + (size_t)(row0 + rr) * QKVN + h * 64 + kk);
                split2(v.x * 0.125f, v.y * 0.125f, qh[kt][q], ql[kt][q]);
            }
        }
    }

    float Oa[8][4];
    #pragma unroll
    for (int i = 0; i < 8; i++)
        #pragma unroll
        for (int q = 0; q < 4; q++) Oa[i][q] = 0.0f;
    float m_[2] = {-INFINITY, -INFINITY};
    float l_[2] = {0.0f, 0.0f};

    int kq = tid >> 2, qq = tid & 3;   // loader roles

    for (int J = 0; J <= Qb; J++) {
        int kr = b * S_ + J * 64;
        __syncthreads();
        // ---- K tile: thread handles keys kq, kq+32; d = 2qq + 8i (float2) ----
        #pragma unroll
        for (int half = 0; half < 2; half++) {
            int ky = kq + half * 32;
            const float* kp_ = qkv + (size_t)(kr + ky) * QKVN + 512 + h * 64;
            #pragma unroll
            for (int i = 0; i < 8; i++) {
                int d = 2 * qq + 8 * i;
                float2 kv = *(const float2*)(kp_ + d);
                uint32_t hi, lo;
                split2(kv.x, kv.y, hi, lo);
                Kh[ky][d >> 1] = hi;
                Kl[ky][d >> 1] = lo;
            }
        }
        // ---- V tile transposed: thread handles key-pair kq(0..31), d = 2qq + 8i ----
        {
            const float* v0p = qkv + (size_t)(kr + 2 * kq) * QKVN + 1024 + h * 64;
            const float* v1p = v0p + QKVN;
            #pragma unroll
            for (int i = 0; i < 8; i++) {
                int d = 2 * qq + 8 * i;
                float2 a = *(const float2*)(v0p + d);
                float2 c = *(const float2*)(v1p + d);
                uint32_t hi, lo;
                split2(a.x, c.x, hi, lo);
                Vh[d][kq] = hi; Vl[d][kq] = lo;
                split2(a.y, c.y, hi, lo);
                Vh[d + 1][kq] = hi; Vl[d + 1][kq] = lo;
            }
        }
        __syncthreads();

        int diag = (J == Qb) && (w < 2);
        int ntS  = diag ? 4 : 8;   // S n-tiles (keys)
        int ktPV = diag ? 2 : 4;   // PV k-steps (keys)

        // ---- S = Q K^T ----
        float Sa[8][4];
        for (int nt = 0; nt < ntS; nt++) {
            Sa[nt][0] = Sa[nt][1] = Sa[nt][2] = Sa[nt][3] = 0.0f;
            #pragma unroll
            for (int kt = 0; kt < 4; kt++) {
                uint32_t bh[2] = { Kh[8 * nt + g][8 * kt + t], Kh[8 * nt + g][8 * kt + t + 4] };
                uint32_t bl[2] = { Kl[8 * nt + g][8 * kt + t], Kl[8 * nt + g][8 * kt + t + 4] };
                mma16816(Sa[nt], qh[kt], bh);
                mma16816(Sa[nt], qh[kt], bl);
                mma16816(Sa[nt], ql[kt], bh);
            }
        }

        // ---- online softmax (per row-half) ----
        float alpha[2];
        #pragma unroll
        for (int half = 0; half < 2; half++) {
            float mx = -INFINITY;
            for (int nt = 0; nt < ntS; nt++) {
                mx = fmaxf(mx, Sa[nt][half * 2]);
                mx = fmaxf(mx, Sa[nt][half * 2 + 1]);
            }
            mx = fmaxf(mx, __shfl_xor_sync(0xffffffffu, mx, 1));
            mx = fmaxf(mx, __shfl_xor_sync(0xffffffffu, mx, 2));
            float mn = fmaxf(m_[half], mx);
            alpha[half] = __expf(m_[half] - mn);
            m_[half] = mn;
            float ps = 0.0f;
            for (int nt = 0; nt < ntS; nt++) {
                float p0 = __expf(Sa[nt][half * 2]     - mn);
                float p1 = __expf(Sa[nt][half * 2 + 1] - mn);
                Sa[nt][half * 2]     = p0;
                Sa[nt][half * 2 + 1] = p1;
                ps += p0 + p1;
            }
            l_[half] = l_[half] * alpha[half] + ps;
        }
        #pragma unroll
        for (int nt = 0; nt < 8; nt++) {
            Oa[nt][0] *= alpha[0]; Oa[nt][1] *= alpha[0];
            Oa[nt][2] *= alpha[1]; Oa[nt][3] *= alpha[1];
        }

        // ---- P fragments ----
        uint32_t ph[4][4], pl[4][4];
        for (int kt = 0; kt < ktPV; kt++) {
            split2(Sa[2 * kt][0],     Sa[2 * kt][1],     ph[kt][0], pl[kt][0]);
            split2(Sa[2 * kt][2],     Sa[2 * kt][3],     ph[kt][1], pl[kt][1]);
            split2(Sa[2 * kt + 1][0], Sa[2 * kt + 1][1], ph[kt][2], pl[kt][2]);
            split2(Sa[2 * kt + 1][2], Sa[2 * kt + 1][3], ph[kt][3], pl[kt][3]);
        }

        // ---- O += P V ----
        #pragma unroll
        for (int nt = 0; nt < 8; nt++) {
            for (int kt = 0; kt < ktPV; kt++) {
                uint32_t bh[2] = { Vh[8 * nt + g][8 * kt + t], Vh[8 * nt + g][8 * kt + t + 4] };
                uint32_t bl[2] = { Vl[8 * nt + g][8 * kt + t], Vl[8 * nt + g][8 * kt + t + 4] };
                mma16816(Oa[nt], ph[kt], bh);
                mma16816(Oa[nt], ph[kt], bl);
                mma16816(Oa[nt], pl[kt], bh);
            }
        }
    }

    // ---- finalize ----
    float linv[2];
    #pragma unroll
    for (int half = 0; half < 2; half++) {
        float l = l_[half];
        l += __shfl_xor_sync(0xffffffffu, l, 1);
        l += __shfl_xor_sync(0xffffffffu, l, 2);
        linv[half] = 1.0f / l;
    }
    int r0 = w * 16 + g, r1 = r0 + 8;
    #pragma unroll
    for (int nt = 0; nt < 8; nt++) {
        int col = h * 64 + 8 * nt + 2 * t;
        float2 v0 = make_float2(Oa[nt][0] * linv[0], Oa[nt][1] * linv[0]);
        float2 v1 = make_float2(Oa[nt][2] * linv[1], Oa[nt][3] * linv[1]);
        *(float2*)(o + (size_t)(row0 + r0) * 512 + col) = v0;
        *(float2*)(o + (size_t)(row0 + r1) * 512 + col) = v1;
    }
}

// ---------------- elementwise copy ----------------
__global__ void copy_k(const float4* __restrict__ in, float4* __restrict__ out, int n4) {
    int i = blockIdx.x * blockDim.x + threadIdx.x;
    if (i < n4) out[i] = in[i];
}

// ---------------- rmsnorm: one block per row of 512 ----------------
__global__ void rmsnorm_k(const float* __restrict__ in, const float* __restrict__ w,
                          float* __restrict__ out) {
    int row = blockIdx.x;
    const float4* ip = (const float4*)(in + (size_t)row * D_);
    float4 v = ip[threadIdx.x];
    float ss = v.x*v.x + v.y*v.y + v.z*v.z + v.w*v.w;
    #pragma unroll
    for (int o = 16; o; o >>= 1) ss += __shfl_xor_sync(0xffffffffu, ss, o);
    __shared__ float sred[4];
    if ((threadIdx.x & 31) == 0) sred[threadIdx.x >> 5] = ss;
    __syncthreads();
    float tot = sred[0] + sred[1] + sred[2] + sred[3];
    float sc = rsqrtf(tot * (1.0f / 512.0f) + 1.1920929e-7f);
    const float4* wp = (const float4*)w;
    float4 wv = wp[threadIdx.x];
    float4 o4;
    o4.x = v.x * sc * wv.x; o4.y = v.y * sc * wv.y;
    o4.z = v.z * sc * wv.z; o4.w = v.w * sc * wv.w;
    ((float4*)(out + (size_t)row * D_))[threadIdx.x] = o4;
}

// ---------------- save first-layer v ----------------
__global__ void savefv_k(const float* __restrict__ qkv, float* __restrict__ fv) {
    int idx = blockIdx.x * blockDim.x + threadIdx.x;
    int row = idx >> 9, c = idx & 511;
    fv[idx] = qkv[(size_t)row * QKVN + 1024 + c];
}

// ---------------- v-mix (l>0): one warp per (row, head) ----------------
__global__ void vmix_k(const float* __restrict__ x, const float* __restrict__ mw,
                       const float* __restrict__ mb, float* __restrict__ qkv,
                       const float* __restrict__ fv) {
    int row = blockIdx.x;
    int lane = threadIdx.x & 31;
    int h = threadIdx.x >> 5;
    float dot = 0.0f;
    #pragma unroll
    for (int d = lane; d < 512; d += 32) dot += x[(size_t)row * 512 + d] * mw[d * 8 + h];
    #pragma unroll
    for (int o = 16; o; o >>= 1) dot += __shfl_xor_sync(0xffffffffu, dot, o);
    float mix = 1.0f / (1.0f + expf(-(dot + mb[h])));
    #pragma unroll
    for (int d = lane; d < 64; d += 32) {
        size_t vi = (size_t)row * QKVN + 1024 + h * 64 + d;
        float v = qkv[vi];
        float f = fv[(size_t)row * 512 + h * 64 + d];
        qkv[vi] = v + mix * (f - v);
    }
}

// ---------------- RoPE on q and k ----------------
__global__ void rope_k(float* __restrict__ qkv) {
    int idx = blockIdx.x * blockDim.x + threadIdx.x;
    int pair = idx & 31;
    int h    = (idx >> 5) & 7;
    int row  = idx >> 8;
    int pos  = row & (S_ - 1);
    float inv = expf(-logf(10000.0f) * (float)pair * (1.0f / 32.0f));
    float f = (float)pos * inv;
    float s, c;
    sincosf(f, &s, &c);
    size_t base = (size_t)row * QKVN + h * 64 + 2 * pair;
    float q1 = qkv[base], q2 = qkv[base + 1];
    qkv[base]     = q1 * c - q2 * s;
    qkv[base + 1] = q1 * s + q2 * c;
    float k1 = qkv[base + 512], k2 = qkv[base + 513];
    qkv[base + 512] = k1 * c - k2 * s;
    qkv[base + 513] = k1 * s + k2 * c;
}

// ---------------- gated exact GELU (padded strides) ----------------
__global__ void gelu_k(const float* __restrict__ hb, float* __restrict__ y1) {
    int idx = blockIdx.x * blockDim.x + threadIdx.x;
    if (idx >= M_ * DHID) return;
    int row = idx / DHID;
    int j   = idx - row * DHID;
    float a = hb[(size_t)row * LDH_ + j];
    float g = hb[(size_t)row * LDH_ + DHID + j];
    float ge = 0.5f * g * (1.0f + erff(g * 0.70710678118654752f));
    y1[(size_t)row * LDY_ + j] = a * ge;
}

// ---------------- launch ----------------
extern "C" void kernel_launch(void* const* d_in, const int* in_sizes, int n_in,
                              void* d_out, int out_size) {
    const float* tokens       = (const float*)d_in[0];
    const float* attn_norm_w  = (const float*)d_in[1];
    const float* qkv_w        = (const float*)d_in[2];
    const float* out_w        = (const float*)d_in[3];
    const float* mix_w        = (const float*)d_in[4];
    const float* mix_b        = (const float*)d_in[5];
    const float* ff_norm_w    = (const float*)d_in[6];
    const float* ff_in_w      = (const float*)d_in[7];
    const float* ff_in_b      = (const float*)d_in[8];
    const float* ff_out_w     = (const float*)d_in[9];
    const float* ff_out_b     = (const float*)d_in[10];
    const float* final_norm_w = (const float*)d_in[11];

    float *t_, *x_, *qkv_, *fv_, *o_, *h_, *y1_;
    cudaGetSymbolAddress((void**)&t_,   g_t);
    cudaGetSymbolAddress((void**)&x_,   g_x);
    cudaGetSymbolAddress((void**)&qkv_, g_qkv);
    cudaGetSymbolAddress((void**)&fv_,  g_fv);
    cudaGetSymbolAddress((void**)&o_,   g_o);
    cudaGetSymbolAddress((void**)&h_,   g_h);
    cudaGetSymbolAddress((void**)&y1_,  g_y1);

    copy_k<<<(M_ * D_ / 4 + 255) / 256, 256>>>((const float4*)tokens, (float4*)t_, M_ * D_ / 4);

    for (int l = 0; l < L_; l++) {
        rmsnorm_k<<<M_, 128>>>(t_, attn_norm_w + l * D_, x_);

        gemm_mma<<<dim3(QKVN / 128, M_ / 128), 256>>>(
            QKVN, D_, D_, QKVN, QKVN,
            x_, qkv_w + (size_t)l * D_ * QKVN, qkv_, nullptr, nullptr);

        if (l == 0)
            savefv_k<<<(M_ * DI) / 256, 256>>>(qkv_, fv_);
        else
            vmix_k<<<M_, 256>>>(x_, mix_w + (size_t)l * D_ * H_, mix_b + l * H_, qkv_, fv_);

        rope_k<<<M_, 256>>>(qkv_);

        attn_mma<<<dim3(S_ / 64, B_ * H_), 128>>>(qkv_, o_);

        gemm_mma<<<dim3(D_ / 128, M_ / 128), 256>>>(
            D_, DI, DI, D_, D_,
            o_, out_w + (size_t)l * DI * D_, t_, nullptr, t_);

        rmsnorm_k<<<M_, 128>>>(t_, ff_norm_w + l * D_, x_);

        gemm_mma<<<dim3((2 * DHID + 127) / 128, M_ / 128), 256>>>(
            2 * DHID, D_, D_, 2 * DHID, LDH_,
            x_, ff_in_w + (size_t)l * D_ * 2 * DHID, h_,
            ff_in_b + (size_t)l * 2 * DHID, nullptr);

        gelu_k<<<(M_ * DHID + 255) / 256, 256>>>(h_, y1_);

        gemm_mma<<<dim3(D_ / 128, M_ / 128), 256>>>(
            D_, DHID, LDY_, D_, D_,
            y1_, ff_out_w + (size_t)l * DHID * D_, t_,
            ff_out_b + (size_t)l * D_, t_);
    }

    rmsnorm_k<<<M_, 128>>>(t_, final_norm_w, (float*)d_out);
}

// round 7
// speedup vs baseline: 2.8213x; 1.2613x over previous
#include <cuda_runtime.h>
#include <cuda_bf16.h>
#include <math.h>
#include <stdint.h>

#define B_   2
#define S_   2048
#define D_   512
#define L_   4
#define H_   8
#define DH   64
#define M_   (B_*S_)      // 4096 rows
#define DI   512          // H*DH
#define QKVN 1536
#define DHID 1365
#define FFN  2730         // 2*DHID
#define LDH_ 2732         // padded row stride for ff_in output
#define KPX  256          // k-pairs for K=512
#define KPY  688          // k-pairs (padded) for K=1365

// ---------------- scratch (no allocation allowed) ----------------
__device__ float    g_t   [M_ * D_];            // residual stream
__device__ float    g_qkv [M_ * QKVN];          // q|k|v packed per row (fp32)
__device__ float    g_fv  [M_ * DI];            // first layer's v
__device__ float    g_h   [(size_t)M_ * LDH_];  // ff_in output
__device__ float    g_mix [M_ * H_];            // sigmoid gates
__device__ float2   g_rt  [S_ * 32];            // rope cos/sin table
__device__ uint32_t g_xh  [M_ * KPX], g_xl [M_ * KPX];   // rmsnorm out (split)
__device__ uint32_t g_oh  [M_ * KPX], g_ol [M_ * KPX];   // attn out (split)
__device__ uint32_t g_yh  [M_ * KPY], g_yl [M_ * KPY];   // gelu out (split)
// converted weights (transposed [N][Kp], hi/lo planes)
__device__ uint32_t g_wqh [L_ * QKVN * KPX], g_wql [L_ * QKVN * KPX];
__device__ uint32_t g_woh [L_ * DI   * KPX], g_wol [L_ * DI   * KPX];
__device__ uint32_t g_wfh [L_ * FFN  * KPX], g_wfl [L_ * FFN  * KPX];
__device__ uint32_t g_wgh [L_ * DI   * KPY], g_wgl [L_ * DI   * KPY];

// ---------------- helpers ----------------
__device__ __forceinline__ uint32_t smem_u32(const void* p) {
    uint32_t a;
    asm("{ .reg .u64 t; cvta.to.shared.u64 t, %1; cvt.u32.u64 %0, t; }" : "=r"(a) : "l"(p));
    return a;
}
__device__ __forceinline__ uint32_t pack_bf(float x, float y) {
    uint32_t r;
    asm("cvt.rn.bf16x2.f32 %0, %1, %2;" : "=r"(r) : "f"(y), "f"(x));
    return r;
}
__device__ __forceinline__ void split2(float x, float y, uint32_t& hi, uint32_t& lo) {
    hi = pack_bf(x, y);
    float rx = x - __uint_as_float(hi << 16);
    float ry = y - __uint_as_float(hi & 0xFFFF0000u);
    lo = pack_bf(rx, ry);
}
__device__ __forceinline__ void mma16816(float* c, const uint32_t* a, const uint32_t* b) {
    asm volatile(
        "mma.sync.aligned.m16n8k16.row.col.f32.bf16.bf16.f32 "
        "{%0,%1,%2,%3}, {%4,%5,%6,%7}, {%8,%9}, {%0,%1,%2,%3};"
        : "+f"(c[0]), "+f"(c[1]), "+f"(c[2]), "+f"(c[3])
        : "r"(a[0]), "r"(a[1]), "r"(a[2]), "r"(a[3]), "r"(b[0]), "r"(b[1]));
}
__device__ __forceinline__ void cp16(uint32_t dst, const void* src, int sz) {
    asm volatile("cp.async.ca.shared.global [%0], [%1], 16, %2;"
                 :: "r"(dst), "l"(src), "r"(sz) : "memory");
}

// ---------------- weight convert: W[K][N] fp32 -> Wh/Wl [N][Kps] ----------------
__global__ void wconv_k(const float* __restrict__ W, uint32_t* __restrict__ Wh,
                        uint32_t* __restrict__ Wl, int K, int N, int Kps) {
    __shared__ float2 tile[32][33];
    int kp0 = blockIdx.x * 32, n0 = blockIdx.y * 32;
    int tx = threadIdx.x, ty = threadIdx.y;   // 32 x 8
    #pragma unroll
    for (int j = 0; j < 4; j++) {
        int kp = kp0 + ty + j * 8, k = 2 * kp, n = n0 + tx;
        float a = 0.0f, b = 0.0f;
        if (n < N) {
            if (k < K)     a = W[(size_t)k * N + n];
            if (k + 1 < K) b = W[(size_t)(k + 1) * N + n];
        }
        tile[ty + j * 8][tx] = make_float2(a, b);
    }
    __syncthreads();
    #pragma unroll
    for (int j = 0; j < 4; j++) {
        int n = n0 + ty + j * 8, kp = kp0 + tx;
        if (n < N && kp < Kps) {
            float2 v = tile[tx][ty + j * 8];
            uint32_t hi, lo;
            split2(v.x, v.y, hi, lo);
            Wh[(size_t)n * Kps + kp] = hi;
            Wl[(size_t)n * Kps + kp] = lo;
        }
    }
}

// ---------------- rope table ----------------
__global__ void ropetab_k(float2* __restrict__ rt) {
    int idx = blockIdx.x * 256 + threadIdx.x;
    if (idx >= S_ * 32) return;
    int pair = idx & 31, pos = idx >> 5;
    float inv = expf(-logf(10000.0f) * (float)pair * (1.0f / 32.0f));
    float s, c;
    sincosf((float)pos * inv, &s, &c);
    rt[idx] = make_float2(c, s);
}

// ================= split-bf16 HMMA GEMM (pre-split operands, cp.async) =============
// C[M,N] = A[M,K] @ B[K,N] (+bias)(+addsrc). BM=BN=128, BK=32 (16 kpairs).
__global__ void __launch_bounds__(256, 2) gemm_bs(
    int N, int Kp, int ldap, int ldbp, int ldc,
    const uint32_t* __restrict__ Agh, const uint32_t* __restrict__ Agl,
    const uint32_t* __restrict__ Bgh, const uint32_t* __restrict__ Bgl,
    float* __restrict__ C, const float* __restrict__ bias,
    const float* __restrict__ addsrc)
{
    __shared__ uint32_t sAh[128][20], sAl[128][20], sBh[128][20], sBl[128][20];
    int tid = threadIdx.x;
    int wid = tid >> 5, lane = tid & 31;
    int m0 = blockIdx.y * 128, n0 = blockIdx.x * 128;
    int wm = (wid >> 2) * 64, wn = (wid & 3) * 32;
    int g = lane >> 2, t = lane & 3;

    float acc[4][4][4];
    #pragma unroll
    for (int i = 0; i < 4; i++)
        #pragma unroll
        for (int j = 0; j < 4; j++)
            #pragma unroll
            for (int q = 0; q < 4; q++) acc[i][j][q] = 0.0f;

    uint32_t bAh = smem_u32(sAh), bAl = smem_u32(sAl);
    uint32_t bBh = smem_u32(sBh), bBl = smem_u32(sBl);

    for (int kp0 = 0; kp0 < Kp; kp0 += 16) {
        #pragma unroll
        for (int i = 0; i < 2; i++) {
            int e = i * 256 + tid;
            int row = e >> 2, seg = (e & 3) * 4;
            uint32_t soff = (uint32_t)(row * 20 + seg) * 4;
            size_t aoff = (size_t)(m0 + row) * ldap + kp0 + seg;
            cp16(bAh + soff, Agh + aoff, 16);
            cp16(bAl + soff, Agl + aoff, 16);
            int nn = n0 + row;
            int sz = (nn < N) ? 16 : 0;
            size_t boff = (size_t)(nn < N ? nn : 0) * ldbp + kp0 + seg;
            cp16(bBh + soff, Bgh + boff, sz);
            cp16(bBl + soff, Bgl + boff, sz);
        }
        asm volatile("cp.async.commit_group;" ::: "memory");
        asm volatile("cp.async.wait_group 0;" ::: "memory");
        __syncthreads();

        #pragma unroll
        for (int s = 0; s < 2; s++) {
            int kp = s * 8 + t;
            uint32_t afh[4][4], afl[4][4];
            #pragma unroll
            for (int mt = 0; mt < 4; mt++) {
                int r0 = wm + mt * 16 + g, r1 = r0 + 8;
                afh[mt][0] = sAh[r0][kp];     afh[mt][1] = sAh[r1][kp];
                afh[mt][2] = sAh[r0][kp + 4]; afh[mt][3] = sAh[r1][kp + 4];
                afl[mt][0] = sAl[r0][kp];     afl[mt][1] = sAl[r1][kp];
                afl[mt][2] = sAl[r0][kp + 4]; afl[mt][3] = sAl[r1][kp + 4];
            }
            uint32_t bfh[4][2], bfl[4][2];
            #pragma unroll
            for (int nt = 0; nt < 4; nt++) {
                int nr = wn + nt * 8 + g;
                bfh[nt][0] = sBh[nr][kp]; bfh[nt][1] = sBh[nr][kp + 4];
                bfl[nt][0] = sBl[nr][kp]; bfl[nt][1] = sBl[nr][kp + 4];
            }
            #pragma unroll
            for (int mt = 0; mt < 4; mt++)
                #pragma unroll
                for (int nt = 0; nt < 4; nt++) {
                    mma16816(acc[mt][nt], afh[mt], bfh[nt]);
                    mma16816(acc[mt][nt], afh[mt], bfl[nt]);
                    mma16816(acc[mt][nt], afl[mt], bfh[nt]);
                }
        }
        __syncthreads();
    }

    #pragma unroll
    for (int mt = 0; mt < 4; mt++) {
        int r0 = m0 + wm + mt * 16 + g;
        #pragma unroll
        for (int nt = 0; nt < 4; nt++) {
            int col = n0 + wn + nt * 8 + 2 * t;
            #pragma unroll
            for (int half = 0; half < 2; half++) {
                int row = r0 + half * 8;
                float v0 = acc[mt][nt][half * 2 + 0];
                float v1 = acc[mt][nt][half * 2 + 1];
                if (col < N) {
                    if (bias)   v0 += bias[col];
                    if (addsrc) v0 += addsrc[(size_t)row * ldc + col];
                    C[(size_t)row * ldc + col] = v0;
                }
                if (col + 1 < N) {
                    if (bias)   v1 += bias[col + 1];
                    if (addsrc) v1 += addsrc[(size_t)row * ldc + col + 1];
                    C[(size_t)row * ldc + col + 1] = v1;
                }
            }
        }
    }
}

// ================= split-bf16 HMMA flash attention (fused rope + vmix) ============
// Br=Bc=64, 4 warps x 16 query rows. grid (S_/64, B_*H_), 128 threads.
__global__ void __launch_bounds__(128) attn_mma(
    const float* __restrict__ qkv, const float* __restrict__ fv,
    const float* __restrict__ mix, const float2* __restrict__ rt,
    uint32_t* __restrict__ Oh, uint32_t* __restrict__ Ol)
{
    __shared__ uint32_t Kh[64][36], Kl[64][36];
    __shared__ uint32_t Vh[64][36], Vl[64][36];

    int Qb = blockIdx.x;
    int h  = blockIdx.y & 7, b = blockIdx.y >> 3;
    int tid = threadIdx.x, w = tid >> 5, lane = tid & 31;
    int g = lane >> 2, t = lane & 3;
    int row0 = b * S_ + Qb * 64;

    // ---- Q fragments: rope + scale + split ----
    uint32_t qh[4][4], ql[4][4];
    {
        int r0 = w * 16 + g, r1 = r0 + 8;
        #pragma unroll
        for (int kt = 0; kt < 4; kt++) {
            #pragma unroll
            for (int q = 0; q < 4; q++) {
                int rr = (q & 1) ? r1 : r0;
                int kk = kt * 16 + 2 * t + ((q & 2) ? 8 : 0);
                float2 v = *(const float2*)(qkv + (size_t)(row0 + rr) * QKVN + h * 64 + kk);
                float2 cs = rt[(Qb * 64 + rr) * 32 + (kk >> 1)];
                float q1 = v.x * cs.x - v.y * cs.y;
                float q2 = v.x * cs.y + v.y * cs.x;
                split2(q1 * 0.125f, q2 * 0.125f, qh[kt][q], ql[kt][q]);
            }
        }
    }

    float Oa[8][4];
    #pragma unroll
    for (int i = 0; i < 8; i++)
        #pragma unroll
        for (int q = 0; q < 4; q++) Oa[i][q] = 0.0f;
    float m_[2] = {-INFINITY, -INFINITY};
    float l_[2] = {0.0f, 0.0f};

    int kq = tid >> 2, qq = tid & 3;

    for (int J = 0; J <= Qb; J++) {
        int kr = b * S_ + J * 64;
        __syncthreads();
        // ---- K tile: rope + split ----
        #pragma unroll
        for (int half = 0; half < 2; half++) {
            int ky = kq + half * 32;
            const float* kp_ = qkv + (size_t)(kr + ky) * QKVN + 512 + h * 64;
            int posk = J * 64 + ky;
            #pragma unroll
            for (int i = 0; i < 8; i++) {
                int d = 2 * qq + 8 * i;
                float2 kv = *(const float2*)(kp_ + d);
                float2 cs = rt[posk * 32 + (d >> 1)];
                float k1 = kv.x * cs.x - kv.y * cs.y;
                float k2 = kv.x * cs.y + kv.y * cs.x;
                uint32_t hi, lo;
                split2(k1, k2, hi, lo);
                Kh[ky][d >> 1] = hi;
                Kl[ky][d >> 1] = lo;
            }
        }
        // ---- V tile transposed, with optional vmix ----
        {
            int vrow = kr + 2 * kq;
            const float* v0p = qkv + (size_t)vrow * QKVN + 1024 + h * 64;
            const float* v1p = v0p + QKVN;
            float mix0 = 0.0f, mix1 = 0.0f;
            if (mix) {
                mix0 = mix[(size_t)vrow * H_ + h];
                mix1 = mix[(size_t)(vrow + 1) * H_ + h];
            }
            #pragma unroll
            for (int i = 0; i < 8; i++) {
                int d = 2 * qq + 8 * i;
                float2 a = *(const float2*)(v0p + d);
                float2 c2 = *(const float2*)(v1p + d);
                if (mix) {
                    float2 fa = *(const float2*)(fv + (size_t)vrow * DI + h * 64 + d);
                    float2 fc = *(const float2*)(fv + (size_t)(vrow + 1) * DI + h * 64 + d);
                    a.x  += mix0 * (fa.x - a.x);   a.y  += mix0 * (fa.y - a.y);
                    c2.x += mix1 * (fc.x - c2.x);  c2.y += mix1 * (fc.y - c2.y);
                }
                uint32_t hi, lo;
                split2(a.x, c2.x, hi, lo);
                Vh[d][kq] = hi; Vl[d][kq] = lo;
                split2(a.y, c2.y, hi, lo);
                Vh[d + 1][kq] = hi; Vl[d + 1][kq] = lo;
            }
        }
        __syncthreads();

        int diag = (J == Qb) && (w < 2);
        int ntS  = diag ? 4 : 8;
        int ktPV = diag ? 2 : 4;

        float Sa[8][4];
        for (int nt = 0; nt < ntS; nt++) {
            Sa[nt][0] = Sa[nt][1] = Sa[nt][2] = Sa[nt][3] = 0.0f;
            #pragma unroll
            for (int kt = 0; kt < 4; kt++) {
                uint32_t bh[2] = { Kh[8 * nt + g][8 * kt + t], Kh[8 * nt + g][8 * kt + t + 4] };
                uint32_t bl[2] = { Kl[8 * nt + g][8 * kt + t], Kl[8 * nt + g][8 * kt + t + 4] };
                mma16816(Sa[nt], qh[kt], bh);
                mma16816(Sa[nt], qh[kt], bl);
                mma16816(Sa[nt], ql[kt], bh);
            }
        }

        float alpha[2];
        #pragma unroll
        for (int half = 0; half < 2; half++) {
            float mx = -INFINITY;
            for (int nt = 0; nt < ntS; nt++) {
                mx = fmaxf(mx, Sa[nt][half * 2]);
                mx = fmaxf(mx, Sa[nt][half * 2 + 1]);
            }
            mx = fmaxf(mx, __shfl_xor_sync(0xffffffffu, mx, 1));
            mx = fmaxf(mx, __shfl_xor_sync(0xffffffffu, mx, 2));
            float mn = fmaxf(m_[half], mx);
            alpha[half] = __expf(m_[half] - mn);
            m_[half] = mn;
            float ps = 0.0f;
            for (int nt = 0; nt < ntS; nt++) {
                float p0 = __expf(Sa[nt][half * 2]     - mn);
                float p1 = __expf(Sa[nt][half * 2 + 1] - mn);
                Sa[nt][half * 2]     = p0;
                Sa[nt][half * 2 + 1] = p1;
                ps += p0 + p1;
            }
            l_[half] = l_[half] * alpha[half] + ps;
        }
        #pragma unroll
        for (int nt = 0; nt < 8; nt++) {
            Oa[nt][0] *= alpha[0]; Oa[nt][1] *= alpha[0];
            Oa[nt][2] *= alpha[1]; Oa[nt][3] *= alpha[1];
        }

        uint32_t ph[4][4], pl[4][4];
        for (int kt = 0; kt < ktPV; kt++) {
            split2(Sa[2 * kt][0],     Sa[2 * kt][1],     ph[kt][0], pl[kt][0]);
            split2(Sa[2 * kt][2],     Sa[2 * kt][3],     ph[kt][1], pl[kt][1]);
            split2(Sa[2 * kt + 1][0], Sa[2 * kt + 1][1], ph[kt][2], pl[kt][2]);
            split2(Sa[2 * kt + 1][2], Sa[2 * kt + 1][3], ph[kt][3], pl[kt][3]);
        }

        #pragma unroll
        for (int nt = 0; nt < 8; nt++) {
            for (int kt = 0; kt < ktPV; kt++) {
                uint32_t bh[2] = { Vh[8 * nt + g][8 * kt + t], Vh[8 * nt + g][8 * kt + t + 4] };
                uint32_t bl[2] = { Vl[8 * nt + g][8 * kt + t], Vl[8 * nt + g][8 * kt + t + 4] };
                mma16816(Oa[nt], ph[kt], bh);
                mma16816(Oa[nt], ph[kt], bl);
                mma16816(Oa[nt], pl[kt], bh);
            }
        }
    }

    float linv[2];
    #pragma unroll
    for (int half = 0; half < 2; half++) {
        float l = l_[half];
        l += __shfl_xor_sync(0xffffffffu, l, 1);
        l += __shfl_xor_sync(0xffffffffu, l, 2);
        linv[half] = 1.0f / l;
    }
    int r0 = w * 16 + g, r1 = r0 + 8;
    #pragma unroll
    for (int nt = 0; nt < 8; nt++) {
        int kp = h * 32 + 4 * nt + t;
        uint32_t hi, lo;
        split2(Oa[nt][0] * linv[0], Oa[nt][1] * linv[0], hi, lo);
        Oh[(size_t)(row0 + r0) * KPX + kp] = hi;
        Ol[(size_t)(row0 + r0) * KPX + kp] = lo;
        split2(Oa[nt][2] * linv[1], Oa[nt][3] * linv[1], hi, lo);
        Oh[(size_t)(row0 + r1) * KPX + kp] = hi;
        Ol[(size_t)(row0 + r1) * KPX + kp] = lo;
    }
}

// ---------------- elementwise copy ----------------
__global__ void copy_k(const float4* __restrict__ in, float4* __restrict__ out, int n4) {
    int i = blockIdx.x * blockDim.x + threadIdx.x;
    if (i < n4) out[i] = in[i];
}

// ---------------- rmsnorm -> split output ----------------
__global__ void rmsnorm_split_k(const float* __restrict__ in, const float* __restrict__ w,
                                uint32_t* __restrict__ Xh, uint32_t* __restrict__ Xl) {
    int row = blockIdx.x;
    const float4* ip = (const float4*)(in + (size_t)row * D_);
    float4 v = ip[threadIdx.x];
    float ss = v.x*v.x + v.y*v.y + v.z*v.z + v.w*v.w;
    #pragma unroll
    for (int o = 16; o; o >>= 1) ss += __shfl_xor_sync(0xffffffffu, ss, o);
    __shared__ float sred[4];
    if ((threadIdx.x & 31) == 0) sred[threadIdx.x >> 5] = ss;
    __syncthreads();
    float tot = sred[0] + sred[1] + sred[2] + sred[3];
    float sc = rsqrtf(tot * (1.0f / 512.0f) + 1.1920929e-7f);
    const float4* wp = (const float4*)w;
    float4 wv = wp[threadIdx.x];
    float o0 = v.x * sc * wv.x, o1 = v.y * sc * wv.y;
    float o2 = v.z * sc * wv.z, o3 = v.w * sc * wv.w;
    uint32_t h0, l0, h1, l1;
    split2(o0, o1, h0, l0);
    split2(o2, o3, h1, l1);
    size_t base = (size_t)row * KPX + threadIdx.x * 2;
    Xh[base] = h0; Xh[base + 1] = h1;
    Xl[base] = l0; Xl[base + 1] = l1;
}

// ---------------- rmsnorm fp32 out (final) ----------------
__global__ void rmsnorm_k(const float* __restrict__ in, const float* __restrict__ w,
                          float* __restrict__ out) {
    int row = blockIdx.x;
    const float4* ip = (const float4*)(in + (size_t)row * D_);
    float4 v = ip[threadIdx.x];
    float ss = v.x*v.x + v.y*v.y + v.z*v.z + v.w*v.w;
    #pragma unroll
    for (int o = 16; o; o >>= 1) ss += __shfl_xor_sync(0xffffffffu, ss, o);
    __shared__ float sred[4];
    if ((threadIdx.x & 31) == 0) sred[threadIdx.x >> 5] = ss;
    __syncthreads();
    float tot = sred[0] + sred[1] + sred[2] + sred[3];
    float sc = rsqrtf(tot * (1.0f / 512.0f) + 1.1920929e-7f);
    const float4* wp = (const float4*)w;
    float4 wv = wp[threadIdx.x];
    float4 o4;
    o4.x = v.x * sc * wv.x; o4.y = v.y * sc * wv.y;
    o4.z = v.z * sc * wv.z; o4.w = v.w * sc * wv.w;
    ((float4*)(out + (size_t)row * D_))[threadIdx.x] = o4;
}

// ---------------- save first-layer v ----------------
__global__ void savefv_k(const float* __restrict__ qkv, float* __restrict__ fv) {
    int idx = blockIdx.x * blockDim.x + threadIdx.x;
    int row = idx >> 9, c = idx & 511;
    fv[idx] = qkv[(size_t)row * QKVN + 1024 + c];
}

// ---------------- mix gate: sigmoid(x @ mw + mb), x from split ----------------
__global__ void mix_k(const uint32_t* __restrict__ Xh, const uint32_t* __restrict__ Xl,
                      const float* __restrict__ mw, const float* __restrict__ mb,
                      float* __restrict__ mix) {
    int row = blockIdx.x;
    int lane = threadIdx.x & 31;
    int h = threadIdx.x >> 5;
    float dot = 0.0f;
    #pragma unroll
    for (int kp = lane; kp < KPX; kp += 32) {
        uint32_t hv = Xh[(size_t)row * KPX + kp], lv = Xl[(size_t)row * KPX + kp];
        float x0 = __uint_as_float(hv << 16) + __uint_as_float(lv << 16);
        float x1 = __uint_as_float(hv & 0xFFFF0000u) + __uint_as_float(lv & 0xFFFF0000u);
        dot += x0 * mw[(2 * kp) * H_ + h] + x1 * mw[(2 * kp + 1) * H_ + h];
    }
    #pragma unroll
    for (int o = 16; o; o >>= 1) dot += __shfl_xor_sync(0xffffffffu, dot, o);
    if (lane == 0)
        mix[(size_t)row * H_ + h] = 1.0f / (1.0f + expf(-(dot + mb[h])));
}

// ---------------- gated exact GELU -> split output ----------------
__global__ void gelu_k(const float* __restrict__ hb, uint32_t* __restrict__ Yh,
                       uint32_t* __restrict__ Yl) {
    int idx = blockIdx.x * blockDim.x + threadIdx.x;
    if (idx >= M_ * KPY) return;
    int row = idx / KPY;
    int kp  = idx - row * KPY;
    int j = 2 * kp;
    float y0 = 0.0f, y1 = 0.0f;
    if (j < DHID) {
        float a = hb[(size_t)row * LDH_ + j];
        float gg = hb[(size_t)row * LDH_ + DHID + j];
        y0 = a * 0.5f * gg * (1.0f + erff(gg * 0.70710678118654752f));
    }
    if (j + 1 < DHID) {
        float a = hb[(size_t)row * LDH_ + j + 1];
        float gg = hb[(size_t)row * LDH_ + DHID + j + 1];
        y1 = a * 0.5f * gg * (1.0f + erff(gg * 0.70710678118654752f));
    }
    uint32_t hi, lo;
    split2(y0, y1, hi, lo);
    Yh[(size_t)row * KPY + kp] = hi;
    Yl[(size_t)row * KPY + kp] = lo;
}

// ---------------- launch ----------------
extern "C" void kernel_launch(void* const* d_in, const int* in_sizes, int n_in,
                              void* d_out, int out_size) {
    const float* tokens       = (const float*)d_in[0];
    const float* attn_norm_w  = (const float*)d_in[1];
    const float* qkv_w        = (const float*)d_in[2];
    const float* out_w        = (const float*)d_in[3];
    const float* mix_w        = (const float*)d_in[4];
    const float* mix_b        = (const float*)d_in[5];
    const float* ff_norm_w    = (const float*)d_in[6];
    const float* ff_in_w      = (const float*)d_in[7];
    const float* ff_in_b      = (const float*)d_in[8];
    const float* ff_out_w     = (const float*)d_in[9];
    const float* ff_out_b     = (const float*)d_in[10];
    const float* final_norm_w = (const float*)d_in[11];

    float *t_, *qkv_, *fv_, *h_, *mix_;
    float2* rt_;
    uint32_t *xh_, *xl_, *oh_, *ol_, *yh_, *yl_;
    uint32_t *wqh_, *wql_, *woh_, *wol_, *wfh_, *wfl_, *wgh_, *wgl_;
    cudaGetSymbolAddress((void**)&t_,   g_t);
    cudaGetSymbolAddress((void**)&qkv_, g_qkv);
    cudaGetSymbolAddress((void**)&fv_,  g_fv);
    cudaGetSymbolAddress((void**)&h_,   g_h);
    cudaGetSymbolAddress((void**)&mix_, g_mix);
    cudaGetSymbolAddress((void**)&rt_,  g_rt);
    cudaGetSymbolAddress((void**)&xh_,  g_xh);
    cudaGetSymbolAddress((void**)&xl_,  g_xl);
    cudaGetSymbolAddress((void**)&oh_,  g_oh);
    cudaGetSymbolAddress((void**)&ol_,  g_ol);
    cudaGetSymbolAddress((void**)&yh_,  g_yh);
    cudaGetSymbolAddress((void**)&yl_,  g_yl);
    cudaGetSymbolAddress((void**)&wqh_, g_wqh);
    cudaGetSymbolAddress((void**)&wql_, g_wql);
    cudaGetSymbolAddress((void**)&woh_, g_woh);
    cudaGetSymbolAddress((void**)&wol_, g_wol);
    cudaGetSymbolAddress((void**)&wfh_, g_wfh);
    cudaGetSymbolAddress((void**)&wfl_, g_wfl);
    cudaGetSymbolAddress((void**)&wgh_, g_wgh);
    cudaGetSymbolAddress((void**)&wgl_, g_wgl);

    copy_k<<<(M_ * D_ / 4 + 255) / 256, 256>>>((const float4*)tokens, (float4*)t_, M_ * D_ / 4);
    ropetab_k<<<(S_ * 32 + 255) / 256, 256>>>(rt_);

    dim3 cb(32, 8);
    for (int l = 0; l < L_; l++) {
        wconv_k<<<dim3(KPX / 32, QKVN / 32), cb>>>(
            qkv_w + (size_t)l * D_ * QKVN, wqh_ + (size_t)l * QKVN * KPX,
            wql_ + (size_t)l * QKVN * KPX, D_, QKVN, KPX);
        wconv_k<<<dim3(KPX / 32, DI / 32), cb>>>(
            out_w + (size_t)l * DI * D_, woh_ + (size_t)l * DI * KPX,
            wol_ + (size_t)l * DI * KPX, DI, D_, KPX);
        wconv_k<<<dim3(KPX / 32, (FFN + 31) / 32), cb>>>(
            ff_in_w + (size_t)l * D_ * FFN, wfh_ + (size_t)l * FFN * KPX,
            wfl_ + (size_t)l * FFN * KPX, D_, FFN, KPX);
        wconv_k<<<dim3((KPY + 31) / 32, DI / 32), cb>>>(
            ff_out_w + (size_t)l * DHID * D_, wgh_ + (size_t)l * DI * KPY,
            wgl_ + (size_t)l * DI * KPY, DHID, D_, KPY);
    }

    for (int l = 0; l < L_; l++) {
        rmsnorm_split_k<<<M_, 128>>>(t_, attn_norm_w + l * D_, xh_, xl_);

        gemm_bs<<<dim3(QKVN / 128, M_ / 128), 256>>>(
            QKVN, KPX, KPX, KPX, QKVN,
            xh_, xl_, wqh_ + (size_t)l * QKVN * KPX, wql_ + (size_t)l * QKVN * KPX,
            qkv_, nullptr, nullptr);

        const float* mixp = nullptr;
        if (l == 0) {
            savefv_k<<<(M_ * DI) / 256, 256>>>(qkv_, fv_);
        } else {
            mix_k<<<M_, 256>>>(xh_, xl_, mix_w + (size_t)l * D_ * H_, mix_b + l * H_, mix_);
            mixp = mix_;
        }

        attn_mma<<<dim3(S_ / 64, B_ * H_), 128>>>(qkv_, fv_, mixp, rt_, oh_, ol_);

        gemm_bs<<<dim3(D_ / 128, M_ / 128), 256>>>(
            D_, KPX, KPX, KPX, D_,
            oh_, ol_, woh_ + (size_t)l * DI * KPX, wol_ + (size_t)l * DI * KPX,
            t_, nullptr, t_);

        rmsnorm_split_k<<<M_, 128>>>(t_, ff_norm_w + l * D_, xh_, xl_);

        gemm_bs<<<dim3((FFN + 127) / 128, M_ / 128), 256>>>(
            FFN, KPX, KPX, KPX, LDH_,
            xh_, xl_, wfh_ + (size_t)l * FFN * KPX, wfl_ + (size_t)l * FFN * KPX,
            h_, ff_in_b + (size_t)l * FFN, nullptr);

        gelu_k<<<(M_ * KPY + 255) / 256, 256>>>(h_, yh_, yl_);

        gemm_bs<<<dim3(D_ / 128, M_ / 128), 256>>>(
            D_, KPY, KPY, KPY, D_,
            yh_, yl_, wgh_ + (size_t)l * DI * KPY, wgl_ + (size_t)l * DI * KPY,
            t_, ff_out_b + (size_t)l * D_, t_);
    }

    rmsnorm_k<<<M_, 128>>>(t_, final_norm_w, (float*)d_out);
}

// round 8
// speedup vs baseline: 2.9874x; 1.0589x over previous
#include <cuda_runtime.h>
#include <cuda_bf16.h>
#include <math.h>
#include <stdint.h>

#define B_   2
#define S_   2048
#define D_   512
#define L_   4
#define H_   8
#define DH   64
#define M_   (B_*S_)      // 4096 rows
#define DI   512          // H*DH
#define QKVN 1536
#define DHID 1365
#define FFN  2730         // 2*DHID
#define KPX  256          // k-pairs for K=512
#define KPY  688          // k-pairs (padded) for K=1365

// ---------------- scratch (no allocation allowed) ----------------
__device__ float    g_t   [M_ * D_];            // residual stream
__device__ float    g_qkv [M_ * QKVN];          // q|k|v packed per row (fp32)
__device__ float    g_fv  [M_ * DI];            // first layer's v
__device__ float    g_mix [M_ * H_];            // sigmoid gates
__device__ float2   g_rt  [S_ * 32];            // rope cos/sin table
__device__ uint32_t g_xh  [M_ * KPX], g_xl [M_ * KPX];   // rmsnorm out (split)
__device__ uint32_t g_oh  [M_ * KPX], g_ol [M_ * KPX];   // attn out (split)
__device__ uint32_t g_yh  [M_ * KPY], g_yl [M_ * KPY];   // gelu out (split; padding stays 0)
// converted weights (transposed [N][Kp], hi/lo planes)
__device__ uint32_t g_wqh [L_ * QKVN * KPX], g_wql [L_ * QKVN * KPX];
__device__ uint32_t g_woh [L_ * DI   * KPX], g_wol [L_ * DI   * KPX];
__device__ uint32_t g_wfh [L_ * FFN  * KPX], g_wfl [L_ * FFN  * KPX];
__device__ uint32_t g_wgh [L_ * DI   * KPY], g_wgl [L_ * DI   * KPY];

// ---------------- helpers ----------------
__device__ __forceinline__ uint32_t smem_u32(const void* p) {
    uint32_t a;
    asm("{ .reg .u64 t; cvta.to.shared.u64 t, %1; cvt.u32.u64 %0, t; }" : "=r"(a) : "l"(p));
    return a;
}
__device__ __forceinline__ uint32_t pack_bf(float x, float y) {
    uint32_t r;
    asm("cvt.rn.bf16x2.f32 %0, %1, %2;" : "=r"(r) : "f"(y), "f"(x));
    return r;
}
__device__ __forceinline__ void split2(float x, float y, uint32_t& hi, uint32_t& lo) {
    hi = pack_bf(x, y);
    float rx = x - __uint_as_float(hi << 16);
    float ry = y - __uint_as_float(hi & 0xFFFF0000u);
    lo = pack_bf(rx, ry);
}
__device__ __forceinline__ void mma16816(float* c, const uint32_t* a, const uint32_t* b) {
    asm volatile(
        "mma.sync.aligned.m16n8k16.row.col.f32.bf16.bf16.f32 "
        "{%0,%1,%2,%3}, {%4,%5,%6,%7}, {%8,%9}, {%0,%1,%2,%3};"
        : "+f"(c[0]), "+f"(c[1]), "+f"(c[2]), "+f"(c[3])
        : "r"(a[0]), "r"(a[1]), "r"(a[2]), "r"(a[3]), "r"(b[0]), "r"(b[1]));
}
__device__ __forceinline__ void cp16(uint32_t dst, const void* src, int sz) {
    asm volatile("cp.async.ca.shared.global [%0], [%1], 16, %2;"
                 :: "r"(dst), "l"(src), "r"(sz) : "memory");
}

// ---------------- weight convert: W[K][N] fp32 -> Wh/Wl [N][Kps]; z = layer --------
// ilv != 0: output column n' maps to orig col (n'&1) ? (n'>>1)+DHID : (n'>>1)
__global__ void wconv_k(const float* __restrict__ W0, uint32_t* __restrict__ Wh0,
                        uint32_t* __restrict__ Wl0, int K, int N, int Kps, int ilv,
                        size_t wstride, size_t pstride) {
    const float* W = W0 + blockIdx.z * wstride;
    uint32_t* Wh = Wh0 + blockIdx.z * pstride;
    uint32_t* Wl = Wl0 + blockIdx.z * pstride;
    __shared__ float2 tile[32][33];
    int kp0 = blockIdx.x * 32, n0 = blockIdx.y * 32;
    int tx = threadIdx.x, ty = threadIdx.y;   // 32 x 8
    #pragma unroll
    for (int j = 0; j < 4; j++) {
        int kp = kp0 + ty + j * 8, k = 2 * kp, n = n0 + tx;
        int on = n;
        if (ilv) on = (n & 1) ? (n >> 1) + DHID : (n >> 1);
        float a = 0.0f, b = 0.0f;
        if (n < N) {
            if (k < K)     a = W[(size_t)k * N + on];
            if (k + 1 < K) b = W[(size_t)(k + 1) * N + on];
        }
        tile[ty + j * 8][tx] = make_float2(a, b);
    }
    __syncthreads();
    #pragma unroll
    for (int j = 0; j < 4; j++) {
        int n = n0 + ty + j * 8, kp = kp0 + tx;
        if (n < N && kp < Kps) {
            float2 v = tile[tx][ty + j * 8];
            uint32_t hi, lo;
            split2(v.x, v.y, hi, lo);
            Wh[(size_t)n * Kps + kp] = hi;
            Wl[(size_t)n * Kps + kp] = lo;
        }
    }
}

// ---------------- rope table ----------------
__global__ void ropetab_k(float2* __restrict__ rt) {
    int idx = blockIdx.x * 256 + threadIdx.x;
    if (idx >= S_ * 32) return;
    int pair = idx & 31, pos = idx >> 5;
    float inv = expf(-logf(10000.0f) * (float)pair * (1.0f / 32.0f));
    float s, c;
    sincosf((float)pos * inv, &s, &c);
    rt[idx] = make_float2(c, s);
}

// ================= split-bf16 HMMA GEMM, double-buffered cp.async =================
// mode 0: C[M,N] fp32 (+bias)(+addsrc). mode 1: gated-GELU epilogue -> Yh/Yl split.
#define SM_CH 2560          // uint32 per plane (128*20)
#define SM_BUF 10240        // uint32 per buffer (4 planes)
__global__ void __launch_bounds__(256, 2) gemm_bs(
    int N, int Kp, int ldap, int ldbp, int ldc,
    const uint32_t* __restrict__ Agh, const uint32_t* __restrict__ Agl,
    const uint32_t* __restrict__ Bgh, const uint32_t* __restrict__ Bgl,
    float* __restrict__ C, const float* __restrict__ bias,
    const float* __restrict__ addsrc, int mode,
    uint32_t* __restrict__ Yh, uint32_t* __restrict__ Yl)
{
    extern __shared__ uint32_t sm[];
    int tid = threadIdx.x;
    int wid = tid >> 5, lane = tid & 31;
    int m0 = blockIdx.y * 128, n0 = blockIdx.x * 128;
    int wm = (wid >> 2) * 64, wn = (wid & 3) * 32;
    int g = lane >> 2, t = lane & 3;

    float acc[4][4][4];
    #pragma unroll
    for (int i = 0; i < 4; i++)
        #pragma unroll
        for (int j = 0; j < 4; j++)
            #pragma unroll
            for (int q = 0; q < 4; q++) acc[i][j][q] = 0.0f;

    uint32_t smb = smem_u32(sm);
    int nch = Kp >> 4;

    // chunk loader: 2 iterations x 4 cp16 per thread
    auto load_chunk = [&](int c, int buf) {
        int kp0 = c << 4;
        uint32_t base = smb + (uint32_t)buf * (SM_BUF * 4);
        #pragma unroll
        for (int i = 0; i < 2; i++) {
            int e = i * 256 + tid;
            int row = e >> 2, seg = (e & 3) * 4;
            uint32_t soff = (uint32_t)(row * 20 + seg) * 4;
            size_t aoff = (size_t)(m0 + row) * ldap + kp0 + seg;
            cp16(base + soff, Agh + aoff, 16);
            cp16(base + SM_CH * 4 + soff, Agl + aoff, 16);
            int nn = n0 + row;
            int sz = (nn < N) ? 16 : 0;
            size_t boff = (size_t)(nn < N ? nn : 0) * ldbp + kp0 + seg;
            cp16(base + SM_CH * 8 + soff, Bgh + boff, sz);
            cp16(base + SM_CH * 12 + soff, Bgl + boff, sz);
        }
        asm volatile("cp.async.commit_group;" ::: "memory");
    };

    load_chunk(0, 0);
    for (int c = 0; c < nch; c++) {
        if (c + 1 < nch) {
            load_chunk(c + 1, (c + 1) & 1);
            asm volatile("cp.async.wait_group 1;" ::: "memory");
        } else {
            asm volatile("cp.async.wait_group 0;" ::: "memory");
        }
        __syncthreads();

        const uint32_t* pAh = sm + (c & 1) * SM_BUF;
        const uint32_t* pAl = pAh + SM_CH;
        const uint32_t* pBh = pAh + SM_CH * 2;
        const uint32_t* pBl = pAh + SM_CH * 3;

        #pragma unroll
        for (int s = 0; s < 2; s++) {
            int kp = s * 8 + t;
            uint32_t afh[4][4], afl[4][4];
            #pragma unroll
            for (int mt = 0; mt < 4; mt++) {
                int r0 = wm + mt * 16 + g, r1 = r0 + 8;
                afh[mt][0] = pAh[r0 * 20 + kp];     afh[mt][1] = pAh[r1 * 20 + kp];
                afh[mt][2] = pAh[r0 * 20 + kp + 4]; afh[mt][3] = pAh[r1 * 20 + kp + 4];
                afl[mt][0] = pAl[r0 * 20 + kp];     afl[mt][1] = pAl[r1 * 20 + kp];
                afl[mt][2] = pAl[r0 * 20 + kp + 4]; afl[mt][3] = pAl[r1 * 20 + kp + 4];
            }
            uint32_t bfh[4][2], bfl[4][2];
            #pragma unroll
            for (int nt = 0; nt < 4; nt++) {
                int nr = wn + nt * 8 + g;
                bfh[nt][0] = pBh[nr * 20 + kp]; bfh[nt][1] = pBh[nr * 20 + kp + 4];
                bfl[nt][0] = pBl[nr * 20 + kp]; bfl[nt][1] = pBl[nr * 20 + kp + 4];
            }
            #pragma unroll
            for (int mt = 0; mt < 4; mt++)
                #pragma unroll
                for (int nt = 0; nt < 4; nt++) {
                    mma16816(acc[mt][nt], afh[mt], bfh[nt]);
                    mma16816(acc[mt][nt], afh[mt], bfl[nt]);
                    mma16816(acc[mt][nt], afl[mt], bfh[nt]);
                }
        }
        __syncthreads();
    }

    if (mode == 0) {
        #pragma unroll
        for (int mt = 0; mt < 4; mt++) {
            int r0 = m0 + wm + mt * 16 + g;
            #pragma unroll
            for (int nt = 0; nt < 4; nt++) {
                int col = n0 + wn + nt * 8 + 2 * t;
                #pragma unroll
                for (int half = 0; half < 2; half++) {
                    int row = r0 + half * 8;
                    float v0 = acc[mt][nt][half * 2 + 0];
                    float v1 = acc[mt][nt][half * 2 + 1];
                    if (col < N) {
                        if (bias)   v0 += bias[col];
                        if (addsrc) v0 += addsrc[(size_t)row * ldc + col];
                        C[(size_t)row * ldc + col] = v0;
                    }
                    if (col + 1 < N) {
                        if (bias)   v1 += bias[col + 1];
                        if (addsrc) v1 += addsrc[(size_t)row * ldc + col + 1];
                        C[(size_t)row * ldc + col + 1] = v1;
                    }
                }
            }
        }
    } else {
        // gated-GELU epilogue: cols (2j, 2j+1) = (a_j, g_j); y_j = a*gelu(g)
        #pragma unroll
        for (int mt = 0; mt < 4; mt++) {
            int r0 = m0 + wm + mt * 16 + g;
            #pragma unroll
            for (int nt = 0; nt < 4; nt++) {
                int col = n0 + wn + nt * 8 + 2 * t;
                int j = col >> 1;
                bool valid = col < N;
                #pragma unroll
                for (int half = 0; half < 2; half++) {
                    int row = r0 + half * 8;
                    float y = 0.0f;
                    if (valid) {
                        float a  = acc[mt][nt][half * 2 + 0] + bias[j];
                        float gg = acc[mt][nt][half * 2 + 1] + bias[j + DHID];
                        y = a * 0.5f * gg * (1.0f + erff(gg * 0.70710678118654752f));
                    }
                    float y1 = __shfl_down_sync(0xffffffffu, y, 1);
                    if ((t & 1) == 0) {
                        int kp = j >> 1;
                        if (kp < KPY) {
                            uint32_t hi, lo;
                            split2(y, y1, hi, lo);
                            Yh[(size_t)row * KPY + kp] = hi;
                            Yl[(size_t)row * KPY + kp] = lo;
                        }
                    }
                }
            }
        }
    }
}

// ================= split-bf16 HMMA flash attention (fused rope + vmix) ============
__global__ void __launch_bounds__(128) attn_mma(
    const float* __restrict__ qkv, const float* __restrict__ fv,
    const float* __restrict__ mix, const float2* __restrict__ rt,
    uint32_t* __restrict__ Oh, uint32_t* __restrict__ Ol)
{
    __shared__ uint32_t Kh[64][36], Kl[64][36];
    __shared__ uint32_t Vh[64][36], Vl[64][36];

    int Qb = blockIdx.x;
    int h  = blockIdx.y & 7, b = blockIdx.y >> 3;
    int tid = threadIdx.x, w = tid >> 5, lane = tid & 31;
    int g = lane >> 2, t = lane & 3;
    int row0 = b * S_ + Qb * 64;

    uint32_t qh[4][4], ql[4][4];
    {
        int r0 = w * 16 + g, r1 = r0 + 8;
        #pragma unroll
        for (int kt = 0; kt < 4; kt++) {
            #pragma unroll
            for (int q = 0; q < 4; q++) {
                int rr = (q & 1) ? r1 : r0;
                int kk = kt * 16 + 2 * t + ((q & 2) ? 8 : 0);
                float2 v = *(const float2*)(qkv + (size_t)(row0 + rr) * QKVN + h * 64 + kk);
                float2 cs = rt[(Qb * 64 + rr) * 32 + (kk >> 1)];
                float q1 = v.x * cs.x - v.y * cs.y;
                float q2 = v.x * cs.y + v.y * cs.x;
                split2(q1 * 0.125f, q2 * 0.125f, qh[kt][q], ql[kt][q]);
            }
        }
    }

    float Oa[8][4];
    #pragma unroll
    for (int i = 0; i < 8; i++)
        #pragma unroll
        for (int q = 0; q < 4; q++) Oa[i][q] = 0.0f;
    float m_[2] = {-INFINITY, -INFINITY};
    float l_[2] = {0.0f, 0.0f};

    int kq = tid >> 2, qq = tid & 3;

    for (int J = 0; J <= Qb; J++) {
        int kr = b * S_ + J * 64;
        __syncthreads();
        #pragma unroll
        for (int half = 0; half < 2; half++) {
            int ky = kq + half * 32;
            const float* kp_ = qkv + (size_t)(kr + ky) * QKVN + 512 + h * 64;
            int posk = J * 64 + ky;
            #pragma unroll
            for (int i = 0; i < 8; i++) {
                int d = 2 * qq + 8 * i;
                float2 kv = *(const float2*)(kp_ + d);
                float2 cs = rt[posk * 32 + (d >> 1)];
                float k1 = kv.x * cs.x - kv.y * cs.y;
                float k2 = kv.x * cs.y + kv.y * cs.x;
                uint32_t hi, lo;
                split2(k1, k2, hi, lo);
                Kh[ky][d >> 1] = hi;
                Kl[ky][d >> 1] = lo;
            }
        }
        {
            int vrow = kr + 2 * kq;
            const float* v0p = qkv + (size_t)vrow * QKVN + 1024 + h * 64;
            const float* v1p = v0p + QKVN;
            float mix0 = 0.0f, mix1 = 0.0f;
            if (mix) {
                mix0 = mix[(size_t)vrow * H_ + h];
                mix1 = mix[(size_t)(vrow + 1) * H_ + h];
            }
            #pragma unroll
            for (int i = 0; i < 8; i++) {
                int d = 2 * qq + 8 * i;
                float2 a = *(const float2*)(v0p + d);
                float2 c2 = *(const float2*)(v1p + d);
                if (mix) {
                    float2 fa = *(const float2*)(fv + (size_t)vrow * DI + h * 64 + d);
                    float2 fc = *(const float2*)(fv + (size_t)(vrow + 1) * DI + h * 64 + d);
                    a.x  += mix0 * (fa.x - a.x);   a.y  += mix0 * (fa.y - a.y);
                    c2.x += mix1 * (fc.x - c2.x);  c2.y += mix1 * (fc.y - c2.y);
                }
                uint32_t hi, lo;
                split2(a.x, c2.x, hi, lo);
                Vh[d][kq] = hi; Vl[d][kq] = lo;
                split2(a.y, c2.y, hi, lo);
                Vh[d + 1][kq] = hi; Vl[d + 1][kq] = lo;
            }
        }
        __syncthreads();

        int diag = (J == Qb) && (w < 2);
        int ntS  = diag ? 4 : 8;
        int ktPV = diag ? 2 : 4;

        float Sa[8][4];
        for (int nt = 0; nt < ntS; nt++) {
            Sa[nt][0] = Sa[nt][1] = Sa[nt][2] = Sa[nt][3] = 0.0f;
            #pragma unroll
            for (int kt = 0; kt < 4; kt++) {
                uint32_t bh[2] = { Kh[8 * nt + g][8 * kt + t], Kh[8 * nt + g][8 * kt + t + 4] };
                uint32_t bl[2] = { Kl[8 * nt + g][8 * kt + t], Kl[8 * nt + g][8 * kt + t + 4] };
                mma16816(Sa[nt], qh[kt], bh);
                mma16816(Sa[nt], qh[kt], bl);
                mma16816(Sa[nt], ql[kt], bh);
            }
        }

        float alpha[2];
        #pragma unroll
        for (int half = 0; half < 2; half++) {
            float mx = -INFINITY;
            for (int nt = 0; nt < ntS; nt++) {
                mx = fmaxf(mx, Sa[nt][half * 2]);
                mx = fmaxf(mx, Sa[nt][half * 2 + 1]);
            }
            mx = fmaxf(mx, __shfl_xor_sync(0xffffffffu, mx, 1));
            mx = fmaxf(mx, __shfl_xor_sync(0xffffffffu, mx, 2));
            float mn = fmaxf(m_[half], mx);
            alpha[half] = __expf(m_[half] - mn);
            m_[half] = mn;
            float ps = 0.0f;
            for (int nt = 0; nt < ntS; nt++) {
                float p0 = __expf(Sa[nt][half * 2]     - mn);
                float p1 = __expf(Sa[nt][half * 2 + 1] - mn);
                Sa[nt][half * 2]     = p0;
                Sa[nt][half * 2 + 1] = p1;
                ps += p0 + p1;
            }
            l_[half] = l_[half] * alpha[half] + ps;
        }
        #pragma unroll
        for (int nt = 0; nt < 8; nt++) {
            Oa[nt][0] *= alpha[0]; Oa[nt][1] *= alpha[0];
            Oa[nt][2] *= alpha[1]; Oa[nt][3] *= alpha[1];
        }

        uint32_t ph[4][4], pl[4][4];
        for (int kt = 0; kt < ktPV; kt++) {
            split2(Sa[2 * kt][0],     Sa[2 * kt][1],     ph[kt][0], pl[kt][0]);
            split2(Sa[2 * kt][2],     Sa[2 * kt][3],     ph[kt][1], pl[kt][1]);
            split2(Sa[2 * kt + 1][0], Sa[2 * kt + 1][1], ph[kt][2], pl[kt][2]);
            split2(Sa[2 * kt + 1][2], Sa[2 * kt + 1][3], ph[kt][3], pl[kt][3]);
        }

        #pragma unroll
        for (int nt = 0; nt < 8; nt++) {
            for (int kt = 0; kt < ktPV; kt++) {
                uint32_t bh[2] = { Vh[8 * nt + g][8 * kt + t], Vh[8 * nt + g][8 * kt + t + 4] };
                uint32_t bl[2] = { Vl[8 * nt + g][8 * kt + t], Vl[8 * nt + g][8 * kt + t + 4] };
                mma16816(Oa[nt], ph[kt], bh);
                mma16816(Oa[nt], ph[kt], bl);
                mma16816(Oa[nt], pl[kt], bh);
            }
        }
    }

    float linv[2];
    #pragma unroll
    for (int half = 0; half < 2; half++) {
        float l = l_[half];
        l += __shfl_xor_sync(0xffffffffu, l, 1);
        l += __shfl_xor_sync(0xffffffffu, l, 2);
        linv[half] = 1.0f / l;
    }
    int r0 = w * 16 + g, r1 = r0 + 8;
    #pragma unroll
    for (int nt = 0; nt < 8; nt++) {
        int kp = h * 32 + 4 * nt + t;
        uint32_t hi, lo;
        split2(Oa[nt][0] * linv[0], Oa[nt][1] * linv[0], hi, lo);
        Oh[(size_t)(row0 + r0) * KPX + kp] = hi;
        Ol[(size_t)(row0 + r0) * KPX + kp] = lo;
        split2(Oa[nt][2] * linv[1], Oa[nt][3] * linv[1], hi, lo);
        Oh[(size_t)(row0 + r1) * KPX + kp] = hi;
        Ol[(size_t)(row0 + r1) * KPX + kp] = lo;
    }
}

// ---------------- elementwise copy ----------------
__global__ void copy_k(const float4* __restrict__ in, float4* __restrict__ out, int n4) {
    int i = blockIdx.x * blockDim.x + threadIdx.x;
    if (i < n4) out[i] = in[i];
}

// ---------------- rmsnorm -> split output ----------------
__global__ void rmsnorm_split_k(const float* __restrict__ in, const float* __restrict__ w,
                                uint32_t* __restrict__ Xh, uint32_t* __restrict__ Xl) {
    int row = blockIdx.x;
    const float4* ip = (const float4*)(in + (size_t)row * D_);
    float4 v = ip[threadIdx.x];
    float ss = v.x*v.x + v.y*v.y + v.z*v.z + v.w*v.w;
    #pragma unroll
    for (int o = 16; o; o >>= 1) ss += __shfl_xor_sync(0xffffffffu, ss, o);
    __shared__ float sred[4];
    if ((threadIdx.x & 31) == 0) sred[threadIdx.x >> 5] = ss;
    __syncthreads();
    float tot = sred[0] + sred[1] + sred[2] + sred[3];
    float sc = rsqrtf(tot * (1.0f / 512.0f) + 1.1920929e-7f);
    const float4* wp = (const float4*)w;
    float4 wv = wp[threadIdx.x];
    float o0 = v.x * sc * wv.x, o1 = v.y * sc * wv.y;
    float o2 = v.z * sc * wv.z, o3 = v.w * sc * wv.w;
    uint32_t h0, l0, h1, l1;
    split2(o0, o1, h0, l0);
    split2(o2, o3, h1, l1);
    size_t base = (size_t)row * KPX + threadIdx.x * 2;
    Xh[base] = h0; Xh[base + 1] = h1;
    Xl[base] = l0; Xl[base + 1] = l1;
}

// ---------------- rmsnorm fp32 out (final) ----------------
__global__ void rmsnorm_k(const float* __restrict__ in, const float* __restrict__ w,
                          float* __restrict__ out) {
    int row = blockIdx.x;
    const float4* ip = (const float4*)(in + (size_t)row * D_);
    float4 v = ip[threadIdx.x];
    float ss = v.x*v.x + v.y*v.y + v.z*v.z + v.w*v.w;
    #pragma unroll
    for (int o = 16; o; o >>= 1) ss += __shfl_xor_sync(0xffffffffu, ss, o);
    __shared__ float sred[4];
    if ((threadIdx.x & 31) == 0) sred[threadIdx.x >> 5] = ss;
    __syncthreads();
    float tot = sred[0] + sred[1] + sred[2] + sred[3];
    float sc = rsqrtf(tot * (1.0f / 512.0f) + 1.1920929e-7f);
    const float4* wp = (const float4*)w;
    float4 wv = wp[threadIdx.x];
    float4 o4;
    o4.x = v.x * sc * wv.x; o4.y = v.y * sc * wv.y;
    o4.z = v.z * sc * wv.z; o4.w = v.w * sc * wv.w;
    ((float4*)(out + (size_t)row * D_))[threadIdx.x] = o4;
}

// ---------------- save first-layer v ----------------
__global__ void savefv_k(const float* __restrict__ qkv, float* __restrict__ fv) {
    int idx = blockIdx.x * blockDim.x + threadIdx.x;
    int row = idx >> 9, c = idx & 511;
    fv[idx] = qkv[(size_t)row * QKVN + 1024 + c];
}

// ---------------- mix gate ----------------
__global__ void mix_k(const uint32_t* __restrict__ Xh, const uint32_t* __restrict__ Xl,
                      const float* __restrict__ mw, const float* __restrict__ mb,
                      float* __restrict__ mix) {
    int row = blockIdx.x;
    int lane = threadIdx.x & 31;
    int h = threadIdx.x >> 5;
    float dot = 0.0f;
    #pragma unroll
    for (int kp = lane; kp < KPX; kp += 32) {
        uint32_t hv = Xh[(size_t)row * KPX + kp], lv = Xl[(size_t)row * KPX + kp];
        float x0 = __uint_as_float(hv << 16) + __uint_as_float(lv << 16);
        float x1 = __uint_as_float(hv & 0xFFFF0000u) + __uint_as_float(lv & 0xFFFF0000u);
        dot += x0 * mw[(2 * kp) * H_ + h] + x1 * mw[(2 * kp + 1) * H_ + h];
    }
    #pragma unroll
    for (int o = 16; o; o >>= 1) dot += __shfl_xor_sync(0xffffffffu, dot, o);
    if (lane == 0)
        mix[(size_t)row * H_ + h] = 1.0f / (1.0f + expf(-(dot + mb[h])));
}

// ---------------- launch ----------------
extern "C" void kernel_launch(void* const* d_in, const int* in_sizes, int n_in,
                              void* d_out, int out_size) {
    const float* tokens       = (const float*)d_in[0];
    const float* attn_norm_w  = (const float*)d_in[1];
    const float* qkv_w        = (const float*)d_in[2];
    const float* out_w        = (const float*)d_in[3];
    const float* mix_w        = (const float*)d_in[4];
    const float* mix_b        = (const float*)d_in[5];
    const float* ff_norm_w    = (const float*)d_in[6];
    const float* ff_in_w      = (const float*)d_in[7];
    const float* ff_in_b      = (const float*)d_in[8];
    const float* ff_out_w     = (const float*)d_in[9];
    const float* ff_out_b     = (const float*)d_in[10];
    const float* final_norm_w = (const float*)d_in[11];

    float *t_, *qkv_, *fv_, *mix_;
    float2* rt_;
    uint32_t *xh_, *xl_, *oh_, *ol_, *yh_, *yl_;
    uint32_t *wqh_, *wql_, *woh_, *wol_, *wfh_, *wfl_, *wgh_, *wgl_;
    cudaGetSymbolAddress((void**)&t_,   g_t);
    cudaGetSymbolAddress((void**)&qkv_, g_qkv);
    cudaGetSymbolAddress((void**)&fv_,  g_fv);
    cudaGetSymbolAddress((void**)&mix_, g_mix);
    cudaGetSymbolAddress((void**)&rt_,  g_rt);
    cudaGetSymbolAddress((void**)&xh_,  g_xh);
    cudaGetSymbolAddress((void**)&xl_,  g_xl);
    cudaGetSymbolAddress((void**)&oh_,  g_oh);
    cudaGetSymbolAddress((void**)&ol_,  g_ol);
    cudaGetSymbolAddress((void**)&yh_,  g_yh);
    cudaGetSymbolAddress((void**)&yl_,  g_yl);
    cudaGetSymbolAddress((void**)&wqh_, g_wqh);
    cudaGetSymbolAddress((void**)&wql_, g_wql);
    cudaGetSymbolAddress((void**)&woh_, g_woh);
    cudaGetSymbolAddress((void**)&wol_, g_wol);
    cudaGetSymbolAddress((void**)&wfh_, g_wfh);
    cudaGetSymbolAddress((void**)&wfl_, g_wfl);
    cudaGetSymbolAddress((void**)&wgh_, g_wgh);
    cudaGetSymbolAddress((void**)&wgl_, g_wgl);

    static int smem_set = 0;
    if (!smem_set) {
        cudaFuncSetAttribute(gemm_bs, cudaFuncAttributeMaxDynamicSharedMemorySize,
                             2 * SM_BUF * 4);
        smem_set = 1;
    }
    const int GSM = 2 * SM_BUF * 4;

    copy_k<<<(M_ * D_ / 4 + 255) / 256, 256>>>((const float4*)tokens, (float4*)t_, M_ * D_ / 4);
    ropetab_k<<<(S_ * 32 + 255) / 256, 256>>>(rt_);

    dim3 cb(32, 8);
    wconv_k<<<dim3(KPX / 32, QKVN / 32, L_), cb>>>(
        qkv_w, wqh_, wql_, D_, QKVN, KPX, 0,
        (size_t)D_ * QKVN, (size_t)QKVN * KPX);
    wconv_k<<<dim3(KPX / 32, DI / 32, L_), cb>>>(
        out_w, woh_, wol_, DI, D_, KPX, 0,
        (size_t)DI * D_, (size_t)DI * KPX);
    wconv_k<<<dim3(KPX / 32, (FFN + 31) / 32, L_), cb>>>(
        ff_in_w, wfh_, wfl_, D_, FFN, KPX, 1,
        (size_t)D_ * FFN, (size_t)FFN * KPX);
    wconv_k<<<dim3((KPY + 31) / 32, DI / 32, L_), cb>>>(
        ff_out_w, wgh_, wgl_, DHID, D_, KPY, 0,
        (size_t)DHID * D_, (size_t)DI * KPY);

    for (int l = 0; l < L_; l++) {
        rmsnorm_split_k<<<M_, 128>>>(t_, attn_norm_w + l * D_, xh_, xl_);

        gemm_bs<<<dim3(QKVN / 128, M_ / 128), 256, GSM>>>(
            QKVN, KPX, KPX, KPX, QKVN,
            xh_, xl_, wqh_ + (size_t)l * QKVN * KPX, wql_ + (size_t)l * QKVN * KPX,
            qkv_, nullptr, nullptr, 0, nullptr, nullptr);

        const float* mixp = nullptr;
        if (l == 0) {
            savefv_k<<<(M_ * DI) / 256, 256>>>(qkv_, fv_);
        } else {
            mix_k<<<M_, 256>>>(xh_, xl_, mix_w + (size_t)l * D_ * H_, mix_b + l * H_, mix_);
            mixp = mix_;
        }

        attn_mma<<<dim3(S_ / 64, B_ * H_), 128>>>(qkv_, fv_, mixp, rt_, oh_, ol_);

        gemm_bs<<<dim3(D_ / 128, M_ / 128), 256, GSM>>>(
            D_, KPX, KPX, KPX, D_,
            oh_, ol_, woh_ + (size_t)l * DI * KPX, wol_ + (size_t)l * DI * KPX,
            t_, nullptr, t_, 0, nullptr, nullptr);

        rmsnorm_split_k<<<M_, 128>>>(t_, ff_norm_w + l * D_, xh_, xl_);

        gemm_bs<<<dim3((FFN + 127) / 128, M_ / 128), 256, GSM>>>(
            FFN, KPX, KPX, KPX, 0,
            xh_, xl_, wfh_ + (size_t)l * FFN * KPX, wfl_ + (size_t)l * FFN * KPX,
            nullptr, ff_in_b + (size_t)l * FFN, nullptr, 1, yh_, yl_);

        gemm_bs<<<dim3(D_ / 128, M_ / 128), 256, GSM>>>(
            D_, KPY, KPY, KPY, D_,
            yh_, yl_, wgh_ + (size_t)l * DI * KPY, wgl_ + (size_t)l * DI * KPY,
            t_, ff_out_b + (size_t)l * D_, t_, 0, nullptr, nullptr);
    }

    rmsnorm_k<<<M_, 128>>>(t_, final_norm_w, (float*)d_out);
}

// round 9
// speedup vs baseline: 3.4337x; 1.1494x over previous
#include <cuda_runtime.h>
#include <cuda_bf16.h>
#include <math.h>
#include <stdint.h>

#define B_   2
#define S_   2048
#define D_   512
#define L_   4
#define H_   8
#define DH   64
#define M_   (B_*S_)      // 4096 rows
#define DI   512          // H*DH
#define QKVN 1536
#define DHID 1365
#define FFN  2730         // 2*DHID
#define KPX  256          // k-pairs for K=512
#define KPY  688          // k-pairs (padded) for K=1365

// ---------------- scratch (no allocation allowed) ----------------
__device__ float    g_t   [M_ * D_];            // residual stream
__device__ float    g_qkv [M_ * QKVN];          // q|k|v packed per row (fp32)
__device__ float    g_fv  [M_ * DI];            // first layer's v
__device__ float    g_mix [M_ * H_];            // sigmoid gates
__device__ float2   g_rt  [S_ * 32];            // rope cos/sin table
__device__ uint32_t g_xh  [M_ * KPX], g_xl [M_ * KPX];   // rmsnorm out (split)
__device__ uint32_t g_oh  [M_ * KPX], g_ol [M_ * KPX];   // attn out (split)
__device__ uint32_t g_yh  [M_ * KPY], g_yl [M_ * KPY];   // gelu out (split; padding stays 0)
// converted weights (transposed [N][Kp], hi/lo planes)
__device__ uint32_t g_wqh [L_ * QKVN * KPX], g_wql [L_ * QKVN * KPX];
__device__ uint32_t g_woh [L_ * DI   * KPX], g_wol [L_ * DI   * KPX];
__device__ uint32_t g_wfh [L_ * FFN  * KPX], g_wfl [L_ * FFN  * KPX];
__device__ uint32_t g_wgh [L_ * DI   * KPY], g_wgl [L_ * DI   * KPY];

// ---------------- helpers ----------------
__device__ __forceinline__ uint32_t smem_u32(const void* p) {
    uint32_t a;
    asm("{ .reg .u64 t; cvta.to.shared.u64 t, %1; cvt.u32.u64 %0, t; }" : "=r"(a) : "l"(p));
    return a;
}
__device__ __forceinline__ uint32_t pack_bf(float x, float y) {
    uint32_t r;
    asm("cvt.rn.bf16x2.f32 %0, %1, %2;" : "=r"(r) : "f"(y), "f"(x));
    return r;
}
__device__ __forceinline__ void split2(float x, float y, uint32_t& hi, uint32_t& lo) {
    hi = pack_bf(x, y);
    float rx = x - __uint_as_float(hi << 16);
    float ry = y - __uint_as_float(hi & 0xFFFF0000u);
    lo = pack_bf(rx, ry);
}
__device__ __forceinline__ void mma16816(float* c, const uint32_t* a, const uint32_t* b) {
    asm volatile(
        "mma.sync.aligned.m16n8k16.row.col.f32.bf16.bf16.f32 "
        "{%0,%1,%2,%3}, {%4,%5,%6,%7}, {%8,%9}, {%0,%1,%2,%3};"
        : "+f"(c[0]), "+f"(c[1]), "+f"(c[2]), "+f"(c[3])
        : "r"(a[0]), "r"(a[1]), "r"(a[2]), "r"(a[3]), "r"(b[0]), "r"(b[1]));
}
__device__ __forceinline__ void ldsm4(uint32_t& r0, uint32_t& r1, uint32_t& r2, uint32_t& r3,
                                      uint32_t addr) {
    asm volatile("ldmatrix.sync.aligned.m8n8.x4.shared.b16 {%0,%1,%2,%3}, [%4];"
                 : "=r"(r0), "=r"(r1), "=r"(r2), "=r"(r3) : "r"(addr));
}
__device__ __forceinline__ void cp16(uint32_t dst, const void* src, int sz) {
    asm volatile("cp.async.ca.shared.global [%0], [%1], 16, %2;"
                 :: "r"(dst), "l"(src), "r"(sz) : "memory");
}

// ---------------- weight convert: W[K][N] fp32 -> Wh/Wl [N][Kps]; z = layer --------
__global__ void wconv_k(const float* __restrict__ W0, uint32_t* __restrict__ Wh0,
                        uint32_t* __restrict__ Wl0, int K, int N, int Kps, int ilv,
                        size_t wstride, size_t pstride) {
    const float* W = W0 + blockIdx.z * wstride;
    uint32_t* Wh = Wh0 + blockIdx.z * pstride;
    uint32_t* Wl = Wl0 + blockIdx.z * pstride;
    __shared__ float2 tile[32][33];
    int kp0 = blockIdx.x * 32, n0 = blockIdx.y * 32;
    int tx = threadIdx.x, ty = threadIdx.y;   // 32 x 8
    #pragma unroll
    for (int j = 0; j < 4; j++) {
        int kp = kp0 + ty + j * 8, k = 2 * kp, n = n0 + tx;
        int on = n;
        if (ilv) on = (n & 1) ? (n >> 1) + DHID : (n >> 1);
        float a = 0.0f, b = 0.0f;
        if (n < N) {
            if (k < K)     a = W[(size_t)k * N + on];
            if (k + 1 < K) b = W[(size_t)(k + 1) * N + on];
        }
        tile[ty + j * 8][tx] = make_float2(a, b);
    }
    __syncthreads();
    #pragma unroll
    for (int j = 0; j < 4; j++) {
        int n = n0 + ty + j * 8, kp = kp0 + tx;
        if (n < N && kp < Kps) {
            float2 v = tile[tx][ty + j * 8];
            uint32_t hi, lo;
            split2(v.x, v.y, hi, lo);
            Wh[(size_t)n * Kps + kp] = hi;
            Wl[(size_t)n * Kps + kp] = lo;
        }
    }
}

// ---------------- rope table ----------------
__global__ void ropetab_k(float2* __restrict__ rt) {
    int idx = blockIdx.x * 256 + threadIdx.x;
    if (idx >= S_ * 32) return;
    int pair = idx & 31, pos = idx >> 5;
    float inv = expf(-logf(10000.0f) * (float)pair * (1.0f / 32.0f));
    float s, c;
    sincosf((float)pos * inv, &s, &c);
    rt[idx] = make_float2(c, s);
}

// ================= split-bf16 HMMA GEMM, double-buffered cp.async + ldmatrix ======
#define SM_CH 2560          // uint32 per plane (128*20)
#define SM_BUF 10240        // uint32 per buffer (4 planes)
__global__ void __launch_bounds__(256, 2) gemm_bs(
    int N, int Kp, int ldap, int ldbp, int ldc,
    const uint32_t* __restrict__ Agh, const uint32_t* __restrict__ Agl,
    const uint32_t* __restrict__ Bgh, const uint32_t* __restrict__ Bgl,
    float* __restrict__ C, const float* __restrict__ bias,
    const float* __restrict__ addsrc, int mode,
    uint32_t* __restrict__ Yh, uint32_t* __restrict__ Yl)
{
    extern __shared__ uint32_t sm[];
    int tid = threadIdx.x;
    int wid = tid >> 5, lane = tid & 31;
    int m0 = blockIdx.y * 128, n0 = blockIdx.x * 128;
    int wm = (wid >> 2) * 64, wn = (wid & 3) * 32;
    int g = lane >> 2, t = lane & 3;

    float acc[4][4][4];
    #pragma unroll
    for (int i = 0; i < 4; i++)
        #pragma unroll
        for (int j = 0; j < 4; j++)
            #pragma unroll
            for (int q = 0; q < 4; q++) acc[i][j][q] = 0.0f;

    uint32_t smb = smem_u32(sm);
    int nch = Kp >> 4;

    auto load_chunk = [&](int c, int buf) {
        int kp0 = c << 4;
        uint32_t base = smb + (uint32_t)buf * (SM_BUF * 4);
        #pragma unroll
        for (int i = 0; i < 2; i++) {
            int e = i * 256 + tid;
            int row = e >> 2, seg = (e & 3) * 4;
            uint32_t soff = (uint32_t)(row * 20 + seg) * 4;
            size_t aoff = (size_t)(m0 + row) * ldap + kp0 + seg;
            cp16(base + soff, Agh + aoff, 16);
            cp16(base + SM_CH * 4 + soff, Agl + aoff, 16);
            int nn = n0 + row;
            int sz = (nn < N) ? 16 : 0;
            size_t boff = (size_t)(nn < N ? nn : 0) * ldbp + kp0 + seg;
            cp16(base + SM_CH * 8 + soff, Bgh + boff, sz);
            cp16(base + SM_CH * 12 + soff, Bgl + boff, sz);
        }
        asm volatile("cp.async.commit_group;" ::: "memory");
    };

    // ldmatrix lane-role precompute
    int a_row = lane & 15, a_colo = (lane >> 4) * 4;      // A: 16 rows x 2 col-halves
    int b_l8 = lane & 7, b_seg = lane >> 3;               // B: 8 rows x 4 (nt-half, col-half)

    load_chunk(0, 0);
    for (int c = 0; c < nch; c++) {
        if (c + 1 < nch) {
            load_chunk(c + 1, (c + 1) & 1);
            asm volatile("cp.async.wait_group 1;" ::: "memory");
        } else {
            asm volatile("cp.async.wait_group 0;" ::: "memory");
        }
        __syncthreads();

        uint32_t abh = smb + (uint32_t)(c & 1) * (SM_BUF * 4);
        uint32_t abl = abh + SM_CH * 4;
        uint32_t bbh = abh + SM_CH * 8;
        uint32_t bbl = abh + SM_CH * 12;

        #pragma unroll
        for (int s = 0; s < 2; s++) {
            uint32_t afh[4][4], afl[4][4];
            #pragma unroll
            for (int mt = 0; mt < 4; mt++) {
                uint32_t off = (uint32_t)(((wm + mt * 16 + a_row) * 20 + s * 8 + a_colo) * 4);
                ldsm4(afh[mt][0], afh[mt][1], afh[mt][2], afh[mt][3], abh + off);
                ldsm4(afl[mt][0], afl[mt][1], afl[mt][2], afl[mt][3], abl + off);
            }
            uint32_t bfh[4][2], bfl[4][2];
            #pragma unroll
            for (int np = 0; np < 2; np++) {
                int brow = wn + (np * 2 + (b_seg >> 1)) * 8 + b_l8;
                int bcol = s * 8 + (b_seg & 1) * 4;
                uint32_t off = (uint32_t)((brow * 20 + bcol) * 4);
                ldsm4(bfh[np*2][0], bfh[np*2][1], bfh[np*2+1][0], bfh[np*2+1][1], bbh + off);
                ldsm4(bfl[np*2][0], bfl[np*2][1], bfl[np*2+1][0], bfl[np*2+1][1], bbl + off);
            }
            #pragma unroll
            for (int mt = 0; mt < 4; mt++)
                #pragma unroll
                for (int nt = 0; nt < 4; nt++) {
                    mma16816(acc[mt][nt], afh[mt], bfh[nt]);
                    mma16816(acc[mt][nt], afh[mt], bfl[nt]);
                    mma16816(acc[mt][nt], afl[mt], bfh[nt]);
                }
        }
        __syncthreads();
    }

    if (mode == 0) {
        #pragma unroll
        for (int mt = 0; mt < 4; mt++) {
            int r0 = m0 + wm + mt * 16 + g;
            #pragma unroll
            for (int nt = 0; nt < 4; nt++) {
                int col = n0 + wn + nt * 8 + 2 * t;
                #pragma unroll
                for (int half = 0; half < 2; half++) {
                    int row = r0 + half * 8;
                    float v0 = acc[mt][nt][half * 2 + 0];
                    float v1 = acc[mt][nt][half * 2 + 1];
                    if (col < N) {
                        if (bias)   v0 += bias[col];
                        if (addsrc) v0 += addsrc[(size_t)row * ldc + col];
                        C[(size_t)row * ldc + col] = v0;
                    }
                    if (col + 1 < N) {
                        if (bias)   v1 += bias[col + 1];
                        if (addsrc) v1 += addsrc[(size_t)row * ldc + col + 1];
                        C[(size_t)row * ldc + col + 1] = v1;
                    }
                }
            }
        }
    } else {
        #pragma unroll
        for (int mt = 0; mt < 4; mt++) {
            int r0 = m0 + wm + mt * 16 + g;
            #pragma unroll
            for (int nt = 0; nt < 4; nt++) {
                int col = n0 + wn + nt * 8 + 2 * t;
                int j = col >> 1;
                bool valid = col < N;
                #pragma unroll
                for (int half = 0; half < 2; half++) {
                    int row = r0 + half * 8;
                    float y = 0.0f;
                    if (valid) {
                        float a  = acc[mt][nt][half * 2 + 0] + bias[j];
                        float gg = acc[mt][nt][half * 2 + 1] + bias[j + DHID];
                        y = a * 0.5f * gg * (1.0f + erff(gg * 0.70710678118654752f));
                    }
                    float y1 = __shfl_down_sync(0xffffffffu, y, 1);
                    if ((t & 1) == 0) {
                        int kp = j >> 1;
                        if (kp < KPY) {
                            uint32_t hi, lo;
                            split2(y, y1, hi, lo);
                            Yh[(size_t)row * KPY + kp] = hi;
                            Yl[(size_t)row * KPY + kp] = lo;
                        }
                    }
                }
            }
        }
    }
}

// ================= split-bf16 HMMA flash attention (rope + vmix, ldmatrix) ========
__global__ void __launch_bounds__(128) attn_mma(
    const float* __restrict__ qkv, const float* __restrict__ fv,
    const float* __restrict__ mix, const float2* __restrict__ rt,
    uint32_t* __restrict__ Oh, uint32_t* __restrict__ Ol)
{
    __shared__ uint32_t Kh[64][36], Kl[64][36];
    __shared__ uint32_t Vh[64][36], Vl[64][36];

    int Qb = blockIdx.x;
    int h  = blockIdx.y & 7, b = blockIdx.y >> 3;
    int tid = threadIdx.x, w = tid >> 5, lane = tid & 31;
    int g = lane >> 2, t = lane & 3;
    int row0 = b * S_ + Qb * 64;

    uint32_t kbh = smem_u32(Kh), kbl = smem_u32(Kl);
    uint32_t vbh = smem_u32(Vh), vbl = smem_u32(Vl);
    int l8 = lane & 7, seg = lane >> 3;

    uint32_t qh[4][4], ql[4][4];
    {
        int r0 = w * 16 + g, r1 = r0 + 8;
        #pragma unroll
        for (int kt = 0; kt < 4; kt++) {
            #pragma unroll
            for (int q = 0; q < 4; q++) {
                int rr = (q & 1) ? r1 : r0;
                int kk = kt * 16 + 2 * t + ((q & 2) ? 8 : 0);
                float2 v = *(const float2*)(qkv + (size_t)(row0 + rr) * QKVN + h * 64 + kk);
                float2 cs = rt[(Qb * 64 + rr) * 32 + (kk >> 1)];
                float q1 = v.x * cs.x - v.y * cs.y;
                float q2 = v.x * cs.y + v.y * cs.x;
                split2(q1 * 0.125f, q2 * 0.125f, qh[kt][q], ql[kt][q]);
            }
        }
    }

    float Oa[8][4];
    #pragma unroll
    for (int i = 0; i < 8; i++)
        #pragma unroll
        for (int q = 0; q < 4; q++) Oa[i][q] = 0.0f;
    float m_[2] = {-INFINITY, -INFINITY};
    float l_[2] = {0.0f, 0.0f};

    int kq = tid >> 2, qq = tid & 3;

    for (int J = 0; J <= Qb; J++) {
        int kr = b * S_ + J * 64;
        __syncthreads();
        #pragma unroll
        for (int half = 0; half < 2; half++) {
            int ky = kq + half * 32;
            const float* kp_ = qkv + (size_t)(kr + ky) * QKVN + 512 + h * 64;
            int posk = J * 64 + ky;
            #pragma unroll
            for (int i = 0; i < 8; i++) {
                int d = 2 * qq + 8 * i;
                float2 kv = *(const float2*)(kp_ + d);
                float2 cs = rt[posk * 32 + (d >> 1)];
                float k1 = kv.x * cs.x - kv.y * cs.y;
                float k2 = kv.x * cs.y + kv.y * cs.x;
                uint32_t hi, lo;
                split2(k1, k2, hi, lo);
                Kh[ky][d >> 1] = hi;
                Kl[ky][d >> 1] = lo;
            }
        }
        {
            int vrow = kr + 2 * kq;
            const float* v0p = qkv + (size_t)vrow * QKVN + 1024 + h * 64;
            const float* v1p = v0p + QKVN;
            float mix0 = 0.0f, mix1 = 0.0f;
            if (mix) {
                mix0 = mix[(size_t)vrow * H_ + h];
                mix1 = mix[(size_t)(vrow + 1) * H_ + h];
            }
            #pragma unroll
            for (int i = 0; i < 8; i++) {
                int d = 2 * qq + 8 * i;
                float2 a = *(const float2*)(v0p + d);
                float2 c2 = *(const float2*)(v1p + d);
                if (mix) {
                    float2 fa = *(const float2*)(fv + (size_t)vrow * DI + h * 64 + d);
                    float2 fc = *(const float2*)(fv + (size_t)(vrow + 1) * DI + h * 64 + d);
                    a.x  += mix0 * (fa.x - a.x);   a.y  += mix0 * (fa.y - a.y);
                    c2.x += mix1 * (fc.x - c2.x);  c2.y += mix1 * (fc.y - c2.y);
                }
                uint32_t hi, lo;
                split2(a.x, c2.x, hi, lo);
                Vh[d][kq] = hi; Vl[d][kq] = lo;
                split2(a.y, c2.y, hi, lo);
                Vh[d + 1][kq] = hi; Vl[d + 1][kq] = lo;
            }
        }
        __syncthreads();

        int diag = (J == Qb) && (w < 2);
        int ntS  = diag ? 4 : 8;
        int ktPV = diag ? 2 : 4;

        float Sa[8][4];
        for (int nt = 0; nt < ntS; nt++) {
            Sa[nt][0] = Sa[nt][1] = Sa[nt][2] = Sa[nt][3] = 0.0f;
            uint32_t kfh[4][2], kfl[4][2];
            uint32_t off0 = (uint32_t)(((8 * nt + l8) * 36 + seg * 4) * 4);
            ldsm4(kfh[0][0], kfh[0][1], kfh[1][0], kfh[1][1], kbh + off0);
            ldsm4(kfh[2][0], kfh[2][1], kfh[3][0], kfh[3][1], kbh + off0 + 64);
            ldsm4(kfl[0][0], kfl[0][1], kfl[1][0], kfl[1][1], kbl + off0);
            ldsm4(kfl[2][0], kfl[2][1], kfl[3][0], kfl[3][1], kbl + off0 + 64);
            #pragma unroll
            for (int kt = 0; kt < 4; kt++) {
                mma16816(Sa[nt], qh[kt], kfh[kt]);
                mma16816(Sa[nt], qh[kt], kfl[kt]);
                mma16816(Sa[nt], ql[kt], kfh[kt]);
            }
        }

        float alpha[2];
        #pragma unroll
        for (int half = 0; half < 2; half++) {
            float mx = -INFINITY;
            for (int nt = 0; nt < ntS; nt++) {
                mx = fmaxf(mx, Sa[nt][half * 2]);
                mx = fmaxf(mx, Sa[nt][half * 2 + 1]);
            }
            mx = fmaxf(mx, __shfl_xor_sync(0xffffffffu, mx, 1));
            mx = fmaxf(mx, __shfl_xor_sync(0xffffffffu, mx, 2));
            float mn = fmaxf(m_[half], mx);
            alpha[half] = __expf(m_[half] - mn);
            m_[half] = mn;
            float ps = 0.0f;
            for (int nt = 0; nt < ntS; nt++) {
                float p0 = __expf(Sa[nt][half * 2]     - mn);
                float p1 = __expf(Sa[nt][half * 2 + 1] - mn);
                Sa[nt][half * 2]     = p0;
                Sa[nt][half * 2 + 1] = p1;
                ps += p0 + p1;
            }
            l_[half] = l_[half] * alpha[half] + ps;
        }
        #pragma unroll
        for (int nt = 0; nt < 8; nt++) {
            Oa[nt][0] *= alpha[0]; Oa[nt][1] *= alpha[0];
            Oa[nt][2] *= alpha[1]; Oa[nt][3] *= alpha[1];
        }

        uint32_t ph[4][4], pl[4][4];
        for (int kt = 0; kt < ktPV; kt++) {
            split2(Sa[2 * kt][0],     Sa[2 * kt][1],     ph[kt][0], pl[kt][0]);
            split2(Sa[2 * kt][2],     Sa[2 * kt][3],     ph[kt][1], pl[kt][1]);
            split2(Sa[2 * kt + 1][0], Sa[2 * kt + 1][1], ph[kt][2], pl[kt][2]);
            split2(Sa[2 * kt + 1][2], Sa[2 * kt + 1][3], ph[kt][3], pl[kt][3]);
        }

        #pragma unroll
        for (int nt = 0; nt < 8; nt++) {
            uint32_t vfh[4][2], vfl[4][2];
            uint32_t off0 = (uint32_t)(((8 * nt + l8) * 36 + seg * 4) * 4);
            ldsm4(vfh[0][0], vfh[0][1], vfh[1][0], vfh[1][1], vbh + off0);
            ldsm4(vfl[0][0], vfl[0][1], vfl[1][0], vfl[1][1], vbl + off0);
            if (ktPV > 2) {
                ldsm4(vfh[2][0], vfh[2][1], vfh[3][0], vfh[3][1], vbh + off0 + 64);
                ldsm4(vfl[2][0], vfl[2][1], vfl[3][0], vfl[3][1], vbl + off0 + 64);
            }
            for (int kt = 0; kt < ktPV; kt++) {
                mma16816(Oa[nt], ph[kt], vfh[kt]);
                mma16816(Oa[nt], ph[kt], vfl[kt]);
                mma16816(Oa[nt], pl[kt], vfh[kt]);
            }
        }
    }

    float linv[2];
    #pragma unroll
    for (int half = 0; half < 2; half++) {
        float l = l_[half];
        l += __shfl_xor_sync(0xffffffffu, l, 1);
        l += __shfl_xor_sync(0xffffffffu, l, 2);
        linv[half] = 1.0f / l;
    }
    int r0 = w * 16 + g, r1 = r0 + 8;
    #pragma unroll
    for (int nt = 0; nt < 8; nt++) {
        int kp = h * 32 + 4 * nt + t;
        uint32_t hi, lo;
        split2(Oa[nt][0] * linv[0], Oa[nt][1] * linv[0], hi, lo);
        Oh[(size_t)(row0 + r0) * KPX + kp] = hi;
        Ol[(size_t)(row0 + r0) * KPX + kp] = lo;
        split2(Oa[nt][2] * linv[1], Oa[nt][3] * linv[1], hi, lo);
        Oh[(size_t)(row0 + r1) * KPX + kp] = hi;
        Ol[(size_t)(row0 + r1) * KPX + kp] = lo;
    }
}

// ---------------- elementwise copy ----------------
__global__ void copy_k(const float4* __restrict__ in, float4* __restrict__ out, int n4) {
    int i = blockIdx.x * blockDim.x + threadIdx.x;
    if (i < n4) out[i] = in[i];
}

// ---------------- rmsnorm -> split output ----------------
__global__ void rmsnorm_split_k(const float* __restrict__ in, const float* __restrict__ w,
                                uint32_t* __restrict__ Xh, uint32_t* __restrict__ Xl) {
    int row = blockIdx.x;
    const float4* ip = (const float4*)(in + (size_t)row * D_);
    float4 v = ip[threadIdx.x];
    float ss = v.x*v.x + v.y*v.y + v.z*v.z + v.w*v.w;
    #pragma unroll
    for (int o = 16; o; o >>= 1) ss += __shfl_xor_sync(0xffffffffu, ss, o);
    __shared__ float sred[4];
    if ((threadIdx.x & 31) == 0) sred[threadIdx.x >> 5] = ss;
    __syncthreads();
    float tot = sred[0] + sred[1] + sred[2] + sred[3];
    float sc = rsqrtf(tot * (1.0f / 512.0f) + 1.1920929e-7f);
    const float4* wp = (const float4*)w;
    float4 wv = wp[threadIdx.x];
    float o0 = v.x * sc * wv.x, o1 = v.y * sc * wv.y;
    float o2 = v.z * sc * wv.z, o3 = v.w * sc * wv.w;
    uint32_t h0, l0, h1, l1;
    split2(o0, o1, h0, l0);
    split2(o2, o3, h1, l1);
    size_t base = (size_t)row * KPX + threadIdx.x * 2;
    Xh[base] = h0; Xh[base + 1] = h1;
    Xl[base] = l0; Xl[base + 1] = l1;
}

// ---------------- rmsnorm fp32 out (final) ----------------
__global__ void rmsnorm_k(const float* __restrict__ in, const float* __restrict__ w,
                          float* __restrict__ out) {
    int row = blockIdx.x;
    const float4* ip = (const float4*)(in + (size_t)row * D_);
    float4 v = ip[threadIdx.x];
    float ss = v.x*v.x + v.y*v.y + v.z*v.z + v.w*v.w;
    #pragma unroll
    for (int o = 16; o; o >>= 1) ss += __shfl_xor_sync(0xffffffffu, ss, o);
    __shared__ float sred[4];
    if ((threadIdx.x & 31) == 0) sred[threadIdx.x >> 5] = ss;
    __syncthreads();
    float tot = sred[0] + sred[1] + sred[2] + sred[3];
    float sc = rsqrtf(tot * (1.0f / 512.0f) + 1.1920929e-7f);
    const float4* wp = (const float4*)w;
    float4 wv = wp[threadIdx.x];
    float4 o4;
    o4.x = v.x * sc * wv.x; o4.y = v.y * sc * wv.y;
    o4.z = v.z * sc * wv.z; o4.w = v.w * sc * wv.w;
    ((float4*)(out + (size_t)row * D_))[threadIdx.x] = o4;
}

// ---------------- save first-layer v ----------------
__global__ void savefv_k(const float* __restrict__ qkv, float* __restrict__ fv) {
    int idx = blockIdx.x * blockDim.x + threadIdx.x;
    int row = idx >> 9, c = idx & 511;
    fv[idx] = qkv[(size_t)row * QKVN + 1024 + c];
}

// ---------------- mix gate ----------------
__global__ void mix_k(const uint32_t* __restrict__ Xh, const uint32_t* __restrict__ Xl,
                      const float* __restrict__ mw, const float* __restrict__ mb,
                      float* __restrict__ mix) {
    int row = blockIdx.x;
    int lane = threadIdx.x & 31;
    int h = threadIdx.x >> 5;
    float dot = 0.0f;
    #pragma unroll
    for (int kp = lane; kp < KPX; kp += 32) {
        uint32_t hv = Xh[(size_t)row * KPX + kp], lv = Xl[(size_t)row * KPX + kp];
        float x0 = __uint_as_float(hv << 16) + __uint_as_float(lv << 16);
        float x1 = __uint_as_float(hv & 0xFFFF0000u) + __uint_as_float(lv & 0xFFFF0000u);
        dot += x0 * mw[(2 * kp) * H_ + h] + x1 * mw[(2 * kp + 1) * H_ + h];
    }
    #pragma unroll
    for (int o = 16; o; o >>= 1) dot += __shfl_xor_sync(0xffffffffu, dot, o);
    if (lane == 0)
        mix[(size_t)row * H_ + h] = 1.0f / (1.0f + expf(-(dot + mb[h])));
}

// ---------------- launch ----------------
extern "C" void kernel_launch(void* const* d_in, const int* in_sizes, int n_in,
                              void* d_out, int out_size) {
    const float* tokens       = (const float*)d_in[0];
    const float* attn_norm_w  = (const float*)d_in[1];
    const float* qkv_w        = (const float*)d_in[2];
    const float* out_w        = (const float*)d_in[3];
    const float* mix_w        = (const float*)d_in[4];
    const float* mix_b        = (const float*)d_in[5];
    const float* ff_norm_w    = (const float*)d_in[6];
    const float* ff_in_w      = (const float*)d_in[7];
    const float* ff_in_b      = (const float*)d_in[8];
    const float* ff_out_w     = (const float*)d_in[9];
    const float* ff_out_b     = (const float*)d_in[10];
    const float* final_norm_w = (const float*)d_in[11];

    float *t_, *qkv_, *fv_, *mix_;
    float2* rt_;
    uint32_t *xh_, *xl_, *oh_, *ol_, *yh_, *yl_;
    uint32_t *wqh_, *wql_, *woh_, *wol_, *wfh_, *wfl_, *wgh_, *wgl_;
    cudaGetSymbolAddress((void**)&t_,   g_t);
    cudaGetSymbolAddress((void**)&qkv_, g_qkv);
    cudaGetSymbolAddress((void**)&fv_,  g_fv);
    cudaGetSymbolAddress((void**)&mix_, g_mix);
    cudaGetSymbolAddress((void**)&rt_,  g_rt);
    cudaGetSymbolAddress((void**)&xh_,  g_xh);
    cudaGetSymbolAddress((void**)&xl_,  g_xl);
    cudaGetSymbolAddress((void**)&oh_,  g_oh);
    cudaGetSymbolAddress((void**)&ol_,  g_ol);
    cudaGetSymbolAddress((void**)&yh_,  g_yh);
    cudaGetSymbolAddress((void**)&yl_,  g_yl);
    cudaGetSymbolAddress((void**)&wqh_, g_wqh);
    cudaGetSymbolAddress((void**)&wql_, g_wql);
    cudaGetSymbolAddress((void**)&woh_, g_woh);
    cudaGetSymbolAddress((void**)&wol_, g_wol);
    cudaGetSymbolAddress((void**)&wfh_, g_wfh);
    cudaGetSymbolAddress((void**)&wfl_, g_wfl);
    cudaGetSymbolAddress((void**)&wgh_, g_wgh);
    cudaGetSymbolAddress((void**)&wgl_, g_wgl);

    static int smem_set = 0;
    if (!smem_set) {
        cudaFuncSetAttribute(gemm_bs, cudaFuncAttributeMaxDynamicSharedMemorySize,
                             2 * SM_BUF * 4);
        smem_set = 1;
    }
    const int GSM = 2 * SM_BUF * 4;

    copy_k<<<(M_ * D_ / 4 + 255) / 256, 256>>>((const float4*)tokens, (float4*)t_, M_ * D_ / 4);
    ropetab_k<<<(S_ * 32 + 255) / 256, 256>>>(rt_);

    dim3 cb(32, 8);
    wconv_k<<<dim3(KPX / 32, QKVN / 32, L_), cb>>>(
        qkv_w, wqh_, wql_, D_, QKVN, KPX, 0,
        (size_t)D_ * QKVN, (size_t)QKVN * KPX);
    wconv_k<<<dim3(KPX / 32, DI / 32, L_), cb>>>(
        out_w, woh_, wol_, DI, D_, KPX, 0,
        (size_t)DI * D_, (size_t)DI * KPX);
    wconv_k<<<dim3(KPX / 32, (FFN + 31) / 32, L_), cb>>>(
        ff_in_w, wfh_, wfl_, D_, FFN, KPX, 1,
        (size_t)D_ * FFN, (size_t)FFN * KPX);
    wconv_k<<<dim3((KPY + 31) / 32, DI / 32, L_), cb>>>(
        ff_out_w, wgh_, wgl_, DHID, D_, KPY, 0,
        (size_t)DHID * D_, (size_t)DI * KPY);

    for (int l = 0; l < L_; l++) {
        rmsnorm_split_k<<<M_, 128>>>(t_, attn_norm_w + l * D_, xh_, xl_);

        gemm_bs<<<dim3(QKVN / 128, M_ / 128), 256, GSM>>>(
            QKVN, KPX, KPX, KPX, QKVN,
            xh_, xl_, wqh_ + (size_t)l * QKVN * KPX, wql_ + (size_t)l * QKVN * KPX,
            qkv_, nullptr, nullptr, 0, nullptr, nullptr);

        const float* mixp = nullptr;
        if (l == 0) {
            savefv_k<<<(M_ * DI) / 256, 256>>>(qkv_, fv_);
        } else {
            mix_k<<<M_, 256>>>(xh_, xl_, mix_w + (size_t)l * D_ * H_, mix_b + l * H_, mix_);
            mixp = mix_;
        }

        attn_mma<<<dim3(S_ / 64, B_ * H_), 128>>>(qkv_, fv_, mixp, rt_, oh_, ol_);

        gemm_bs<<<dim3(D_ / 128, M_ / 128), 256, GSM>>>(
            D_, KPX, KPX, KPX, D_,
            oh_, ol_, woh_ + (size_t)l * DI * KPX, wol_ + (size_t)l * DI * KPX,
            t_, nullptr, t_, 0, nullptr, nullptr);

        rmsnorm_split_k<<<M_, 128>>>(t_, ff_norm_w + l * D_, xh_, xl_);

        gemm_bs<<<dim3((FFN + 127) / 128, M_ / 128), 256, GSM>>>(
            FFN, KPX, KPX, KPX, 0,
            xh_, xl_, wfh_ + (size_t)l * FFN * KPX, wfl_ + (size_t)l * FFN * KPX,
            nullptr, ff_in_b + (size_t)l * FFN, nullptr, 1, yh_, yl_);

        gemm_bs<<<dim3(D_ / 128, M_ / 128), 256, GSM>>>(
            D_, KPY, KPY, KPY, D_,
            yh_, yl_, wgh_ + (size_t)l * DI * KPY, wgl_ + (size_t)l * DI * KPY,
            t_, ff_out_b + (size_t)l * D_, t_, 0, nullptr, nullptr);
    }

    rmsnorm_k<<<M_, 128>>>(t_, final_norm_w, (float*)d_out);
}

// round 10
// speedup vs baseline: 4.0492x; 1.1793x over previous
#include <cuda_runtime.h>
#include <cuda_bf16.h>
#include <math.h>
#include <stdint.h>

#define B_   2
#define S_   2048
#define D_   512
#define L_   4
#define H_   8
#define DH   64
#define M_   (B_*S_)      // 4096 rows
#define DI   512          // H*DH
#define QKVN 1536
#define DHID 1365
#define FFN  2730         // 2*DHID
#define KPX  256          // k-pairs for K=512
#define KPY  688          // k-pairs (padded) for K=1365

// ---------------- scratch (no allocation allowed) ----------------
__device__ float    g_t   [M_ * D_];            // residual stream
__device__ float    g_fv  [M_ * DI];            // first layer's v (fp32)
__device__ float    g_mix [M_ * H_];            // sigmoid gates
__device__ float2   g_rt  [S_ * 32];            // rope cos/sin table
__device__ uint32_t g_xh  [M_ * KPX], g_xl [M_ * KPX];   // rmsnorm out (split)
__device__ uint32_t g_oh  [M_ * KPX], g_ol [M_ * KPX];   // attn out (split)
__device__ uint32_t g_yh  [M_ * KPY], g_yl [M_ * KPY];   // gelu out (split; padding stays 0)
__device__ uint32_t g_qh2 [M_ * KPX], g_ql2 [M_ * KPX];  // roped+scaled q (split)
__device__ uint32_t g_kh2 [M_ * KPX], g_kl2 [M_ * KPX];  // roped k (split)
__device__ uint32_t g_vh2 [M_ * KPX], g_vl2 [M_ * KPX];  // mixed v (split)
// converted weights (transposed [N][Kp], hi/lo planes)
__device__ uint32_t g_wqh [L_ * QKVN * KPX], g_wql [L_ * QKVN * KPX];
__device__ uint32_t g_woh [L_ * DI   * KPX], g_wol [L_ * DI   * KPX];
__device__ uint32_t g_wfh [L_ * FFN  * KPX], g_wfl [L_ * FFN  * KPX];
__device__ uint32_t g_wgh [L_ * DI   * KPY], g_wgl [L_ * DI   * KPY];

// ---------------- helpers ----------------
__device__ __forceinline__ uint32_t smem_u32(const void* p) {
    uint32_t a;
    asm("{ .reg .u64 t; cvta.to.shared.u64 t, %1; cvt.u32.u64 %0, t; }" : "=r"(a) : "l"(p));
    return a;
}
__device__ __forceinline__ uint32_t pack_bf(float x, float y) {
    uint32_t r;
    asm("cvt.rn.bf16x2.f32 %0, %1, %2;" : "=r"(r) : "f"(y), "f"(x));
    return r;
}
__device__ __forceinline__ void split2(float x, float y, uint32_t& hi, uint32_t& lo) {
    hi = pack_bf(x, y);
    float rx = x - __uint_as_float(hi << 16);
    float ry = y - __uint_as_float(hi & 0xFFFF0000u);
    lo = pack_bf(rx, ry);
}
__device__ __forceinline__ void mma16816(float* c, const uint32_t* a, const uint32_t* b) {
    asm volatile(
        "mma.sync.aligned.m16n8k16.row.col.f32.bf16.bf16.f32 "
        "{%0,%1,%2,%3}, {%4,%5,%6,%7}, {%8,%9}, {%0,%1,%2,%3};"
        : "+f"(c[0]), "+f"(c[1]), "+f"(c[2]), "+f"(c[3])
        : "r"(a[0]), "r"(a[1]), "r"(a[2]), "r"(a[3]), "r"(b[0]), "r"(b[1]));
}
__device__ __forceinline__ void ldsm4(uint32_t& r0, uint32_t& r1, uint32_t& r2, uint32_t& r3,
                                      uint32_t addr) {
    asm volatile("ldmatrix.sync.aligned.m8n8.x4.shared.b16 {%0,%1,%2,%3}, [%4];"
                 : "=r"(r0), "=r"(r1), "=r"(r2), "=r"(r3) : "r"(addr));
}
__device__ __forceinline__ void ldsm4t(uint32_t& r0, uint32_t& r1, uint32_t& r2, uint32_t& r3,
                                       uint32_t addr) {
    asm volatile("ldmatrix.sync.aligned.m8n8.x4.trans.shared.b16 {%0,%1,%2,%3}, [%4];"
                 : "=r"(r0), "=r"(r1), "=r"(r2), "=r"(r3) : "r"(addr));
}
__device__ __forceinline__ void cp16(uint32_t dst, const void* src, int sz) {
    asm volatile("cp.async.ca.shared.global [%0], [%1], 16, %2;"
                 :: "r"(dst), "l"(src), "r"(sz) : "memory");
}

// ---------------- weight convert: W[K][N] fp32 -> Wh/Wl [N][Kps]; z = layer --------
__global__ void wconv_k(const float* __restrict__ W0, uint32_t* __restrict__ Wh0,
                        uint32_t* __restrict__ Wl0, int K, int N, int Kps, int ilv,
                        size_t wstride, size_t pstride) {
    const float* W = W0 + blockIdx.z * wstride;
    uint32_t* Wh = Wh0 + blockIdx.z * pstride;
    uint32_t* Wl = Wl0 + blockIdx.z * pstride;
    __shared__ float2 tile[32][33];
    int kp0 = blockIdx.x * 32, n0 = blockIdx.y * 32;
    int tx = threadIdx.x, ty = threadIdx.y;   // 32 x 8
    #pragma unroll
    for (int j = 0; j < 4; j++) {
        int kp = kp0 + ty + j * 8, k = 2 * kp, n = n0 + tx;
        int on = n;
        if (ilv) on = (n & 1) ? (n >> 1) + DHID : (n >> 1);
        float a = 0.0f, b = 0.0f;
        if (n < N) {
            if (k < K)     a = W[(size_t)k * N + on];
            if (k + 1 < K) b = W[(size_t)(k + 1) * N + on];
        }
        tile[ty + j * 8][tx] = make_float2(a, b);
    }
    __syncthreads();
    #pragma unroll
    for (int j = 0; j < 4; j++) {
        int n = n0 + ty + j * 8, kp = kp0 + tx;
        if (n < N && kp < Kps) {
            float2 v = tile[tx][ty + j * 8];
            uint32_t hi, lo;
            split2(v.x, v.y, hi, lo);
            Wh[(size_t)n * Kps + kp] = hi;
            Wl[(size_t)n * Kps + kp] = lo;
        }
    }
}

// ---------------- rope table ----------------
__global__ void ropetab_k(float2* __restrict__ rt) {
    int idx = blockIdx.x * 256 + threadIdx.x;
    if (idx >= S_ * 32) return;
    int pair = idx & 31, pos = idx >> 5;
    float inv = expf(-logf(10000.0f) * (float)pair * (1.0f / 32.0f));
    float s, c;
    sincosf((float)pos * inv, &s, &c);
    rt[idx] = make_float2(c, s);
}

// ================= split-bf16 HMMA GEMM, double-buffered cp.async + ldmatrix ======
// mode 0: fp32 C (+bias)(+addsrc). mode 1: gated-GELU -> Yh/Yl.
// mode 2: qkv epilogue: rope+scale+split q/k, mix+split v, write planes.
#define SM_CH 2560
#define SM_BUF 10240
__global__ void __launch_bounds__(256, 2) gemm_bs(
    int N, int Kp, int ldap, int ldbp, int ldc,
    const uint32_t* __restrict__ Agh, const uint32_t* __restrict__ Agl,
    const uint32_t* __restrict__ Bgh, const uint32_t* __restrict__ Bgl,
    float* __restrict__ C, const float* __restrict__ bias,
    const float* __restrict__ addsrc, int mode,
    uint32_t* __restrict__ Yh, uint32_t* __restrict__ Yl,
    const float2* __restrict__ rt, const float* __restrict__ mixp,
    float* __restrict__ fvp,
    uint32_t* __restrict__ Qh, uint32_t* __restrict__ Ql,
    uint32_t* __restrict__ Kh2, uint32_t* __restrict__ Kl2,
    uint32_t* __restrict__ Vh2, uint32_t* __restrict__ Vl2, int layer0)
{
    extern __shared__ uint32_t sm[];
    int tid = threadIdx.x;
    int wid = tid >> 5, lane = tid & 31;
    int m0 = blockIdx.y * 128, n0 = blockIdx.x * 128;
    int wm = (wid >> 2) * 64, wn = (wid & 3) * 32;
    int g = lane >> 2, t = lane & 3;

    float acc[4][4][4];
    #pragma unroll
    for (int i = 0; i < 4; i++)
        #pragma unroll
        for (int j = 0; j < 4; j++)
            #pragma unroll
            for (int q = 0; q < 4; q++) acc[i][j][q] = 0.0f;

    uint32_t smb = smem_u32(sm);
    int nch = Kp >> 4;

    auto load_chunk = [&](int c, int buf) {
        int kp0 = c << 4;
        uint32_t base = smb + (uint32_t)buf * (SM_BUF * 4);
        #pragma unroll
        for (int i = 0; i < 2; i++) {
            int e = i * 256 + tid;
            int row = e >> 2, seg = (e & 3) * 4;
            uint32_t soff = (uint32_t)(row * 20 + seg) * 4;
            size_t aoff = (size_t)(m0 + row) * ldap + kp0 + seg;
            cp16(base + soff, Agh + aoff, 16);
            cp16(base + SM_CH * 4 + soff, Agl + aoff, 16);
            int nn = n0 + row;
            int sz = (nn < N) ? 16 : 0;
            size_t boff = (size_t)(nn < N ? nn : 0) * ldbp + kp0 + seg;
            cp16(base + SM_CH * 8 + soff, Bgh + boff, sz);
            cp16(base + SM_CH * 12 + soff, Bgl + boff, sz);
        }
        asm volatile("cp.async.commit_group;" ::: "memory");
    };

    int a_row = lane & 15, a_colo = (lane >> 4) * 4;
    int b_l8 = lane & 7, b_seg = lane >> 3;

    load_chunk(0, 0);
    for (int c = 0; c < nch; c++) {
        if (c + 1 < nch) {
            load_chunk(c + 1, (c + 1) & 1);
            asm volatile("cp.async.wait_group 1;" ::: "memory");
        } else {
            asm volatile("cp.async.wait_group 0;" ::: "memory");
        }
        __syncthreads();

        uint32_t abh = smb + (uint32_t)(c & 1) * (SM_BUF * 4);
        uint32_t abl = abh + SM_CH * 4;
        uint32_t bbh = abh + SM_CH * 8;
        uint32_t bbl = abh + SM_CH * 12;

        #pragma unroll
        for (int s = 0; s < 2; s++) {
            uint32_t afh[4][4], afl[4][4];
            #pragma unroll
            for (int mt = 0; mt < 4; mt++) {
                uint32_t off = (uint32_t)(((wm + mt * 16 + a_row) * 20 + s * 8 + a_colo) * 4);
                ldsm4(afh[mt][0], afh[mt][1], afh[mt][2], afh[mt][3], abh + off);
                ldsm4(afl[mt][0], afl[mt][1], afl[mt][2], afl[mt][3], abl + off);
            }
            uint32_t bfh[4][2], bfl[4][2];
            #pragma unroll
            for (int np = 0; np < 2; np++) {
                int brow = wn + (np * 2 + (b_seg >> 1)) * 8 + b_l8;
                int bcol = s * 8 + (b_seg & 1) * 4;
                uint32_t off = (uint32_t)((brow * 20 + bcol) * 4);
                ldsm4(bfh[np*2][0], bfh[np*2][1], bfh[np*2+1][0], bfh[np*2+1][1], bbh + off);
                ldsm4(bfl[np*2][0], bfl[np*2][1], bfl[np*2+1][0], bfl[np*2+1][1], bbl + off);
            }
            #pragma unroll
            for (int mt = 0; mt < 4; mt++)
                #pragma unroll
                for (int nt = 0; nt < 4; nt++) {
                    mma16816(acc[mt][nt], afh[mt], bfh[nt]);
                    mma16816(acc[mt][nt], afh[mt], bfl[nt]);
                    mma16816(acc[mt][nt], afl[mt], bfh[nt]);
                }
        }
        __syncthreads();
    }

    if (mode == 0) {
        #pragma unroll
        for (int mt = 0; mt < 4; mt++) {
            int r0 = m0 + wm + mt * 16 + g;
            #pragma unroll
            for (int nt = 0; nt < 4; nt++) {
                int col = n0 + wn + nt * 8 + 2 * t;
                #pragma unroll
                for (int half = 0; half < 2; half++) {
                    int row = r0 + half * 8;
                    float v0 = acc[mt][nt][half * 2 + 0];
                    float v1 = acc[mt][nt][half * 2 + 1];
                    if (col < N) {
                        if (bias)   v0 += bias[col];
                        if (addsrc) v0 += addsrc[(size_t)row * ldc + col];
                        C[(size_t)row * ldc + col] = v0;
                    }
                    if (col + 1 < N) {
                        if (bias)   v1 += bias[col + 1];
                        if (addsrc) v1 += addsrc[(size_t)row * ldc + col + 1];
                        C[(size_t)row * ldc + col + 1] = v1;
                    }
                }
            }
        }
    } else if (mode == 1) {
        #pragma unroll
        for (int mt = 0; mt < 4; mt++) {
            int r0 = m0 + wm + mt * 16 + g;
            #pragma unroll
            for (int nt = 0; nt < 4; nt++) {
                int col = n0 + wn + nt * 8 + 2 * t;
                int j = col >> 1;
                bool valid = col < N;
                #pragma unroll
                for (int half = 0; half < 2; half++) {
                    int row = r0 + half * 8;
                    float y = 0.0f;
                    if (valid) {
                        float a  = acc[mt][nt][half * 2 + 0] + bias[j];
                        float gg = acc[mt][nt][half * 2 + 1] + bias[j + DHID];
                        y = a * 0.5f * gg * (1.0f + erff(gg * 0.70710678118654752f));
                    }
                    float y1 = __shfl_down_sync(0xffffffffu, y, 1);
                    if ((t & 1) == 0) {
                        int kp = j >> 1;
                        if (kp < KPY) {
                            uint32_t hi, lo;
                            split2(y, y1, hi, lo);
                            Yh[(size_t)row * KPY + kp] = hi;
                            Yl[(size_t)row * KPY + kp] = lo;
                        }
                    }
                }
            }
        }
    } else {
        // mode 2: qkv epilogue. region uniform per CTA (512 % 128 == 0).
        int region = n0 >> 9;   // 0=q, 1=k, 2=v
        #pragma unroll
        for (int mt = 0; mt < 4; mt++) {
            int r0 = m0 + wm + mt * 16 + g;
            #pragma unroll
            for (int nt = 0; nt < 4; nt++) {
                int col = n0 + wn + nt * 8 + 2 * t;
                int cc = col & 511;
                #pragma unroll
                for (int half = 0; half < 2; half++) {
                    int row = r0 + half * 8;
                    float v0 = acc[mt][nt][half * 2 + 0];
                    float v1 = acc[mt][nt][half * 2 + 1];
                    size_t idx = (size_t)row * KPX + (cc >> 1);
                    if (region <= 1) {
                        float2 cs = rt[(row & (S_ - 1)) * 32 + ((cc & 63) >> 1)];
                        float r1 = v0 * cs.x - v1 * cs.y;
                        float r2 = v0 * cs.y + v1 * cs.x;
                        if (region == 0) { r1 *= 0.125f; r2 *= 0.125f; }
                        uint32_t hi, lo;
                        split2(r1, r2, hi, lo);
                        if (region == 0) { Qh[idx] = hi; Ql[idx] = lo; }
                        else             { Kh2[idx] = hi; Kl2[idx] = lo; }
                    } else {
                        if (layer0) {
                            fvp[(size_t)row * DI + cc] = v0;
                            fvp[(size_t)row * DI + cc + 1] = v1;
                        } else {
                            float mx = mixp[(size_t)row * H_ + (cc >> 6)];
                            float f0 = fvp[(size_t)row * DI + cc];
                            float f1 = fvp[(size_t)row * DI + cc + 1];
                            v0 += mx * (f0 - v0);
                            v1 += mx * (f1 - v1);
                        }
                        uint32_t hi, lo;
                        split2(v0, v1, hi, lo);
                        Vh2[idx] = hi; Vl2[idx] = lo;
                    }
                }
            }
        }
    }
}

// ================= flash attention: pure cp.async tiles, ldmatrix(.trans) ========
__global__ void __launch_bounds__(128) attn_mma(
    const uint32_t* __restrict__ Qh, const uint32_t* __restrict__ Ql,
    const uint32_t* __restrict__ Kg_h, const uint32_t* __restrict__ Kg_l,
    const uint32_t* __restrict__ Vg_h, const uint32_t* __restrict__ Vg_l,
    uint32_t* __restrict__ Oh, uint32_t* __restrict__ Ol)
{
    __shared__ uint32_t Khs[64][36], Kls[64][36];
    __shared__ uint32_t Vhs[64][36], Vls[64][36];

    int Qb = blockIdx.x;
    int h  = blockIdx.y & 7, b = blockIdx.y >> 3;
    int tid = threadIdx.x, w = tid >> 5, lane = tid & 31;
    int g = lane >> 2, t = lane & 3;
    int row0 = b * S_ + Qb * 64;

    uint32_t kbh = smem_u32(Khs), kbl = smem_u32(Kls);
    uint32_t vbh = smem_u32(Vhs), vbl = smem_u32(Vls);
    int l8 = lane & 7, seg8 = lane >> 3;

    // ---- Q fragments: direct loads (pre-roped, pre-scaled, pre-split) ----
    uint32_t qh[4][4], ql[4][4];
    #pragma unroll
    for (int kt = 0; kt < 4; kt++) {
        #pragma unroll
        for (int q = 0; q < 4; q++) {
            int rr = row0 + w * 16 + g + ((q & 1) ? 8 : 0);
            int kp = kt * 8 + t + ((q & 2) ? 4 : 0);
            size_t idx = (size_t)rr * KPX + h * 32 + kp;
            qh[kt][q] = Qh[idx];
            ql[kt][q] = Ql[idx];
        }
    }

    float Oa[8][4];
    #pragma unroll
    for (int i = 0; i < 8; i++)
        #pragma unroll
        for (int q = 0; q < 4; q++) Oa[i][q] = 0.0f;
    float m_[2] = {-INFINITY, -INFINITY};
    float l_[2] = {0.0f, 0.0f};

    for (int J = 0; J <= Qb; J++) {
        int kr = b * S_ + J * 64;
        __syncthreads();
        // ---- K,V tiles via cp.async (4 x 16B per plane per thread) ----
        #pragma unroll
        for (int i = 0; i < 4; i++) {
            int cc = i * 128 + tid;        // 0..511
            int row = cc >> 3, sg = cc & 7;
            size_t src = (size_t)(kr + row) * KPX + h * 32 + sg * 4;
            uint32_t soff = (uint32_t)(row * 36 + sg * 4) * 4;
            cp16(kbh + soff, Kg_h + src, 16);
            cp16(kbl + soff, Kg_l + src, 16);
            cp16(vbh + soff, Vg_h + src, 16);
            cp16(vbl + soff, Vg_l + src, 16);
        }
        asm volatile("cp.async.commit_group;" ::: "memory");
        asm volatile("cp.async.wait_group 0;" ::: "memory");
        __syncthreads();

        int diag = (J == Qb) && (w < 2);
        int ntS  = diag ? 4 : 8;
        int ktPV = diag ? 2 : 4;

        // ---- S = Q K^T ----
        float Sa[8][4];
        for (int nt = 0; nt < ntS; nt++) {
            Sa[nt][0] = Sa[nt][1] = Sa[nt][2] = Sa[nt][3] = 0.0f;
            uint32_t kfh[4][2], kfl[4][2];
            uint32_t off0 = (uint32_t)(((8 * nt + l8) * 36 + seg8 * 4) * 4);
            ldsm4(kfh[0][0], kfh[0][1], kfh[1][0], kfh[1][1], kbh + off0);
            ldsm4(kfh[2][0], kfh[2][1], kfh[3][0], kfh[3][1], kbh + off0 + 64);
            ldsm4(kfl[0][0], kfl[0][1], kfl[1][0], kfl[1][1], kbl + off0);
            ldsm4(kfl[2][0], kfl[2][1], kfl[3][0], kfl[3][1], kbl + off0 + 64);
            #pragma unroll
            for (int kt = 0; kt < 4; kt++) {
                mma16816(Sa[nt], qh[kt], kfh[kt]);
                mma16816(Sa[nt], qh[kt], kfl[kt]);
                mma16816(Sa[nt], ql[kt], kfh[kt]);
            }
        }

        // ---- online softmax ----
        float alpha[2];
        #pragma unroll
        for (int half = 0; half < 2; half++) {
            float mx = -INFINITY;
            for (int nt = 0; nt < ntS; nt++) {
                mx = fmaxf(mx, Sa[nt][half * 2]);
                mx = fmaxf(mx, Sa[nt][half * 2 + 1]);
            }
            mx = fmaxf(mx, __shfl_xor_sync(0xffffffffu, mx, 1));
            mx = fmaxf(mx, __shfl_xor_sync(0xffffffffu, mx, 2));
            float mn = fmaxf(m_[half], mx);
            alpha[half] = __expf(m_[half] - mn);
            m_[half] = mn;
            float ps = 0.0f;
            for (int nt = 0; nt < ntS; nt++) {
                float p0 = __expf(Sa[nt][half * 2]     - mn);
                float p1 = __expf(Sa[nt][half * 2 + 1] - mn);
                Sa[nt][half * 2]     = p0;
                Sa[nt][half * 2 + 1] = p1;
                ps += p0 + p1;
            }
            l_[half] = l_[half] * alpha[half] + ps;
        }
        #pragma unroll
        for (int nt = 0; nt < 8; nt++) {
            Oa[nt][0] *= alpha[0]; Oa[nt][1] *= alpha[0];
            Oa[nt][2] *= alpha[1]; Oa[nt][3] *= alpha[1];
        }

        // ---- P fragments ----
        uint32_t ph[4][4], pl[4][4];
        for (int kt = 0; kt < ktPV; kt++) {
            split2(Sa[2 * kt][0],     Sa[2 * kt][1],     ph[kt][0], pl[kt][0]);
            split2(Sa[2 * kt][2],     Sa[2 * kt][3],     ph[kt][1], pl[kt][1]);
            split2(Sa[2 * kt + 1][0], Sa[2 * kt + 1][1], ph[kt][2], pl[kt][2]);
            split2(Sa[2 * kt + 1][2], Sa[2 * kt + 1][3], ph[kt][3], pl[kt][3]);
        }

        // ---- O += P V  (B-frags via ldmatrix.trans from row-major V) ----
        int npair = ktPV >> 1;
        for (int p = 0; p < npair; p++) {
            int key = 32 * p + seg8 * 8 + l8;      // address lane role
            #pragma unroll
            for (int nt = 0; nt < 8; nt++) {
                uint32_t off = (uint32_t)((key * 36 + nt * 4) * 4);
                uint32_t bh0, bh1, bh2, bh3, bl0, bl1, bl2, bl3;
                ldsm4t(bh0, bh1, bh2, bh3, vbh + off);
                ldsm4t(bl0, bl1, bl2, bl3, vbl + off);
                uint32_t b0h[2] = {bh0, bh1}, b0l[2] = {bl0, bl1};
                uint32_t b1h[2] = {bh2, bh3}, b1l[2] = {bl2, bl3};
                mma16816(Oa[nt], ph[2*p],     b0h);
                mma16816(Oa[nt], ph[2*p],     b0l);
                mma16816(Oa[nt], pl[2*p],     b0h);
                mma16816(Oa[nt], ph[2*p + 1], b1h);
                mma16816(Oa[nt], ph[2*p + 1], b1l);
                mma16816(Oa[nt], pl[2*p + 1], b1h);
            }
        }
    }

    float linv[2];
    #pragma unroll
    for (int half = 0; half < 2; half++) {
        float l = l_[half];
        l += __shfl_xor_sync(0xffffffffu, l, 1);
        l += __shfl_xor_sync(0xffffffffu, l, 2);
        linv[half] = 1.0f / l;
    }
    int r0 = w * 16 + g, r1 = r0 + 8;
    #pragma unroll
    for (int nt = 0; nt < 8; nt++) {
        int kp = h * 32 + 4 * nt + t;
        uint32_t hi, lo;
        split2(Oa[nt][0] * linv[0], Oa[nt][1] * linv[0], hi, lo);
        Oh[(size_t)(row0 + r0) * KPX + kp] = hi;
        Ol[(size_t)(row0 + r0) * KPX + kp] = lo;
        split2(Oa[nt][2] * linv[1], Oa[nt][3] * linv[1], hi, lo);
        Oh[(size_t)(row0 + r1) * KPX + kp] = hi;
        Ol[(size_t)(row0 + r1) * KPX + kp] = lo;
    }
}

// ---------------- elementwise copy ----------------
__global__ void copy_k(const float4* __restrict__ in, float4* __restrict__ out, int n4) {
    int i = blockIdx.x * blockDim.x + threadIdx.x;
    if (i < n4) out[i] = in[i];
}

// ---------------- rmsnorm -> split output ----------------
__global__ void rmsnorm_split_k(const float* __restrict__ in, const float* __restrict__ w,
                                uint32_t* __restrict__ Xh, uint32_t* __restrict__ Xl) {
    int row = blockIdx.x;
    const float4* ip = (const float4*)(in + (size_t)row * D_);
    float4 v = ip[threadIdx.x];
    float ss = v.x*v.x + v.y*v.y + v.z*v.z + v.w*v.w;
    #pragma unroll
    for (int o = 16; o; o >>= 1) ss += __shfl_xor_sync(0xffffffffu, ss, o);
    __shared__ float sred[4];
    if ((threadIdx.x & 31) == 0) sred[threadIdx.x >> 5] = ss;
    __syncthreads();
    float tot = sred[0] + sred[1] + sred[2] + sred[3];
    float sc = rsqrtf(tot * (1.0f / 512.0f) + 1.1920929e-7f);
    const float4* wp = (const float4*)w;
    float4 wv = wp[threadIdx.x];
    float o0 = v.x * sc * wv.x, o1 = v.y * sc * wv.y;
    float o2 = v.z * sc * wv.z, o3 = v.w * sc * wv.w;
    uint32_t h0, l0, h1, l1;
    split2(o0, o1, h0, l0);
    split2(o2, o3, h1, l1);
    size_t base = (size_t)row * KPX + threadIdx.x * 2;
    Xh[base] = h0; Xh[base + 1] = h1;
    Xl[base] = l0; Xl[base + 1] = l1;
}

// ---------------- rmsnorm fp32 out (final) ----------------
__global__ void rmsnorm_k(const float* __restrict__ in, const float* __restrict__ w,
                          float* __restrict__ out) {
    int row = blockIdx.x;
    const float4* ip = (const float4*)(in + (size_t)row * D_);
    float4 v = ip[threadIdx.x];
    float ss = v.x*v.x + v.y*v.y + v.z*v.z + v.w*v.w;
    #pragma unroll
    for (int o = 16; o; o >>= 1) ss += __shfl_xor_sync(0xffffffffu, ss, o);
    __shared__ float sred[4];
    if ((threadIdx.x & 31) == 0) sred[threadIdx.x >> 5] = ss;
    __syncthreads();
    float tot = sred[0] + sred[1] + sred[2] + sred[3];
    float sc = rsqrtf(tot * (1.0f / 512.0f) + 1.1920929e-7f);
    const float4* wp = (const float4*)w;
    float4 wv = wp[threadIdx.x];
    float4 o4;
    o4.x = v.x * sc * wv.x; o4.y = v.y * sc * wv.y;
    o4.z = v.z * sc * wv.z; o4.w = v.w * sc * wv.w;
    ((float4*)(out + (size_t)row * D_))[threadIdx.x] = o4;
}

// ---------------- mix gate ----------------
__global__ void mix_k(const uint32_t* __restrict__ Xh, const uint32_t* __restrict__ Xl,
                      const float* __restrict__ mw, const float* __restrict__ mb,
                      float* __restrict__ mix) {
    int row = blockIdx.x;
    int lane = threadIdx.x & 31;
    int h = threadIdx.x >> 5;
    float dot = 0.0f;
    #pragma unroll
    for (int kp = lane; kp < KPX; kp += 32) {
        uint32_t hv = Xh[(size_t)row * KPX + kp], lv = Xl[(size_t)row * KPX + kp];
        float x0 = __uint_as_float(hv << 16) + __uint_as_float(lv << 16);
        float x1 = __uint_as_float(hv & 0xFFFF0000u) + __uint_as_float(lv & 0xFFFF0000u);
        dot += x0 * mw[(2 * kp) * H_ + h] + x1 * mw[(2 * kp + 1) * H_ + h];
    }
    #pragma unroll
    for (int o = 16; o; o >>= 1) dot += __shfl_xor_sync(0xffffffffu, dot, o);
    if (lane == 0)
        mix[(size_t)row * H_ + h] = 1.0f / (1.0f + expf(-(dot + mb[h])));
}

// ---------------- launch ----------------
extern "C" void kernel_launch(void* const* d_in, const int* in_sizes, int n_in,
                              void* d_out, int out_size) {
    const float* tokens       = (const float*)d_in[0];
    const float* attn_norm_w  = (const float*)d_in[1];
    const float* qkv_w        = (const float*)d_in[2];
    const float* out_w        = (const float*)d_in[3];
    const float* mix_w        = (const float*)d_in[4];
    const float* mix_b        = (const float*)d_in[5];
    const float* ff_norm_w    = (const float*)d_in[6];
    const float* ff_in_w      = (const float*)d_in[7];
    const float* ff_in_b      = (const float*)d_in[8];
    const float* ff_out_w     = (const float*)d_in[9];
    const float* ff_out_b     = (const float*)d_in[10];
    const float* final_norm_w = (const float*)d_in[11];

    float *t_, *fv_, *mix_;
    float2* rt_;
    uint32_t *xh_, *xl_, *oh_, *ol_, *yh_, *yl_;
    uint32_t *qh2_, *ql2_, *kh2_, *kl2_, *vh2_, *vl2_;
    uint32_t *wqh_, *wql_, *woh_, *wol_, *wfh_, *wfl_, *wgh_, *wgl_;
    cudaGetSymbolAddress((void**)&t_,   g_t);
    cudaGetSymbolAddress((void**)&fv_,  g_fv);
    cudaGetSymbolAddress((void**)&mix_, g_mix);
    cudaGetSymbolAddress((void**)&rt_,  g_rt);
    cudaGetSymbolAddress((void**)&xh_,  g_xh);
    cudaGetSymbolAddress((void**)&xl_,  g_xl);
    cudaGetSymbolAddress((void**)&oh_,  g_oh);
    cudaGetSymbolAddress((void**)&ol_,  g_ol);
    cudaGetSymbolAddress((void**)&yh_,  g_yh);
    cudaGetSymbolAddress((void**)&yl_,  g_yl);
    cudaGetSymbolAddress((void**)&qh2_, g_qh2);
    cudaGetSymbolAddress((void**)&ql2_, g_ql2);
    cudaGetSymbolAddress((void**)&kh2_, g_kh2);
    cudaGetSymbolAddress((void**)&kl2_, g_kl2);
    cudaGetSymbolAddress((void**)&vh2_, g_vh2);
    cudaGetSymbolAddress((void**)&vl2_, g_vl2);
    cudaGetSymbolAddress((void**)&wqh_, g_wqh);
    cudaGetSymbolAddress((void**)&wql_, g_wql);
    cudaGetSymbolAddress((void**)&woh_, g_woh);
    cudaGetSymbolAddress((void**)&wol_, g_wol);
    cudaGetSymbolAddress((void**)&wfh_, g_wfh);
    cudaGetSymbolAddress((void**)&wfl_, g_wfl);
    cudaGetSymbolAddress((void**)&wgh_, g_wgh);
    cudaGetSymbolAddress((void**)&wgl_, g_wgl);

    static int smem_set = 0;
    if (!smem_set) {
        cudaFuncSetAttribute(gemm_bs, cudaFuncAttributeMaxDynamicSharedMemorySize,
                             2 * SM_BUF * 4);
        smem_set = 1;
    }
    const int GSM = 2 * SM_BUF * 4;

    copy_k<<<(M_ * D_ / 4 + 255) / 256, 256>>>((const float4*)tokens, (float4*)t_, M_ * D_ / 4);
    ropetab_k<<<(S_ * 32 + 255) / 256, 256>>>(rt_);

    dim3 cb(32, 8);
    wconv_k<<<dim3(KPX / 32, QKVN / 32, L_), cb>>>(
        qkv_w, wqh_, wql_, D_, QKVN, KPX, 0,
        (size_t)D_ * QKVN, (size_t)QKVN * KPX);
    wconv_k<<<dim3(KPX / 32, DI / 32, L_), cb>>>(
        out_w, woh_, wol_, DI, D_, KPX, 0,
        (size_t)DI * D_, (size_t)DI * KPX);
    wconv_k<<<dim3(KPX / 32, (FFN + 31) / 32, L_), cb>>>(
        ff_in_w, wfh_, wfl_, D_, FFN, KPX, 1,
        (size_t)D_ * FFN, (size_t)FFN * KPX);
    wconv_k<<<dim3((KPY + 31) / 32, DI / 32, L_), cb>>>(
        ff_out_w, wgh_, wgl_, DHID, D_, KPY, 0,
        (size_t)DHID * D_, (size_t)DI * KPY);

    for (int l = 0; l < L_; l++) {
        rmsnorm_split_k<<<M_, 128>>>(t_, attn_norm_w + l * D_, xh_, xl_);

        if (l > 0)
            mix_k<<<M_, 256>>>(xh_, xl_, mix_w + (size_t)l * D_ * H_, mix_b + l * H_, mix_);

        gemm_bs<<<dim3(QKVN / 128, M_ / 128), 256, GSM>>>(
            QKVN, KPX, KPX, KPX, 0,
            xh_, xl_, wqh_ + (size_t)l * QKVN * KPX, wql_ + (size_t)l * QKVN * KPX,
            nullptr, nullptr, nullptr, 2, nullptr, nullptr,
            rt_, mix_, fv_, qh2_, ql2_, kh2_, kl2_, vh2_, vl2_, (l == 0) ? 1 : 0);

        attn_mma<<<dim3(S_ / 64, B_ * H_), 128>>>(
            qh2_, ql2_, kh2_, kl2_, vh2_, vl2_, oh_, ol_);

        gemm_bs<<<dim3(D_ / 128, M_ / 128), 256, GSM>>>(
            D_, KPX, KPX, KPX, D_,
            oh_, ol_, woh_ + (size_t)l * DI * KPX, wol_ + (size_t)l * DI * KPX,
            t_, nullptr, t_, 0, nullptr, nullptr,
            nullptr, nullptr, nullptr, nullptr, nullptr, nullptr, nullptr, nullptr, nullptr, 0);

        rmsnorm_split_k<<<M_, 128>>>(t_, ff_norm_w + l * D_, xh_, xl_);

        gemm_bs<<<dim3((FFN + 127) / 128, M_ / 128), 256, GSM>>>(
            FFN, KPX, KPX, KPX, 0,
            xh_, xl_, wfh_ + (size_t)l * FFN * KPX, wfl_ + (size_t)l * FFN * KPX,
            nullptr, ff_in_b + (size_t)l * FFN, nullptr, 1, yh_, yl_,
            nullptr, nullptr, nullptr, nullptr, nullptr, nullptr, nullptr, nullptr, nullptr, 0);

        gemm_bs<<<dim3(D_ / 128, M_ / 128), 256, GSM>>>(
            D_, KPY, KPY, KPY, D_,
            yh_, yl_, wgh_ + (size_t)l * DI * KPY, wgl_ + (size_t)l * DI * KPY,
            t_, ff_out_b + (size_t)l * D_, t_, 0, nullptr, nullptr,
            nullptr, nullptr, nullptr, nullptr, nullptr, nullptr, nullptr, nullptr, nullptr, 0);
    }

    rmsnorm_k<<<M_, 128>>>(t_, final_norm_w, (float*)d_out);
}

// round 11
// speedup vs baseline: 4.0684x; 1.0047x over previous
#include <cuda_runtime.h>
#include <cuda_bf16.h>
#include <math.h>
#include <stdint.h>

#define B_   2
#define S_   2048
#define D_   512
#define L_   4
#define H_   8
#define DH   64
#define M_   (B_*S_)      // 4096 rows
#define DI   512          // H*DH
#define QKVN 1536
#define DHID 1365
#define FFN  2730         // 2*DHID
#define KPX  256          // k-pairs for K=512
#define KPY  688          // k-pairs (padded) for K=1365

// ---------------- scratch (no allocation allowed) ----------------
__device__ float    g_t   [M_ * D_];            // residual stream
__device__ float    g_fv  [M_ * DI];            // first layer's v (fp32)
__device__ float    g_mix [M_ * H_];            // sigmoid gates
__device__ float2   g_rt  [S_ * 32];            // rope cos/sin table
__device__ uint32_t g_xh  [M_ * KPX], g_xl [M_ * KPX];   // rmsnorm out (split)
__device__ uint32_t g_oh  [M_ * KPX], g_ol [M_ * KPX];   // attn out (split)
__device__ uint32_t g_yh  [M_ * KPY], g_yl [M_ * KPY];   // gelu out (split; padding stays 0)
__device__ uint32_t g_qh2 [M_ * KPX], g_ql2 [M_ * KPX];  // roped+scaled q (split)
__device__ uint32_t g_kh2 [M_ * KPX], g_kl2 [M_ * KPX];  // roped k (split)
__device__ uint32_t g_vh2 [M_ * KPX], g_vl2 [M_ * KPX];  // mixed v (split)
// converted weights (transposed [N][Kp], hi/lo planes)
__device__ uint32_t g_wqh [L_ * QKVN * KPX], g_wql [L_ * QKVN * KPX];
__device__ uint32_t g_woh [L_ * DI   * KPX], g_wol [L_ * DI   * KPX];
__device__ uint32_t g_wfh [L_ * FFN  * KPX], g_wfl [L_ * FFN  * KPX];
__device__ uint32_t g_wgh [L_ * DI   * KPY], g_wgl [L_ * DI   * KPY];

// ---------------- helpers ----------------
__device__ __forceinline__ uint32_t smem_u32(const void* p) {
    uint32_t a;
    asm("{ .reg .u64 t; cvta.to.shared.u64 t, %1; cvt.u32.u64 %0, t; }" : "=r"(a) : "l"(p));
    return a;
}
__device__ __forceinline__ uint32_t pack_bf(float x, float y) {
    uint32_t r;
    asm("cvt.rn.bf16x2.f32 %0, %1, %2;" : "=r"(r) : "f"(y), "f"(x));
    return r;
}
__device__ __forceinline__ void split2(float x, float y, uint32_t& hi, uint32_t& lo) {
    hi = pack_bf(x, y);
    float rx = x - __uint_as_float(hi << 16);
    float ry = y - __uint_as_float(hi & 0xFFFF0000u);
    lo = pack_bf(rx, ry);
}
__device__ __forceinline__ void mma16816(float* c, const uint32_t* a, const uint32_t* b) {
    asm volatile(
        "mma.sync.aligned.m16n8k16.row.col.f32.bf16.bf16.f32 "
        "{%0,%1,%2,%3}, {%4,%5,%6,%7}, {%8,%9}, {%0,%1,%2,%3};"
        : "+f"(c[0]), "+f"(c[1]), "+f"(c[2]), "+f"(c[3])
        : "r"(a[0]), "r"(a[1]), "r"(a[2]), "r"(a[3]), "r"(b[0]), "r"(b[1]));
}
__device__ __forceinline__ void ldsm4(uint32_t& r0, uint32_t& r1, uint32_t& r2, uint32_t& r3,
                                      uint32_t addr) {
    asm volatile("ldmatrix.sync.aligned.m8n8.x4.shared.b16 {%0,%1,%2,%3}, [%4];"
                 : "=r"(r0), "=r"(r1), "=r"(r2), "=r"(r3) : "r"(addr));
}
__device__ __forceinline__ void ldsm4t(uint32_t& r0, uint32_t& r1, uint32_t& r2, uint32_t& r3,
                                       uint32_t addr) {
    asm volatile("ldmatrix.sync.aligned.m8n8.x4.trans.shared.b16 {%0,%1,%2,%3}, [%4];"
                 : "=r"(r0), "=r"(r1), "=r"(r2), "=r"(r3) : "r"(addr));
}
__device__ __forceinline__ void cp16(uint32_t dst, const void* src, int sz) {
    asm volatile("cp.async.ca.shared.global [%0], [%1], 16, %2;"
                 :: "r"(dst), "l"(src), "r"(sz) : "memory");
}

// ---------------- weight convert: W[K][N] fp32 -> Wh/Wl [N][Kps]; z = layer --------
__global__ void wconv_k(const float* __restrict__ W0, uint32_t* __restrict__ Wh0,
                        uint32_t* __restrict__ Wl0, int K, int N, int Kps, int ilv,
                        size_t wstride, size_t pstride) {
    const float* W = W0 + blockIdx.z * wstride;
    uint32_t* Wh = Wh0 + blockIdx.z * pstride;
    uint32_t* Wl = Wl0 + blockIdx.z * pstride;
    __shared__ float2 tile[32][33];
    int kp0 = blockIdx.x * 32, n0 = blockIdx.y * 32;
    int tx = threadIdx.x, ty = threadIdx.y;   // 32 x 8
    #pragma unroll
    for (int j = 0; j < 4; j++) {
        int kp = kp0 + ty + j * 8, k = 2 * kp, n = n0 + tx;
        int on = n;
        if (ilv) on = (n & 1) ? (n >> 1) + DHID : (n >> 1);
        float a = 0.0f, b = 0.0f;
        if (n < N) {
            if (k < K)     a = W[(size_t)k * N + on];
            if (k + 1 < K) b = W[(size_t)(k + 1) * N + on];
        }
        tile[ty + j * 8][tx] = make_float2(a, b);
    }
    __syncthreads();
    #pragma unroll
    for (int j = 0; j < 4; j++) {
        int n = n0 + ty + j * 8, kp = kp0 + tx;
        if (n < N && kp < Kps) {
            float2 v = tile[tx][ty + j * 8];
            uint32_t hi, lo;
            split2(v.x, v.y, hi, lo);
            Wh[(size_t)n * Kps + kp] = hi;
            Wl[(size_t)n * Kps + kp] = lo;
        }
    }
}

// ---------------- rope table ----------------
__global__ void ropetab_k(float2* __restrict__ rt) {
    int idx = blockIdx.x * 256 + threadIdx.x;
    if (idx >= S_ * 32) return;
    int pair = idx & 31, pos = idx >> 5;
    float inv = expf(-logf(10000.0f) * (float)pair * (1.0f / 32.0f));
    float s, c;
    sincosf((float)pos * inv, &s, &c);
    rt[idx] = make_float2(c, s);
}

// ================= split-bf16 HMMA GEMM, double-buffered cp.async + ldmatrix ======
#define SM_CH 2560
#define SM_BUF 10240
__global__ void __launch_bounds__(256, 2) gemm_bs(
    int N, int Kp, int ldap, int ldbp, int ldc,
    const uint32_t* __restrict__ Agh, const uint32_t* __restrict__ Agl,
    const uint32_t* __restrict__ Bgh, const uint32_t* __restrict__ Bgl,
    float* __restrict__ C, const float* __restrict__ bias,
    const float* __restrict__ addsrc, int mode,
    uint32_t* __restrict__ Yh, uint32_t* __restrict__ Yl,
    const float2* __restrict__ rt, const float* __restrict__ mixp,
    float* __restrict__ fvp,
    uint32_t* __restrict__ Qh, uint32_t* __restrict__ Ql,
    uint32_t* __restrict__ Kh2, uint32_t* __restrict__ Kl2,
    uint32_t* __restrict__ Vh2, uint32_t* __restrict__ Vl2, int layer0)
{
    extern __shared__ uint32_t sm[];
    int tid = threadIdx.x;
    int wid = tid >> 5, lane = tid & 31;
    int m0 = blockIdx.y * 128, n0 = blockIdx.x * 128;
    int wm = (wid >> 2) * 64, wn = (wid & 3) * 32;
    int g = lane >> 2, t = lane & 3;

    float acc[4][4][4];
    #pragma unroll
    for (int i = 0; i < 4; i++)
        #pragma unroll
        for (int j = 0; j < 4; j++)
            #pragma unroll
            for (int q = 0; q < 4; q++) acc[i][j][q] = 0.0f;

    uint32_t smb = smem_u32(sm);
    int nch = Kp >> 4;

    auto load_chunk = [&](int c, int buf) {
        int kp0 = c << 4;
        uint32_t base = smb + (uint32_t)buf * (SM_BUF * 4);
        #pragma unroll
        for (int i = 0; i < 2; i++) {
            int e = i * 256 + tid;
            int row = e >> 2, seg = (e & 3) * 4;
            uint32_t soff = (uint32_t)(row * 20 + seg) * 4;
            size_t aoff = (size_t)(m0 + row) * ldap + kp0 + seg;
            cp16(base + soff, Agh + aoff, 16);
            cp16(base + SM_CH * 4 + soff, Agl + aoff, 16);
            int nn = n0 + row;
            int sz = (nn < N) ? 16 : 0;
            size_t boff = (size_t)(nn < N ? nn : 0) * ldbp + kp0 + seg;
            cp16(base + SM_CH * 8 + soff, Bgh + boff, sz);
            cp16(base + SM_CH * 12 + soff, Bgl + boff, sz);
        }
        asm volatile("cp.async.commit_group;" ::: "memory");
    };

    int a_row = lane & 15, a_colo = (lane >> 4) * 4;
    int b_l8 = lane & 7, b_seg = lane >> 3;

    load_chunk(0, 0);
    for (int c = 0; c < nch; c++) {
        if (c + 1 < nch) {
            load_chunk(c + 1, (c + 1) & 1);
            asm volatile("cp.async.wait_group 1;" ::: "memory");
        } else {
            asm volatile("cp.async.wait_group 0;" ::: "memory");
        }
        __syncthreads();

        uint32_t abh = smb + (uint32_t)(c & 1) * (SM_BUF * 4);
        uint32_t abl = abh + SM_CH * 4;
        uint32_t bbh = abh + SM_CH * 8;
        uint32_t bbl = abh + SM_CH * 12;

        #pragma unroll
        for (int s = 0; s < 2; s++) {
            uint32_t afh[4][4], afl[4][4];
            #pragma unroll
            for (int mt = 0; mt < 4; mt++) {
                uint32_t off = (uint32_t)(((wm + mt * 16 + a_row) * 20 + s * 8 + a_colo) * 4);
                ldsm4(afh[mt][0], afh[mt][1], afh[mt][2], afh[mt][3], abh + off);
                ldsm4(afl[mt][0], afl[mt][1], afl[mt][2], afl[mt][3], abl + off);
            }
            uint32_t bfh[4][2], bfl[4][2];
            #pragma unroll
            for (int np = 0; np < 2; np++) {
                int brow = wn + (np * 2 + (b_seg >> 1)) * 8 + b_l8;
                int bcol = s * 8 + (b_seg & 1) * 4;
                uint32_t off = (uint32_t)((brow * 20 + bcol) * 4);
                ldsm4(bfh[np*2][0], bfh[np*2][1], bfh[np*2+1][0], bfh[np*2+1][1], bbh + off);
                ldsm4(bfl[np*2][0], bfl[np*2][1], bfl[np*2+1][0], bfl[np*2+1][1], bbl + off);
            }
            #pragma unroll
            for (int mt = 0; mt < 4; mt++)
                #pragma unroll
                for (int nt = 0; nt < 4; nt++) {
                    mma16816(acc[mt][nt], afh[mt], bfh[nt]);
                    mma16816(acc[mt][nt], afh[mt], bfl[nt]);
                    mma16816(acc[mt][nt], afl[mt], bfh[nt]);
                }
        }
        __syncthreads();
    }

    if (mode == 0) {
        #pragma unroll
        for (int mt = 0; mt < 4; mt++) {
            int r0 = m0 + wm + mt * 16 + g;
            #pragma unroll
            for (int nt = 0; nt < 4; nt++) {
                int col = n0 + wn + nt * 8 + 2 * t;
                #pragma unroll
                for (int half = 0; half < 2; half++) {
                    int row = r0 + half * 8;
                    float v0 = acc[mt][nt][half * 2 + 0];
                    float v1 = acc[mt][nt][half * 2 + 1];
                    if (col < N) {
                        if (bias)   v0 += bias[col];
                        if (addsrc) v0 += addsrc[(size_t)row * ldc + col];
                        C[(size_t)row * ldc + col] = v0;
                    }
                    if (col + 1 < N) {
                        if (bias)   v1 += bias[col + 1];
                        if (addsrc) v1 += addsrc[(size_t)row * ldc + col + 1];
                        C[(size_t)row * ldc + col + 1] = v1;
                    }
                }
            }
        }
    } else if (mode == 1) {
        #pragma unroll
        for (int mt = 0; mt < 4; mt++) {
            int r0 = m0 + wm + mt * 16 + g;
            #pragma unroll
            for (int nt = 0; nt < 4; nt++) {
                int col = n0 + wn + nt * 8 + 2 * t;
                int j = col >> 1;
                bool valid = col < N;
                #pragma unroll
                for (int half = 0; half < 2; half++) {
                    int row = r0 + half * 8;
                    float y = 0.0f;
                    if (valid) {
                        float a  = acc[mt][nt][half * 2 + 0] + bias[j];
                        float gg = acc[mt][nt][half * 2 + 1] + bias[j + DHID];
                        y = a * 0.5f * gg * (1.0f + erff(gg * 0.70710678118654752f));
                    }
                    float y1 = __shfl_down_sync(0xffffffffu, y, 1);
                    if ((t & 1) == 0) {
                        int kp = j >> 1;
                        if (kp < KPY) {
                            uint32_t hi, lo;
                            split2(y, y1, hi, lo);
                            Yh[(size_t)row * KPY + kp] = hi;
                            Yl[(size_t)row * KPY + kp] = lo;
                        }
                    }
                }
            }
        }
    } else {
        int region = n0 >> 9;   // 0=q, 1=k, 2=v
        #pragma unroll
        for (int mt = 0; mt < 4; mt++) {
            int r0 = m0 + wm + mt * 16 + g;
            #pragma unroll
            for (int nt = 0; nt < 4; nt++) {
                int col = n0 + wn + nt * 8 + 2 * t;
                int cc = col & 511;
                #pragma unroll
                for (int half = 0; half < 2; half++) {
                    int row = r0 + half * 8;
                    float v0 = acc[mt][nt][half * 2 + 0];
                    float v1 = acc[mt][nt][half * 2 + 1];
                    size_t idx = (size_t)row * KPX + (cc >> 1);
                    if (region <= 1) {
                        float2 cs = rt[(row & (S_ - 1)) * 32 + ((cc & 63) >> 1)];
                        float r1 = v0 * cs.x - v1 * cs.y;
                        float r2 = v0 * cs.y + v1 * cs.x;
                        if (region == 0) { r1 *= 0.125f; r2 *= 0.125f; }
                        uint32_t hi, lo;
                        split2(r1, r2, hi, lo);
                        if (region == 0) { Qh[idx] = hi; Ql[idx] = lo; }
                        else             { Kh2[idx] = hi; Kl2[idx] = lo; }
                    } else {
                        if (layer0) {
                            fvp[(size_t)row * DI + cc] = v0;
                            fvp[(size_t)row * DI + cc + 1] = v1;
                        } else {
                            float mx = mixp[(size_t)row * H_ + (cc >> 6)];
                            float f0 = fvp[(size_t)row * DI + cc];
                            float f1 = fvp[(size_t)row * DI + cc + 1];
                            v0 += mx * (f0 - v0);
                            v1 += mx * (f1 - v1);
                        }
                        uint32_t hi, lo;
                        split2(v0, v1, hi, lo);
                        Vh2[idx] = hi; Vl2[idx] = lo;
                    }
                }
            }
        }
    }
}

// ================= flash attention: Br=128, double-buffered cp.async tiles ========
#define ATSM_PL  2304    // uint32 per plane (64*36)
#define ATSM_BUF 9216    // uint32 per buffer (4 planes)
__global__ void __launch_bounds__(256) attn_mma(
    const uint32_t* __restrict__ Qh, const uint32_t* __restrict__ Ql,
    const uint32_t* __restrict__ Kg_h, const uint32_t* __restrict__ Kg_l,
    const uint32_t* __restrict__ Vg_h, const uint32_t* __restrict__ Vg_l,
    uint32_t* __restrict__ Oh, uint32_t* __restrict__ Ol)
{
    extern __shared__ uint32_t asmem[];
    int Qb = blockIdx.x;                 // 128-row query tile
    int h  = blockIdx.y & 7, b = blockIdx.y >> 3;
    int tid = threadIdx.x, w = tid >> 5, lane = tid & 31;
    int g = lane >> 2, t = lane & 3;
    int row0 = b * S_ + Qb * 128;

    uint32_t base = smem_u32(asmem);
    int l8 = lane & 7, seg8 = lane >> 3;

    auto load_tile = [&](int J, int buf) {
        int kr = b * S_ + J * 64;
        uint32_t bb = base + (uint32_t)buf * (ATSM_BUF * 4);
        #pragma unroll
        for (int i = 0; i < 2; i++) {
            int cc = i * 256 + tid;          // 0..511
            int row = cc >> 3, sg = cc & 7;
            size_t src = (size_t)(kr + row) * KPX + h * 32 + sg * 4;
            uint32_t soff = (uint32_t)(row * 36 + sg * 4) * 4;
            cp16(bb + soff, Kg_h + src, 16);
            cp16(bb + ATSM_PL * 4 + soff, Kg_l + src, 16);
            cp16(bb + ATSM_PL * 8 + soff, Vg_h + src, 16);
            cp16(bb + ATSM_PL * 12 + soff, Vg_l + src, 16);
        }
        asm volatile("cp.async.commit_group;" ::: "memory");
    };

    // ---- Q fragments: direct loads (pre-roped, pre-scaled, pre-split) ----
    uint32_t qh[4][4], ql[4][4];
    #pragma unroll
    for (int kt = 0; kt < 4; kt++) {
        #pragma unroll
        for (int q = 0; q < 4; q++) {
            int rr = row0 + w * 16 + g + ((q & 1) ? 8 : 0);
            int kp = kt * 8 + t + ((q & 2) ? 4 : 0);
            size_t idx = (size_t)rr * KPX + h * 32 + kp;
            qh[kt][q] = Qh[idx];
            ql[kt][q] = Ql[idx];
        }
    }

    float Oa[8][4];
    #pragma unroll
    for (int i = 0; i < 8; i++)
        #pragma unroll
        for (int q = 0; q < 4; q++) Oa[i][q] = 0.0f;
    float m_[2] = {-INFINITY, -INFINITY};
    float l_[2] = {0.0f, 0.0f};

    int Jmax = 2 * Qb + 1;
    load_tile(0, 0);
    for (int J = 0; J <= Jmax; J++) {
        if (J < Jmax) {
            load_tile(J + 1, (J + 1) & 1);
            asm volatile("cp.async.wait_group 1;" ::: "memory");
        } else {
            asm volatile("cp.async.wait_group 0;" ::: "memory");
        }
        __syncthreads();

        uint32_t kbh = base + (uint32_t)(J & 1) * (ATSM_BUF * 4);
        uint32_t kbl = kbh + ATSM_PL * 4;
        uint32_t vbh = kbh + ATSM_PL * 8;
        uint32_t vbl = kbh + ATSM_PL * 12;

        // warp-level block-causal masking (32-row granularity)
        int ntS = 8;
        if (J == 2 * Qb)       { if (w < 2) ntS = 4; }
        else if (J == Jmax)    { ntS = (w < 4) ? 0 : ((w < 6) ? 4 : 8); }

        if (ntS > 0) {
            int ktPV = ntS >> 1;

            // ---- S = Q K^T ----
            float Sa[8][4];
            for (int nt = 0; nt < ntS; nt++) {
                Sa[nt][0] = Sa[nt][1] = Sa[nt][2] = Sa[nt][3] = 0.0f;
                uint32_t kfh[4][2], kfl[4][2];
                uint32_t off0 = (uint32_t)(((8 * nt + l8) * 36 + seg8 * 4) * 4);
                ldsm4(kfh[0][0], kfh[0][1], kfh[1][0], kfh[1][1], kbh + off0);
                ldsm4(kfh[2][0], kfh[2][1], kfh[3][0], kfh[3][1], kbh + off0 + 64);
                ldsm4(kfl[0][0], kfl[0][1], kfl[1][0], kfl[1][1], kbl + off0);
                ldsm4(kfl[2][0], kfl[2][1], kfl[3][0], kfl[3][1], kbl + off0 + 64);
                #pragma unroll
                for (int kt = 0; kt < 4; kt++) {
                    mma16816(Sa[nt], qh[kt], kfh[kt]);
                    mma16816(Sa[nt], qh[kt], kfl[kt]);
                    mma16816(Sa[nt], ql[kt], kfh[kt]);
                }
            }

            // ---- online softmax ----
            float alpha[2];
            #pragma unroll
            for (int half = 0; half < 2; half++) {
                float mx = -INFINITY;
                for (int nt = 0; nt < ntS; nt++) {
                    mx = fmaxf(mx, Sa[nt][half * 2]);
                    mx = fmaxf(mx, Sa[nt][half * 2 + 1]);
                }
                mx = fmaxf(mx, __shfl_xor_sync(0xffffffffu, mx, 1));
                mx = fmaxf(mx, __shfl_xor_sync(0xffffffffu, mx, 2));
                float mn = fmaxf(m_[half], mx);
                alpha[half] = __expf(m_[half] - mn);
                m_[half] = mn;
                float ps = 0.0f;
                for (int nt = 0; nt < ntS; nt++) {
                    float p0 = __expf(Sa[nt][half * 2]     - mn);
                    float p1 = __expf(Sa[nt][half * 2 + 1] - mn);
                    Sa[nt][half * 2]     = p0;
                    Sa[nt][half * 2 + 1] = p1;
                    ps += p0 + p1;
                }
                l_[half] = l_[half] * alpha[half] + ps;
            }
            #pragma unroll
            for (int nt = 0; nt < 8; nt++) {
                Oa[nt][0] *= alpha[0]; Oa[nt][1] *= alpha[0];
                Oa[nt][2] *= alpha[1]; Oa[nt][3] *= alpha[1];
            }

            // ---- P fragments ----
            uint32_t ph[4][4], pl[4][4];
            for (int kt = 0; kt < ktPV; kt++) {
                split2(Sa[2 * kt][0],     Sa[2 * kt][1],     ph[kt][0], pl[kt][0]);
                split2(Sa[2 * kt][2],     Sa[2 * kt][3],     ph[kt][1], pl[kt][1]);
                split2(Sa[2 * kt + 1][0], Sa[2 * kt + 1][1], ph[kt][2], pl[kt][2]);
                split2(Sa[2 * kt + 1][2], Sa[2 * kt + 1][3], ph[kt][3], pl[kt][3]);
            }

            // ---- O += P V (trans ldmatrix from row-major V) ----
            int npair = ktPV >> 1;
            for (int p = 0; p < npair; p++) {
                int key = 32 * p + seg8 * 8 + l8;
                #pragma unroll
                for (int nt = 0; nt < 8; nt++) {
                    uint32_t off = (uint32_t)((key * 36 + nt * 4) * 4);
                    uint32_t bh0, bh1, bh2, bh3, bl0, bl1, bl2, bl3;
                    ldsm4t(bh0, bh1, bh2, bh3, vbh + off);
                    ldsm4t(bl0, bl1, bl2, bl3, vbl + off);
                    uint32_t b0h[2] = {bh0, bh1}, b0l[2] = {bl0, bl1};
                    uint32_t b1h[2] = {bh2, bh3}, b1l[2] = {bl2, bl3};
                    mma16816(Oa[nt], ph[2*p],     b0h);
                    mma16816(Oa[nt], ph[2*p],     b0l);
                    mma16816(Oa[nt], pl[2*p],     b0h);
                    mma16816(Oa[nt], ph[2*p + 1], b1h);
                    mma16816(Oa[nt], ph[2*p + 1], b1l);
                    mma16816(Oa[nt], pl[2*p + 1], b1h);
                }
            }
        }
        __syncthreads();
    }

    float linv[2];
    #pragma unroll
    for (int half = 0; half < 2; half++) {
        float l = l_[half];
        l += __shfl_xor_sync(0xffffffffu, l, 1);
        l += __shfl_xor_sync(0xffffffffu, l, 2);
        linv[half] = 1.0f / l;
    }
    int r0 = w * 16 + g, r1 = r0 + 8;
    #pragma unroll
    for (int nt = 0; nt < 8; nt++) {
        int kp = h * 32 + 4 * nt + t;
        uint32_t hi, lo;
        split2(Oa[nt][0] * linv[0], Oa[nt][1] * linv[0], hi, lo);
        Oh[(size_t)(row0 + r0) * KPX + kp] = hi;
        Ol[(size_t)(row0 + r0) * KPX + kp] = lo;
        split2(Oa[nt][2] * linv[1], Oa[nt][3] * linv[1], hi, lo);
        Oh[(size_t)(row0 + r1) * KPX + kp] = hi;
        Ol[(size_t)(row0 + r1) * KPX + kp] = lo;
    }
}

// ---------------- elementwise copy ----------------
__global__ void copy_k(const float4* __restrict__ in, float4* __restrict__ out, int n4) {
    int i = blockIdx.x * blockDim.x + threadIdx.x;
    if (i < n4) out[i] = in[i];
}

// ---------------- rmsnorm -> split output ----------------
__global__ void rmsnorm_split_k(const float* __restrict__ in, const float* __restrict__ w,
                                uint32_t* __restrict__ Xh, uint32_t* __restrict__ Xl) {
    int row = blockIdx.x;
    const float4* ip = (const float4*)(in + (size_t)row * D_);
    float4 v = ip[threadIdx.x];
    float ss = v.x*v.x + v.y*v.y + v.z*v.z + v.w*v.w;
    #pragma unroll
    for (int o = 16; o; o >>= 1) ss += __shfl_xor_sync(0xffffffffu, ss, o);
    __shared__ float sred[4];
    if ((threadIdx.x & 31) == 0) sred[threadIdx.x >> 5] = ss;
    __syncthreads();
    float tot = sred[0] + sred[1] + sred[2] + sred[3];
    float sc = rsqrtf(tot * (1.0f / 512.0f) + 1.1920929e-7f);
    const float4* wp = (const float4*)w;
    float4 wv = wp[threadIdx.x];
    float o0 = v.x * sc * wv.x, o1 = v.y * sc * wv.y;
    float o2 = v.z * sc * wv.z, o3 = v.w * sc * wv.w;
    uint32_t h0, l0, h1, l1;
    split2(o0, o1, h0, l0);
    split2(o2, o3, h1, l1);
    size_t base = (size_t)row * KPX + threadIdx.x * 2;
    Xh[base] = h0; Xh[base + 1] = h1;
    Xl[base] = l0; Xl[base + 1] = l1;
}

// ---------------- rmsnorm fp32 out (final) ----------------
__global__ void rmsnorm_k(const float* __restrict__ in, const float* __restrict__ w,
                          float* __restrict__ out) {
    int row = blockIdx.x;
    const float4* ip = (const float4*)(in + (size_t)row * D_);
    float4 v = ip[threadIdx.x];
    float ss = v.x*v.x + v.y*v.y + v.z*v.z + v.w*v.w;
    #pragma unroll
    for (int o = 16; o; o >>= 1) ss += __shfl_xor_sync(0xffffffffu, ss, o);
    __shared__ float sred[4];
    if ((threadIdx.x & 31) == 0) sred[threadIdx.x >> 5] = ss;
    __syncthreads();
    float tot = sred[0] + sred[1] + sred[2] + sred[3];
    float sc = rsqrtf(tot * (1.0f / 512.0f) + 1.1920929e-7f);
    const float4* wp = (const float4*)w;
    float4 wv = wp[threadIdx.x];
    float4 o4;
    o4.x = v.x * sc * wv.x; o4.y = v.y * sc * wv.y;
    o4.z = v.z * sc * wv.z; o4.w = v.w * sc * wv.w;
    ((float4*)(out + (size_t)row * D_))[threadIdx.x] = o4;
}

// ---------------- mix gate ----------------
__global__ void mix_k(const uint32_t* __restrict__ Xh, const uint32_t* __restrict__ Xl,
                      const float* __restrict__ mw, const float* __restrict__ mb,
                      float* __restrict__ mix) {
    int row = blockIdx.x;
    int lane = threadIdx.x & 31;
    int h = threadIdx.x >> 5;
    float dot = 0.0f;
    #pragma unroll
    for (int kp = lane; kp < KPX; kp += 32) {
        uint32_t hv = Xh[(size_t)row * KPX + kp], lv = Xl[(size_t)row * KPX + kp];
        float x0 = __uint_as_float(hv << 16) + __uint_as_float(lv << 16);
        float x1 = __uint_as_float(hv & 0xFFFF0000u) + __uint_as_float(lv & 0xFFFF0000u);
        dot += x0 * mw[(2 * kp) * H_ + h] + x1 * mw[(2 * kp + 1) * H_ + h];
    }
    #pragma unroll
    for (int o = 16; o; o >>= 1) dot += __shfl_xor_sync(0xffffffffu, dot, o);
    if (lane == 0)
        mix[(size_t)row * H_ + h] = 1.0f / (1.0f + expf(-(dot + mb[h])));
}

// ---------------- launch ----------------
extern "C" void kernel_launch(void* const* d_in, const int* in_sizes, int n_in,
                              void* d_out, int out_size) {
    const float* tokens       = (const float*)d_in[0];
    const float* attn_norm_w  = (const float*)d_in[1];
    const float* qkv_w        = (const float*)d_in[2];
    const float* out_w        = (const float*)d_in[3];
    const float* mix_w        = (const float*)d_in[4];
    const float* mix_b        = (const float*)d_in[5];
    const float* ff_norm_w    = (const float*)d_in[6];
    const float* ff_in_w      = (const float*)d_in[7];
    const float* ff_in_b      = (const float*)d_in[8];
    const float* ff_out_w     = (const float*)d_in[9];
    const float* ff_out_b     = (const float*)d_in[10];
    const float* final_norm_w = (const float*)d_in[11];

    float *t_, *fv_, *mix_;
    float2* rt_;
    uint32_t *xh_, *xl_, *oh_, *ol_, *yh_, *yl_;
    uint32_t *qh2_, *ql2_, *kh2_, *kl2_, *vh2_, *vl2_;
    uint32_t *wqh_, *wql_, *woh_, *wol_, *wfh_, *wfl_, *wgh_, *wgl_;
    cudaGetSymbolAddress((void**)&t_,   g_t);
    cudaGetSymbolAddress((void**)&fv_,  g_fv);
    cudaGetSymbolAddress((void**)&mix_, g_mix);
    cudaGetSymbolAddress((void**)&rt_,  g_rt);
    cudaGetSymbolAddress((void**)&xh_,  g_xh);
    cudaGetSymbolAddress((void**)&xl_,  g_xl);
    cudaGetSymbolAddress((void**)&oh_,  g_oh);
    cudaGetSymbolAddress((void**)&ol_,  g_ol);
    cudaGetSymbolAddress((void**)&yh_,  g_yh);
    cudaGetSymbolAddress((void**)&yl_,  g_yl);
    cudaGetSymbolAddress((void**)&qh2_, g_qh2);
    cudaGetSymbolAddress((void**)&ql2_, g_ql2);
    cudaGetSymbolAddress((void**)&kh2_, g_kh2);
    cudaGetSymbolAddress((void**)&kl2_, g_kl2);
    cudaGetSymbolAddress((void**)&vh2_, g_vh2);
    cudaGetSymbolAddress((void**)&vl2_, g_vl2);
    cudaGetSymbolAddress((void**)&wqh_, g_wqh);
    cudaGetSymbolAddress((void**)&wql_, g_wql);
    cudaGetSymbolAddress((void**)&woh_, g_woh);
    cudaGetSymbolAddress((void**)&wol_, g_wol);
    cudaGetSymbolAddress((void**)&wfh_, g_wfh);
    cudaGetSymbolAddress((void**)&wfl_, g_wfl);
    cudaGetSymbolAddress((void**)&wgh_, g_wgh);
    cudaGetSymbolAddress((void**)&wgl_, g_wgl);

    static int smem_set = 0;
    if (!smem_set) {
        cudaFuncSetAttribute(gemm_bs, cudaFuncAttributeMaxDynamicSharedMemorySize,
                             2 * SM_BUF * 4);
        cudaFuncSetAttribute(attn_mma, cudaFuncAttributeMaxDynamicSharedMemorySize,
                             2 * ATSM_BUF * 4);
        smem_set = 1;
    }
    const int GSM = 2 * SM_BUF * 4;
    const int ASM = 2 * ATSM_BUF * 4;

    copy_k<<<(M_ * D_ / 4 + 255) / 256, 256>>>((const float4*)tokens, (float4*)t_, M_ * D_ / 4);
    ropetab_k<<<(S_ * 32 + 255) / 256, 256>>>(rt_);

    dim3 cb(32, 8);
    wconv_k<<<dim3(KPX / 32, QKVN / 32, L_), cb>>>(
        qkv_w, wqh_, wql_, D_, QKVN, KPX, 0,
        (size_t)D_ * QKVN, (size_t)QKVN * KPX);
    wconv_k<<<dim3(KPX / 32, DI / 32, L_), cb>>>(
        out_w, woh_, wol_, DI, D_, KPX, 0,
        (size_t)DI * D_, (size_t)DI * KPX);
    wconv_k<<<dim3(KPX / 32, (FFN + 31) / 32, L_), cb>>>(
        ff_in_w, wfh_, wfl_, D_, FFN, KPX, 1,
        (size_t)D_ * FFN, (size_t)FFN * KPX);
    wconv_k<<<dim3((KPY + 31) / 32, DI / 32, L_), cb>>>(
        ff_out_w, wgh_, wgl_, DHID, D_, KPY, 0,
        (size_t)DHID * D_, (size_t)DI * KPY);

    for (int l = 0; l < L_; l++) {
        rmsnorm_split_k<<<M_, 128>>>(t_, attn_norm_w + l * D_, xh_, xl_);

        if (l > 0)
            mix_k<<<M_, 256>>>(xh_, xl_, mix_w + (size_t)l * D_ * H_, mix_b + l * H_, mix_);

        gemm_bs<<<dim3(QKVN / 128, M_ / 128), 256, GSM>>>(
            QKVN, KPX, KPX, KPX, 0,
            xh_, xl_, wqh_ + (size_t)l * QKVN * KPX, wql_ + (size_t)l * QKVN * KPX,
            nullptr, nullptr, nullptr, 2, nullptr, nullptr,
            rt_, mix_, fv_, qh2_, ql2_, kh2_, kl2_, vh2_, vl2_, (l == 0) ? 1 : 0);

        attn_mma<<<dim3(S_ / 128, B_ * H_), 256, ASM>>>(
            qh2_, ql2_, kh2_, kl2_, vh2_, vl2_, oh_, ol_);

        gemm_bs<<<dim3(D_ / 128, M_ / 128), 256, GSM>>>(
            D_, KPX, KPX, KPX, D_,
            oh_, ol_, woh_ + (size_t)l * DI * KPX, wol_ + (size_t)l * DI * KPX,
            t_, nullptr, t_, 0, nullptr, nullptr,
            nullptr, nullptr, nullptr, nullptr, nullptr, nullptr, nullptr, nullptr, nullptr, 0);

        rmsnorm_split_k<<<M_, 128>>>(t_, ff_norm_w + l * D_, xh_, xl_);

        gemm_bs<<<dim3((FFN + 127) / 128, M_ / 128), 256, GSM>>>(
            FFN, KPX, KPX, KPX, 0,
            xh_, xl_, wfh_ + (size_t)l * FFN * KPX, wfl_ + (size_t)l * FFN * KPX,
            nullptr, ff_in_b + (size_t)l * FFN, nullptr, 1, yh_, yl_,
            nullptr, nullptr, nullptr, nullptr, nullptr, nullptr, nullptr, nullptr, nullptr, 0);

        gemm_bs<<<dim3(D_ / 128, M_ / 128), 256, GSM>>>(
            D_, KPY, KPY, KPY, D_,
            yh_, yl_, wgh_ + (size_t)l * DI * KPY, wgl_ + (size_t)l * DI * KPY,
            t_, ff_out_b + (size_t)l * D_, t_, 0, nullptr, nullptr,
            nullptr, nullptr, nullptr, nullptr, nullptr, nullptr, nullptr, nullptr, nullptr, 0);
    }

    rmsnorm_k<<<M_, 128>>>(t_, final_norm_w, (float*)d_out);
}